// round 6
// baseline (speedup 1.0000x reference)
#include <cuda_runtime.h>
#include <cuda_bf16.h>
#include <cstdint>
#include <cstddef>

#define B_ 2
#define L_ 4096
#define DM 2048
#define H_ 32
#define P_ 64
#define N_ 128
#define INTER 2048
#define CONV_DIM 2304
#define PROJ 4384
#define PROJ_PAD 4480
#define EPSV 1e-5f
#define NCHUNK 32
#define TCH 128

// ---------------- scratch (__device__ globals; no allocations allowed) ------
__device__ float g_proj[(size_t)B_ * L_ * PROJ_PAD];
__device__ float g_conv[(size_t)B_ * L_ * CONV_DIM];
__device__ float g_y[(size_t)B_ * L_ * INTER];
__device__ float g_dA[B_ * L_ * H_];
__device__ float g_dt[B_ * L_ * H_];
// chunked-scan scratch
__device__ float g_state[(size_t)B_ * NCHUNK * H_ * P_ * N_];  // chunk end states
__device__ float g_init[(size_t)B_ * NCHUNK * H_ * P_ * N_];   // chunk start states
__device__ float g_adec[B_ * NCHUNK * H_];
// bf16 split operands
__device__ __nv_bfloat16 g_hs_hi[(size_t)B_ * L_ * DM];
__device__ __nv_bfloat16 g_hs_lo[(size_t)B_ * L_ * DM];
__device__ __nv_bfloat16 g_win_hi[(size_t)PROJ_PAD * DM];
__device__ __nv_bfloat16 g_win_lo[(size_t)PROJ_PAD * DM];
__device__ __nv_bfloat16 g_yh[(size_t)B_ * L_ * INTER];
__device__ __nv_bfloat16 g_yl[(size_t)B_ * L_ * INTER];
__device__ __nv_bfloat16 g_wo_hi[(size_t)DM * INTER];
__device__ __nv_bfloat16 g_wo_lo[(size_t)DM * INTER];

// ---------------- helpers ----------------------------------------------------
__device__ __forceinline__ float siluf(float x) {
    return x * (1.f / (1.f + expf(-x)));
}
__device__ __forceinline__ float softplusf(float x) {
    return (x > 20.f) ? x : log1pf(expf(x));
}
__device__ __forceinline__ uint32_t s2u(const void* p) {
    return (uint32_t)__cvta_generic_to_shared(p);
}
__device__ __forceinline__ void cp_async4(uint32_t saddr, const void* g) {
    asm volatile("cp.async.ca.shared.global [%0], [%1], 4;\n" :: "r"(saddr), "l"(g));
}
__device__ __forceinline__ void cp16(uint32_t saddr, const void* g) {
    asm volatile("cp.async.cg.shared.global [%0], [%1], 16;\n" :: "r"(saddr), "l"(g));
}
__device__ __forceinline__ void cp_commit() {
    asm volatile("cp.async.commit_group;\n" ::: "memory");
}
__device__ __forceinline__ void cp_wait2() {
    asm volatile("cp.async.wait_group 2;\n" ::: "memory");
}

// ---------------- warp-level HMMA plumbing ----------------------------------
__device__ __forceinline__ void ldm_x4(uint32_t* r, uint32_t addr) {
    asm volatile("ldmatrix.sync.aligned.m8n8.x4.shared.b16 {%0,%1,%2,%3}, [%4];"
                 : "=r"(r[0]), "=r"(r[1]), "=r"(r[2]), "=r"(r[3]) : "r"(addr));
}
__device__ __forceinline__ void mma16816(float* d, const uint32_t* a, const uint32_t* b) {
    asm volatile(
        "mma.sync.aligned.m16n8k16.row.col.f32.bf16.bf16.f32 "
        "{%0,%1,%2,%3}, {%4,%5,%6,%7}, {%8,%9}, {%0,%1,%2,%3};"
        : "+f"(d[0]), "+f"(d[1]), "+f"(d[2]), "+f"(d[3])
        : "r"(a[0]), "r"(a[1]), "r"(a[2]), "r"(a[3]), "r"(b[0]), "r"(b[1]));
}

// ---------------- 3-product bf16-split GEMM on HMMA -------------------------
#define STAGE_BYTES 65536
#define GEMM_SMEM_BYTES (3 * STAGE_BYTES)

__global__ __launch_bounds__(512, 1)
void gemm_mma3(const __nv_bfloat16* __restrict__ Ah, const __nv_bfloat16* __restrict__ Al,
               const __nv_bfloat16* __restrict__ Bh, const __nv_bfloat16* __restrict__ Bl,
               float* __restrict__ C, int K, int ldc)
{
    extern __shared__ __align__(1024) char smem[];
    const uint32_t sb = s2u(smem);
    const int tid = threadIdx.x;
    const int wid = tid >> 5;
    const int lane = tid & 31;
    const int bn = blockIdx.x * 128;
    const int bm = blockIdx.y * 128;
    const int chunks = K >> 6;

    const int wm = (wid & 3) * 32;
    const int wn = (wid >> 2) * 32;

    const int rA = wm + (lane & 15);
    const uint32_t selA = (lane & 16) ? 16u : 0u;
    const uint32_t xorA = (uint32_t)((rA & 7) * 16);
    uint32_t rowOffA[2];
#pragma unroll
    for (int mf = 0; mf < 2; ++mf) rowOffA[mf] = (uint32_t)((rA + mf * 16) * 128);

    const int rB = wn + (lane & 7) + ((lane & 16) ? 8 : 0);
    const uint32_t selB = (lane & 8) ? 16u : 0u;
    const uint32_t xorB = (uint32_t)((rB & 7) * 16);
    uint32_t rowOffB[2];
#pragma unroll
    for (int nb = 0; nb < 2; ++nb) rowOffB[nb] = (uint32_t)((rB + nb * 16) * 128);

    auto issue = [&](int c) {
        const int s = c % 3;
        const uint32_t base = sb + (uint32_t)s * STAGE_BYTES;
        const int k0 = c << 6;
#pragma unroll
        for (int q = 0; q < 2; ++q) {
            const int cc = tid * 2 + q;
            const int row = cc >> 3;
            const int seg = cc & 7;
            const uint32_t dst = (uint32_t)(row * 128 + ((seg * 16) ^ ((row & 7) * 16)));
            const size_t goffA = (size_t)(bm + row) * K + k0 + seg * 8;
            const size_t goffB = (size_t)(bn + row) * K + k0 + seg * 8;
            cp16(base + 0 * 16384 + dst, Ah + goffA);
            cp16(base + 1 * 16384 + dst, Al + goffA);
            cp16(base + 2 * 16384 + dst, Bh + goffB);
            cp16(base + 3 * 16384 + dst, Bl + goffB);
        }
    };

    float acc[2][4][4];
#pragma unroll
    for (int i = 0; i < 2; ++i)
#pragma unroll
        for (int j = 0; j < 4; ++j)
#pragma unroll
            for (int q = 0; q < 4; ++q) acc[i][j][q] = 0.f;

    issue(0); cp_commit();
    issue(1); cp_commit();

    for (int c = 0; c < chunks; ++c) {
        if (c + 2 < chunks) issue(c + 2);
        cp_commit();
        cp_wait2();
        __syncthreads();

        const uint32_t base = sb + (uint32_t)(c % 3) * STAGE_BYTES;
        const uint32_t bAh = base;
        const uint32_t bAl = base + 16384;
        const uint32_t bBh = base + 32768;
        const uint32_t bBl = base + 49152;

#pragma unroll
        for (int ks = 0; ks < 4; ++ks) {
            const uint32_t cA = ((uint32_t)(ks * 32) + selA) ^ xorA;
            const uint32_t cB = ((uint32_t)(ks * 32) + selB) ^ xorB;
            uint32_t ah[2][4], al[2][4];
#pragma unroll
            for (int mf = 0; mf < 2; ++mf) {
                ldm_x4(ah[mf], bAh + rowOffA[mf] + cA);
                ldm_x4(al[mf], bAl + rowOffA[mf] + cA);
            }
            uint32_t bh[4][2], bl[4][2];
#pragma unroll
            for (int nb = 0; nb < 2; ++nb) {
                uint32_t t[4];
                ldm_x4(t, bBh + rowOffB[nb] + cB);
                bh[nb * 2][0] = t[0]; bh[nb * 2][1] = t[1];
                bh[nb * 2 + 1][0] = t[2]; bh[nb * 2 + 1][1] = t[3];
                ldm_x4(t, bBl + rowOffB[nb] + cB);
                bl[nb * 2][0] = t[0]; bl[nb * 2][1] = t[1];
                bl[nb * 2 + 1][0] = t[2]; bl[nb * 2 + 1][1] = t[3];
            }
            // Interleaved product order: consecutive HMMAs hit 8 distinct
            // accumulators before any reuse (dependency distance 8).
#pragma unroll
            for (int mf = 0; mf < 2; ++mf)
#pragma unroll
                for (int nf = 0; nf < 4; ++nf)
                    mma16816(acc[mf][nf], ah[mf], bh[nf]);
#pragma unroll
            for (int mf = 0; mf < 2; ++mf)
#pragma unroll
                for (int nf = 0; nf < 4; ++nf)
                    mma16816(acc[mf][nf], ah[mf], bl[nf]);
#pragma unroll
            for (int mf = 0; mf < 2; ++mf)
#pragma unroll
                for (int nf = 0; nf < 4; ++nf)
                    mma16816(acc[mf][nf], al[mf], bh[nf]);
        }
        __syncthreads();
    }

    const int g = lane >> 2;
    const int t2 = (lane & 3) * 2;
#pragma unroll
    for (int mf = 0; mf < 2; ++mf) {
#pragma unroll
        for (int nf = 0; nf < 4; ++nf) {
            const int col = bn + wn + nf * 8 + t2;
            const int row0 = bm + wm + mf * 16 + g;
            *(float2*)(C + (size_t)row0 * ldc + col) =
                make_float2(acc[mf][nf][0], acc[mf][nf][1]);
            *(float2*)(C + (size_t)(row0 + 8) * ldc + col) =
                make_float2(acc[mf][nf][2], acc[mf][nf][3]);
        }
    }
}

// ---------------- fp32 -> bf16 hi/lo splits ---------------------------------
__global__ __launch_bounds__(256)
void split_kernel(const float* __restrict__ src, __nv_bfloat16* __restrict__ hi,
                  __nv_bfloat16* __restrict__ lo, int n4)
{
    const int i = blockIdx.x * 256 + threadIdx.x;
    if (i >= n4) return;
    const float4 v = ((const float4*)src)[i];
    __nv_bfloat16 h0 = __float2bfloat16(v.x), h1 = __float2bfloat16(v.y);
    __nv_bfloat16 h2 = __float2bfloat16(v.z), h3 = __float2bfloat16(v.w);
    hi[i * 4 + 0] = h0; hi[i * 4 + 1] = h1; hi[i * 4 + 2] = h2; hi[i * 4 + 3] = h3;
    lo[i * 4 + 0] = __float2bfloat16(v.x - __bfloat162float(h0));
    lo[i * 4 + 1] = __float2bfloat16(v.y - __bfloat162float(h1));
    lo[i * 4 + 2] = __float2bfloat16(v.z - __bfloat162float(h2));
    lo[i * 4 + 3] = __float2bfloat16(v.w - __bfloat162float(h3));
}

__global__ __launch_bounds__(256)
void split_pad_kernel(const float* __restrict__ src, __nv_bfloat16* __restrict__ hi,
                      __nv_bfloat16* __restrict__ lo)
{
    const int i = blockIdx.x * 256 + threadIdx.x;
    if (i >= PROJ_PAD * DM / 4) return;
    const int row = i / (DM / 4);
    float4 v = make_float4(0.f, 0.f, 0.f, 0.f);
    if (row < PROJ) v = ((const float4*)src)[i];
    __nv_bfloat16 h0 = __float2bfloat16(v.x), h1 = __float2bfloat16(v.y);
    __nv_bfloat16 h2 = __float2bfloat16(v.z), h3 = __float2bfloat16(v.w);
    hi[i * 4 + 0] = h0; hi[i * 4 + 1] = h1; hi[i * 4 + 2] = h2; hi[i * 4 + 3] = h3;
    lo[i * 4 + 0] = __float2bfloat16(v.x - __bfloat162float(h0));
    lo[i * 4 + 1] = __float2bfloat16(v.y - __bfloat162float(h1));
    lo[i * 4 + 2] = __float2bfloat16(v.z - __bfloat162float(h2));
    lo[i * 4 + 3] = __float2bfloat16(v.w - __bfloat162float(h3));
}

// ---------------- depthwise causal conv (K=4) + bias + SiLU ------------------
__global__ __launch_bounds__(256)
void conv_kernel(const float* __restrict__ conv_w, const float* __restrict__ conv_b)
{
    const int c = blockIdx.x * 256 + threadIdx.x;
    if (c >= CONV_DIM) return;
    const int bl = blockIdx.y;
    const int l = bl & (L_ - 1);
    float acc = conv_b[c];
    const float* w = conv_w + c * 4;
#pragma unroll
    for (int j = 0; j < 4; ++j) {
        const int ll = l - 3 + j;
        if (ll >= 0)
            acc = fmaf(g_proj[(size_t)(bl + j - 3) * PROJ_PAD + INTER + c], w[j], acc);
    }
    g_conv[(size_t)bl * CONV_DIM + c] = siluf(acc);
}

// ---------------- dt = softplus(dt_raw + bias); dA = exp(dt*A) ---------------
__global__ __launch_bounds__(256)
void dt_kernel(const float* __restrict__ dt_bias, const float* __restrict__ A_log)
{
    const int idx = blockIdx.x * 256 + threadIdx.x;
    if (idx >= B_ * L_ * H_) return;
    const int hh = idx & (H_ - 1);
    const int bl = idx >> 5;
    const float x = g_proj[(size_t)bl * PROJ_PAD + INTER + CONV_DIM + hh] + dt_bias[hh];
    const float dt = softplusf(x);
    const float A = -expf(A_log[hh]);
    g_dt[idx] = dt;
    g_dA[idx] = expf(dt * A);
}

// ---------------- chunked scan ----------------------------------------------
__global__ __launch_bounds__(256)
void adec_kernel()
{
    const int i = blockIdx.x * 256 + threadIdx.x;
    if (i >= B_ * NCHUNK * H_) return;
    const int h = i & (H_ - 1);
    const int c = (i >> 5) & (NCHUNK - 1);
    const int b = i >> 10;
    float p = 1.f;
    const float* base = g_dA + ((size_t)(b * L_ + c * TCH)) * H_ + h;
    for (int t = 0; t < TCH; ++t) p *= base[(size_t)t * H_];
    g_adec[i] = p;
}

// Pass 1: per-chunk scan from zero state; store end state.
__global__ __launch_bounds__(256)
void scan_part1()
{
    const int c = blockIdx.x, h = blockIdx.y, b = blockIdx.z;
    const int tid = threadIdx.x;
    const int pgrp = tid >> 4;
    const int ngrp = tid & 15;
    const int t0 = c * TCH;

    __shared__ float sB[4][128];
    __shared__ float sx[4][64];
    __shared__ float sS[4][2];

    auto issue = [&](int t, int s) {
        const float* base = g_conv + (size_t)(b * L_ + t0 + t) * CONV_DIM;
        if (tid < 32)       cp16(s2u(&sB[s][tid * 4]), base + INTER + tid * 4);
        else if (tid < 48)  cp16(s2u(&sx[s][(tid - 32) * 4]), base + h * P_ + (tid - 32) * 4);
        else if (tid == 48) cp_async4(s2u(&sS[s][0]), g_dA + (size_t)(b * L_ + t0 + t) * H_ + h);
        else if (tid == 49) cp_async4(s2u(&sS[s][1]), g_dt + (size_t)(b * L_ + t0 + t) * H_ + h);
    };

    for (int t = 0; t < 3; ++t) { issue(t, t); cp_commit(); }

    float hst[4][8];
#pragma unroll
    for (int i = 0; i < 4; ++i)
#pragma unroll
        for (int j = 0; j < 8; ++j) hst[i][j] = 0.f;

    for (int t = 0; t < TCH; ++t) {
        cp_wait2();
        __syncthreads();
        if (t + 3 < TCH) issue(t + 3, (t + 3) & 3);
        cp_commit();

        const int s = t & 3;
        const float dA = sS[s][0];
        const float dtv = sS[s][1];
        const float4 xv = *(const float4*)&sx[s][pgrp * 4];
        float bv[8];
        *(float4*)&bv[0] = *(const float4*)&sB[s][ngrp * 8];
        *(float4*)&bv[4] = *(const float4*)&sB[s][ngrp * 8 + 4];
        const float dtx[4] = {dtv * xv.x, dtv * xv.y, dtv * xv.z, dtv * xv.w};
#pragma unroll
        for (int i = 0; i < 4; ++i)
#pragma unroll
            for (int j = 0; j < 8; ++j)
                hst[i][j] = fmaf(dA, hst[i][j], dtx[i] * bv[j]);
    }

    float* st = g_state + (((size_t)(b * NCHUNK + c) * H_ + h)) * (P_ * N_);
#pragma unroll
    for (int i = 0; i < 4; ++i) {
        float* row = st + (pgrp * 4 + i) * N_ + ngrp * 8;
        *(float4*)row = make_float4(hst[i][0], hst[i][1], hst[i][2], hst[i][3]);
        *(float4*)(row + 4) = make_float4(hst[i][4], hst[i][5], hst[i][6], hst[i][7]);
    }
}

// Pass 2: combine chunk states sequentially (parallel over state elements).
__global__ __launch_bounds__(256)
void scan_combine()
{
    const int idx = blockIdx.x * 256 + threadIdx.x;   // B*H*P*N
    if (idx >= B_ * H_ * P_ * N_) return;
    const int h = (idx >> 13) & (H_ - 1);
    const int b = idx >> 18;
    const int pn = idx & (P_ * N_ - 1);
    float carry = 0.f;
#pragma unroll 4
    for (int c = 0; c < NCHUNK; ++c) {
        const size_t off = (((size_t)(b * NCHUNK + c) * H_ + h)) * (P_ * N_) + pn;
        g_init[off] = carry;
        carry = fmaf(g_adec[(b * NCHUNK + c) * H_ + h], carry, g_state[off]);
    }
}

// Pass 3: re-run chunk scan from proper init; emit y.
__global__ __launch_bounds__(256)
void scan_part3()
{
    const int c = blockIdx.x, h = blockIdx.y, b = blockIdx.z;
    const int tid = threadIdx.x;
    const int pgrp = tid >> 4;
    const int ngrp = tid & 15;
    const int t0 = c * TCH;

    __shared__ float sB[4][128];
    __shared__ float sC[4][128];
    __shared__ float sx[4][64];
    __shared__ float sS[4][2];

    auto issue = [&](int t, int s) {
        const float* base = g_conv + (size_t)(b * L_ + t0 + t) * CONV_DIM;
        if (tid < 32)       cp16(s2u(&sB[s][tid * 4]), base + INTER + tid * 4);
        else if (tid < 64)  cp16(s2u(&sC[s][(tid - 32) * 4]), base + INTER + N_ + (tid - 32) * 4);
        else if (tid < 80)  cp16(s2u(&sx[s][(tid - 64) * 4]), base + h * P_ + (tid - 64) * 4);
        else if (tid == 80) cp_async4(s2u(&sS[s][0]), g_dA + (size_t)(b * L_ + t0 + t) * H_ + h);
        else if (tid == 81) cp_async4(s2u(&sS[s][1]), g_dt + (size_t)(b * L_ + t0 + t) * H_ + h);
    };

    for (int t = 0; t < 3; ++t) { issue(t, t); cp_commit(); }

    float hst[4][8];
    {
        const float* st = g_init + (((size_t)(b * NCHUNK + c) * H_ + h)) * (P_ * N_);
#pragma unroll
        for (int i = 0; i < 4; ++i) {
            const float* row = st + (pgrp * 4 + i) * N_ + ngrp * 8;
            const float4 a = *(const float4*)row;
            const float4 d = *(const float4*)(row + 4);
            hst[i][0] = a.x; hst[i][1] = a.y; hst[i][2] = a.z; hst[i][3] = a.w;
            hst[i][4] = d.x; hst[i][5] = d.y; hst[i][6] = d.z; hst[i][7] = d.w;
        }
    }

    for (int t = 0; t < TCH; ++t) {
        cp_wait2();
        __syncthreads();
        if (t + 3 < TCH) issue(t + 3, (t + 3) & 3);
        cp_commit();

        const int s = t & 3;
        const float dA = sS[s][0];
        const float dtv = sS[s][1];
        const float4 xv = *(const float4*)&sx[s][pgrp * 4];
        float bv[8], cv[8];
        *(float4*)&bv[0] = *(const float4*)&sB[s][ngrp * 8];
        *(float4*)&bv[4] = *(const float4*)&sB[s][ngrp * 8 + 4];
        *(float4*)&cv[0] = *(const float4*)&sC[s][ngrp * 8];
        *(float4*)&cv[4] = *(const float4*)&sC[s][ngrp * 8 + 4];
        const float dtx[4] = {dtv * xv.x, dtv * xv.y, dtv * xv.z, dtv * xv.w};
        float y0 = 0.f, y1 = 0.f, y2 = 0.f, y3 = 0.f;
#pragma unroll
        for (int j = 0; j < 8; ++j) {
            hst[0][j] = fmaf(dA, hst[0][j], dtx[0] * bv[j]); y0 = fmaf(hst[0][j], cv[j], y0);
            hst[1][j] = fmaf(dA, hst[1][j], dtx[1] * bv[j]); y1 = fmaf(hst[1][j], cv[j], y1);
            hst[2][j] = fmaf(dA, hst[2][j], dtx[2] * bv[j]); y2 = fmaf(hst[2][j], cv[j], y2);
            hst[3][j] = fmaf(dA, hst[3][j], dtx[3] * bv[j]); y3 = fmaf(hst[3][j], cv[j], y3);
        }
#pragma unroll
        for (int o = 8; o; o >>= 1) {
            y0 += __shfl_xor_sync(0xffffffffu, y0, o);
            y1 += __shfl_xor_sync(0xffffffffu, y1, o);
            y2 += __shfl_xor_sync(0xffffffffu, y2, o);
            y3 += __shfl_xor_sync(0xffffffffu, y3, o);
        }
        if (ngrp == 0) {
            *(float4*)&g_y[(size_t)(b * L_ + t0 + t) * INTER + h * P_ + pgrp * 4] =
                make_float4(y0, y1, y2, y3);
        }
    }
}

// ---------------- y + D*xs, gate*silu, RMSNorm, fused bf16 split -------------
__global__ __launch_bounds__(256)
void gate_rms_kernel(const float* __restrict__ D_param, const float* __restrict__ norm_w)
{
    const int bl = blockIdx.x;
    const int tid = threadIdx.x;
    const float* yrow = g_y + (size_t)bl * INTER;
    const float* grow = g_proj + (size_t)bl * PROJ_PAD;
    const float* xrow = g_conv + (size_t)bl * CONV_DIM;

    float vals[8];
    float ss = 0.f;
#pragma unroll
    for (int r = 0; r < 2; ++r) {
        const int i = tid * 4 + r * 1024;
        const float4 yv = *(const float4*)(yrow + i);
        const float4 gv = *(const float4*)(grow + i);
        const float4 xv = *(const float4*)(xrow + i);
        const float d = D_param[i >> 6];
        float g0 = (yv.x + d * xv.x) * siluf(gv.x);
        float g1 = (yv.y + d * xv.y) * siluf(gv.y);
        float g2 = (yv.z + d * xv.z) * siluf(gv.z);
        float g3 = (yv.w + d * xv.w) * siluf(gv.w);
        vals[r * 4 + 0] = g0; vals[r * 4 + 1] = g1;
        vals[r * 4 + 2] = g2; vals[r * 4 + 3] = g3;
        ss += g0 * g0 + g1 * g1 + g2 * g2 + g3 * g3;
    }

    __shared__ float red[8];
    __shared__ float stot;
#pragma unroll
    for (int o = 16; o; o >>= 1) ss += __shfl_xor_sync(0xffffffffu, ss, o);
    if ((tid & 31) == 0) red[tid >> 5] = ss;
    __syncthreads();
    if (tid == 0) {
        float v = 0.f;
#pragma unroll
        for (int i = 0; i < 8; ++i) v += red[i];
        stot = rsqrtf(v * (1.f / (float)INTER) + EPSV);
    }
    __syncthreads();
    const float rs = stot;

    __nv_bfloat16* yh = g_yh + (size_t)bl * INTER;
    __nv_bfloat16* yl = g_yl + (size_t)bl * INTER;
#pragma unroll
    for (int r = 0; r < 2; ++r) {
        const int i = tid * 4 + r * 1024;
        const float4 nw = *(const float4*)(norm_w + i);
        float o0 = vals[r * 4 + 0] * rs * nw.x;
        float o1 = vals[r * 4 + 1] * rs * nw.y;
        float o2 = vals[r * 4 + 2] * rs * nw.z;
        float o3 = vals[r * 4 + 3] * rs * nw.w;
        __nv_bfloat16 h0 = __float2bfloat16(o0), h1 = __float2bfloat16(o1);
        __nv_bfloat16 h2 = __float2bfloat16(o2), h3 = __float2bfloat16(o3);
        yh[i + 0] = h0; yh[i + 1] = h1; yh[i + 2] = h2; yh[i + 3] = h3;
        yl[i + 0] = __float2bfloat16(o0 - __bfloat162float(h0));
        yl[i + 1] = __float2bfloat16(o1 - __bfloat162float(h1));
        yl[i + 2] = __float2bfloat16(o2 - __bfloat162float(h2));
        yl[i + 3] = __float2bfloat16(o3 - __bfloat162float(h3));
    }
}

// ---------------- launch -----------------------------------------------------
extern "C" void kernel_launch(void* const* d_in, const int* in_sizes, int n_in,
                              void* d_out, int out_size)
{
    const float* hs      = (const float*)d_in[0];
    const float* W_in    = (const float*)d_in[1];
    const float* conv_w  = (const float*)d_in[2];
    const float* conv_b  = (const float*)d_in[3];
    const float* dt_bias = (const float*)d_in[4];
    const float* A_log   = (const float*)d_in[5];
    const float* D_param = (const float*)d_in[6];
    const float* norm_w  = (const float*)d_in[7];
    const float* W_out   = (const float*)d_in[8];
    float* out = (float*)d_out;

    cudaFuncSetAttribute(gemm_mma3, cudaFuncAttributeMaxDynamicSharedMemorySize,
                         GEMM_SMEM_BYTES);

    void *pproj = nullptr;
    void *phh = nullptr, *phl = nullptr, *pwh = nullptr, *pwl = nullptr;
    void *pyh = nullptr, *pyl = nullptr, *poh = nullptr, *pol = nullptr;
    cudaGetSymbolAddress(&pproj, g_proj);
    cudaGetSymbolAddress(&phh, g_hs_hi);
    cudaGetSymbolAddress(&phl, g_hs_lo);
    cudaGetSymbolAddress(&pwh, g_win_hi);
    cudaGetSymbolAddress(&pwl, g_win_lo);
    cudaGetSymbolAddress(&pyh, g_yh);
    cudaGetSymbolAddress(&pyl, g_yl);
    cudaGetSymbolAddress(&poh, g_wo_hi);
    cudaGetSymbolAddress(&pol, g_wo_lo);

    // 0) splits
    {
        const int n4 = B_ * L_ * DM / 4;
        split_kernel<<<(n4 + 255) / 256, 256>>>(hs, (__nv_bfloat16*)phh, (__nv_bfloat16*)phl, n4);
    }
    split_pad_kernel<<<(PROJ_PAD * DM / 4 + 255) / 256, 256>>>(
        W_in, (__nv_bfloat16*)pwh, (__nv_bfloat16*)pwl);
    {
        const int n4 = DM * INTER / 4;
        split_kernel<<<(n4 + 255) / 256, 256>>>(W_out, (__nv_bfloat16*)poh, (__nv_bfloat16*)pol, n4);
    }

    // 1) proj = hs @ W_in^T
    {
        dim3 grid(PROJ_PAD / 128, (B_ * L_) / 128);
        gemm_mma3<<<grid, 512, GEMM_SMEM_BYTES>>>(
            (const __nv_bfloat16*)phh, (const __nv_bfloat16*)phl,
            (const __nv_bfloat16*)pwh, (const __nv_bfloat16*)pwl,
            (float*)pproj, DM, PROJ_PAD);
    }
    // 2) conv + silu
    {
        dim3 grid((CONV_DIM + 255) / 256, B_ * L_);
        conv_kernel<<<grid, 256>>>(conv_w, conv_b);
    }
    // 3) dt / dA
    dt_kernel<<<(B_ * L_ * H_ + 255) / 256, 256>>>(dt_bias, A_log);
    // 4) chunked scan
    adec_kernel<<<(B_ * NCHUNK * H_ + 255) / 256, 256>>>();
    {
        dim3 grid(NCHUNK, H_, B_);
        scan_part1<<<grid, 256>>>();
        scan_combine<<<(B_ * H_ * P_ * N_) / 256, 256>>>();
        scan_part3<<<grid, 256>>>();
    }
    // 5) gate + rmsnorm + split
    gate_rms_kernel<<<B_ * L_, 256>>>(D_param, norm_w);
    // 6) out = g @ W_out^T
    {
        dim3 grid(DM / 128, (B_ * L_) / 128);
        gemm_mma3<<<grid, 512, GEMM_SMEM_BYTES>>>(
            (const __nv_bfloat16*)pyh, (const __nv_bfloat16*)pyl,
            (const __nv_bfloat16*)poh, (const __nv_bfloat16*)pol,
            out, INTER, DM);
    }
}

// round 8
// speedup vs baseline: 1.0963x; 1.0963x over previous
#include <cuda_runtime.h>
#include <cuda_bf16.h>
#include <cstdint>
#include <cstddef>

#define B_ 2
#define L_ 4096
#define DM 2048
#define H_ 32
#define P_ 64
#define N_ 128
#define INTER 2048
#define CONV_DIM 2304
#define PROJ 4384
#define PROJ_PAD 4480
#define EPSV 1e-5f
#define NCHUNK 32
#define TCH 128

// ---------------- scratch (__device__ globals; no allocations allowed) ------
__device__ float g_proj[(size_t)B_ * L_ * PROJ_PAD];
__device__ float g_conv[(size_t)B_ * L_ * CONV_DIM];
__device__ float g_y[(size_t)B_ * L_ * INTER];
__device__ float g_dA[B_ * L_ * H_];
__device__ float g_dt[B_ * L_ * H_];
// chunked-scan scratch
__device__ float g_state[(size_t)B_ * NCHUNK * H_ * P_ * N_];
__device__ float g_init[(size_t)B_ * NCHUNK * H_ * P_ * N_];
__device__ float g_adec[B_ * NCHUNK * H_];
// bf16 split operands
__device__ __nv_bfloat16 g_hs_hi[(size_t)B_ * L_ * DM];
__device__ __nv_bfloat16 g_hs_lo[(size_t)B_ * L_ * DM];
__device__ __nv_bfloat16 g_win_hi[(size_t)PROJ_PAD * DM];
__device__ __nv_bfloat16 g_win_lo[(size_t)PROJ_PAD * DM];
__device__ __nv_bfloat16 g_yh[(size_t)B_ * L_ * INTER];
__device__ __nv_bfloat16 g_yl[(size_t)B_ * L_ * INTER];
__device__ __nv_bfloat16 g_wo_hi[(size_t)DM * INTER];
__device__ __nv_bfloat16 g_wo_lo[(size_t)DM * INTER];

// ---------------- helpers ----------------------------------------------------
__device__ __forceinline__ float siluf(float x) {
    return x * (1.f / (1.f + expf(-x)));
}
__device__ __forceinline__ float softplusf(float x) {
    return (x > 20.f) ? x : log1pf(expf(x));
}
__device__ __forceinline__ uint32_t s2u(const void* p) {
    return (uint32_t)__cvta_generic_to_shared(p);
}
__device__ __forceinline__ void cp_async4(uint32_t saddr, const void* g) {
    asm volatile("cp.async.ca.shared.global [%0], [%1], 4;\n" :: "r"(saddr), "l"(g));
}
__device__ __forceinline__ void cp16(uint32_t saddr, const void* g) {
    asm volatile("cp.async.cg.shared.global [%0], [%1], 16;\n" :: "r"(saddr), "l"(g));
}
__device__ __forceinline__ void cp_commit() {
    asm volatile("cp.async.commit_group;\n" ::: "memory");
}
__device__ __forceinline__ void cp_wait2() {
    asm volatile("cp.async.wait_group 2;\n" ::: "memory");
}

// ---------------- warp-level HMMA plumbing ----------------------------------
__device__ __forceinline__ void ldm_x4(uint32_t* r, uint32_t addr) {
    asm volatile("ldmatrix.sync.aligned.m8n8.x4.shared.b16 {%0,%1,%2,%3}, [%4];"
                 : "=r"(r[0]), "=r"(r[1]), "=r"(r[2]), "=r"(r[3]) : "r"(addr));
}
__device__ __forceinline__ void mma16816(float* d, const uint32_t* a, const uint32_t* b) {
    asm volatile(
        "mma.sync.aligned.m16n8k16.row.col.f32.bf16.bf16.f32 "
        "{%0,%1,%2,%3}, {%4,%5,%6,%7}, {%8,%9}, {%0,%1,%2,%3};"
        : "+f"(d[0]), "+f"(d[1]), "+f"(d[2]), "+f"(d[3])
        : "r"(a[0]), "r"(a[1]), "r"(a[2]), "r"(a[3]), "r"(b[0]), "r"(b[1]));
}

// ---------------- 3-product bf16-split GEMM, 2 CTAs/SM ----------------------
// CTA tile 128x128, BK=32 (64B rows, SW64 swizzle), 3-stage cp.async pipeline.
// 8 warps (256 thr): warp (wid&1) -> m-64-half, (wid>>1) -> n-32-quarter.
// Stage = 4 tensors x 8KB = 32KB; 3 stages = 96KB -> 2 CTAs resident per SM.
#define STAGE_BYTES 32768
#define TEN_BYTES 8192
#define GEMM_SMEM_BYTES (3 * STAGE_BYTES)

__global__ __launch_bounds__(256, 2)
void gemm_mma3(const __nv_bfloat16* __restrict__ Ah, const __nv_bfloat16* __restrict__ Al,
               const __nv_bfloat16* __restrict__ Bh, const __nv_bfloat16* __restrict__ Bl,
               float* __restrict__ C, int K, int ldc)
{
    extern __shared__ __align__(1024) char smem[];
    const uint32_t sb = s2u(smem);
    const int tid = threadIdx.x;
    const int wid = tid >> 5;
    const int lane = tid & 31;
    const int bn = blockIdx.x * 128;
    const int bm = blockIdx.y * 128;
    const int chunks = K >> 5;           // BK = 32

    const int wm = (wid & 1) * 64;
    const int wn = (wid >> 1) * 32;

    // A: 4 m-frags of 16 rows. Row r -> byte row r*64, swizzle ^((r>>1)&3)*16.
    const int rA = wm + (lane & 15);
    const uint32_t selA = (lane & 16) ? 16u : 0u;
    const uint32_t xorA = (uint32_t)(((rA >> 1) & 3) * 16);
    uint32_t rowOffA[4];
#pragma unroll
    for (int mf = 0; mf < 4; ++mf) rowOffA[mf] = (uint32_t)((rA + mf * 16) * 64);

    const int rB = wn + (lane & 7) + ((lane & 16) ? 8 : 0);
    const uint32_t selB = (lane & 8) ? 16u : 0u;
    const uint32_t xorB = (uint32_t)(((rB >> 1) & 3) * 16);
    uint32_t rowOffB[2];
#pragma unroll
    for (int nb = 0; nb < 2; ++nb) rowOffB[nb] = (uint32_t)((rB + nb * 16) * 64);

    // cp.async: per tensor 512 x 16B chunks; thread does 2 per tensor.
    auto issue = [&](int c) {
        const int s = c % 3;
        const uint32_t base = sb + (uint32_t)s * STAGE_BYTES;
        const int k0 = c << 5;
#pragma unroll
        for (int q = 0; q < 2; ++q) {
            const int cc = q * 256 + tid;       // 0..511
            const int row = cc >> 2;
            const int seg = cc & 3;
            const uint32_t dst =
                (uint32_t)(row * 64 + ((seg * 16) ^ (((row >> 1) & 3) * 16)));
            const size_t goffA = (size_t)(bm + row) * K + k0 + seg * 8;
            const size_t goffB = (size_t)(bn + row) * K + k0 + seg * 8;
            cp16(base + 0 * TEN_BYTES + dst, Ah + goffA);
            cp16(base + 1 * TEN_BYTES + dst, Al + goffA);
            cp16(base + 2 * TEN_BYTES + dst, Bh + goffB);
            cp16(base + 3 * TEN_BYTES + dst, Bl + goffB);
        }
    };

    float acc[4][4][4];
#pragma unroll
    for (int i = 0; i < 4; ++i)
#pragma unroll
        for (int j = 0; j < 4; ++j)
#pragma unroll
            for (int q = 0; q < 4; ++q) acc[i][j][q] = 0.f;

    issue(0); cp_commit();
    issue(1); cp_commit();

    for (int c = 0; c < chunks; ++c) {
        if (c + 2 < chunks) issue(c + 2);
        cp_commit();
        cp_wait2();
        __syncthreads();

        const uint32_t base = sb + (uint32_t)(c % 3) * STAGE_BYTES;
        const uint32_t bAh = base;
        const uint32_t bAl = base + TEN_BYTES;
        const uint32_t bBh = base + 2 * TEN_BYTES;
        const uint32_t bBl = base + 3 * TEN_BYTES;

#pragma unroll
        for (int ks = 0; ks < 2; ++ks) {
            const uint32_t cA = ((uint32_t)(ks * 32) + selA) ^ xorA;
            const uint32_t cB = ((uint32_t)(ks * 32) + selB) ^ xorB;
            uint32_t ah[4][4], al[4][4];
#pragma unroll
            for (int mf = 0; mf < 4; ++mf) {
                ldm_x4(ah[mf], bAh + rowOffA[mf] + cA);
                ldm_x4(al[mf], bAl + rowOffA[mf] + cA);
            }
            uint32_t bh[4][2], bl[4][2];
#pragma unroll
            for (int nb = 0; nb < 2; ++nb) {
                uint32_t t[4];
                ldm_x4(t, bBh + rowOffB[nb] + cB);
                bh[nb * 2][0] = t[0]; bh[nb * 2][1] = t[1];
                bh[nb * 2 + 1][0] = t[2]; bh[nb * 2 + 1][1] = t[3];
                ldm_x4(t, bBl + rowOffB[nb] + cB);
                bl[nb * 2][0] = t[0]; bl[nb * 2][1] = t[1];
                bl[nb * 2 + 1][0] = t[2]; bl[nb * 2 + 1][1] = t[3];
            }
#pragma unroll
            for (int mf = 0; mf < 4; ++mf)
#pragma unroll
                for (int nf = 0; nf < 4; ++nf) {
                    mma16816(acc[mf][nf], ah[mf], bh[nf]);
                    mma16816(acc[mf][nf], ah[mf], bl[nf]);
                    mma16816(acc[mf][nf], al[mf], bh[nf]);
                }
        }
        __syncthreads();
    }

    const int g = lane >> 2;
    const int t2 = (lane & 3) * 2;
#pragma unroll
    for (int mf = 0; mf < 4; ++mf) {
#pragma unroll
        for (int nf = 0; nf < 4; ++nf) {
            const int col = bn + wn + nf * 8 + t2;
            const int row0 = bm + wm + mf * 16 + g;
            *(float2*)(C + (size_t)row0 * ldc + col) =
                make_float2(acc[mf][nf][0], acc[mf][nf][1]);
            *(float2*)(C + (size_t)(row0 + 8) * ldc + col) =
                make_float2(acc[mf][nf][2], acc[mf][nf][3]);
        }
    }
}

// ---------------- fp32 -> bf16 hi/lo splits ---------------------------------
__global__ __launch_bounds__(256)
void split_kernel(const float* __restrict__ src, __nv_bfloat16* __restrict__ hi,
                  __nv_bfloat16* __restrict__ lo, int n4)
{
    const int i = blockIdx.x * 256 + threadIdx.x;
    if (i >= n4) return;
    const float4 v = ((const float4*)src)[i];
    __nv_bfloat16 h0 = __float2bfloat16(v.x), h1 = __float2bfloat16(v.y);
    __nv_bfloat16 h2 = __float2bfloat16(v.z), h3 = __float2bfloat16(v.w);
    hi[i * 4 + 0] = h0; hi[i * 4 + 1] = h1; hi[i * 4 + 2] = h2; hi[i * 4 + 3] = h3;
    lo[i * 4 + 0] = __float2bfloat16(v.x - __bfloat162float(h0));
    lo[i * 4 + 1] = __float2bfloat16(v.y - __bfloat162float(h1));
    lo[i * 4 + 2] = __float2bfloat16(v.z - __bfloat162float(h2));
    lo[i * 4 + 3] = __float2bfloat16(v.w - __bfloat162float(h3));
}

__global__ __launch_bounds__(256)
void split_pad_kernel(const float* __restrict__ src, __nv_bfloat16* __restrict__ hi,
                      __nv_bfloat16* __restrict__ lo)
{
    const int i = blockIdx.x * 256 + threadIdx.x;
    if (i >= PROJ_PAD * DM / 4) return;
    const int row = i / (DM / 4);
    float4 v = make_float4(0.f, 0.f, 0.f, 0.f);
    if (row < PROJ) v = ((const float4*)src)[i];
    __nv_bfloat16 h0 = __float2bfloat16(v.x), h1 = __float2bfloat16(v.y);
    __nv_bfloat16 h2 = __float2bfloat16(v.z), h3 = __float2bfloat16(v.w);
    hi[i * 4 + 0] = h0; hi[i * 4 + 1] = h1; hi[i * 4 + 2] = h2; hi[i * 4 + 3] = h3;
    lo[i * 4 + 0] = __float2bfloat16(v.x - __bfloat162float(h0));
    lo[i * 4 + 1] = __float2bfloat16(v.y - __bfloat162float(h1));
    lo[i * 4 + 2] = __float2bfloat16(v.z - __bfloat162float(h2));
    lo[i * 4 + 3] = __float2bfloat16(v.w - __bfloat162float(h3));
}

// ---------------- depthwise causal conv (K=4) + bias + SiLU ------------------
__global__ __launch_bounds__(256)
void conv_kernel(const float* __restrict__ conv_w, const float* __restrict__ conv_b)
{
    const int c = blockIdx.x * 256 + threadIdx.x;
    if (c >= CONV_DIM) return;
    const int bl = blockIdx.y;
    const int l = bl & (L_ - 1);
    float acc = conv_b[c];
    const float* w = conv_w + c * 4;
#pragma unroll
    for (int j = 0; j < 4; ++j) {
        const int ll = l - 3 + j;
        if (ll >= 0)
            acc = fmaf(g_proj[(size_t)(bl + j - 3) * PROJ_PAD + INTER + c], w[j], acc);
    }
    g_conv[(size_t)bl * CONV_DIM + c] = siluf(acc);
}

// ---------------- dt = softplus(dt_raw + bias); dA = exp(dt*A) ---------------
__global__ __launch_bounds__(256)
void dt_kernel(const float* __restrict__ dt_bias, const float* __restrict__ A_log)
{
    const int idx = blockIdx.x * 256 + threadIdx.x;
    if (idx >= B_ * L_ * H_) return;
    const int hh = idx & (H_ - 1);
    const int bl = idx >> 5;
    const float x = g_proj[(size_t)bl * PROJ_PAD + INTER + CONV_DIM + hh] + dt_bias[hh];
    const float dt = softplusf(x);
    const float A = -expf(A_log[hh]);
    g_dt[idx] = dt;
    g_dA[idx] = expf(dt * A);
}

// ---------------- chunked scan ----------------------------------------------
__global__ __launch_bounds__(256)
void adec_kernel()
{
    const int i = blockIdx.x * 256 + threadIdx.x;
    if (i >= B_ * NCHUNK * H_) return;
    const int h = i & (H_ - 1);
    const int c = (i >> 5) & (NCHUNK - 1);
    const int b = i >> 10;
    float p = 1.f;
    const float* base = g_dA + ((size_t)(b * L_ + c * TCH)) * H_ + h;
    for (int t = 0; t < TCH; ++t) p *= base[(size_t)t * H_];
    g_adec[i] = p;
}

__global__ __launch_bounds__(256)
void scan_part1()
{
    const int c = blockIdx.x, h = blockIdx.y, b = blockIdx.z;
    const int tid = threadIdx.x;
    const int pgrp = tid >> 4;
    const int ngrp = tid & 15;
    const int t0 = c * TCH;

    __shared__ float sB[4][128];
    __shared__ float sx[4][64];
    __shared__ float sS[4][2];

    auto issue = [&](int t, int s) {
        const float* base = g_conv + (size_t)(b * L_ + t0 + t) * CONV_DIM;
        if (tid < 32)       cp16(s2u(&sB[s][tid * 4]), base + INTER + tid * 4);
        else if (tid < 48)  cp16(s2u(&sx[s][(tid - 32) * 4]), base + h * P_ + (tid - 32) * 4);
        else if (tid == 48) cp_async4(s2u(&sS[s][0]), g_dA + (size_t)(b * L_ + t0 + t) * H_ + h);
        else if (tid == 49) cp_async4(s2u(&sS[s][1]), g_dt + (size_t)(b * L_ + t0 + t) * H_ + h);
    };

    for (int t = 0; t < 3; ++t) { issue(t, t); cp_commit(); }

    float hst[4][8];
#pragma unroll
    for (int i = 0; i < 4; ++i)
#pragma unroll
        for (int j = 0; j < 8; ++j) hst[i][j] = 0.f;

    for (int t = 0; t < TCH; ++t) {
        cp_wait2();
        __syncthreads();
        if (t + 3 < TCH) issue(t + 3, (t + 3) & 3);
        cp_commit();

        const int s = t & 3;
        const float dA = sS[s][0];
        const float dtv = sS[s][1];
        const float4 xv = *(const float4*)&sx[s][pgrp * 4];
        float bv[8];
        *(float4*)&bv[0] = *(const float4*)&sB[s][ngrp * 8];
        *(float4*)&bv[4] = *(const float4*)&sB[s][ngrp * 8 + 4];
        const float dtx[4] = {dtv * xv.x, dtv * xv.y, dtv * xv.z, dtv * xv.w};
#pragma unroll
        for (int i = 0; i < 4; ++i)
#pragma unroll
            for (int j = 0; j < 8; ++j)
                hst[i][j] = fmaf(dA, hst[i][j], dtx[i] * bv[j]);
    }

    float* st = g_state + (((size_t)(b * NCHUNK + c) * H_ + h)) * (P_ * N_);
#pragma unroll
    for (int i = 0; i < 4; ++i) {
        float* row = st + (pgrp * 4 + i) * N_ + ngrp * 8;
        *(float4*)row = make_float4(hst[i][0], hst[i][1], hst[i][2], hst[i][3]);
        *(float4*)(row + 4) = make_float4(hst[i][4], hst[i][5], hst[i][6], hst[i][7]);
    }
}

__global__ __launch_bounds__(256)
void scan_combine()
{
    const int idx = blockIdx.x * 256 + threadIdx.x;
    if (idx >= B_ * H_ * P_ * N_) return;
    const int h = (idx >> 13) & (H_ - 1);
    const int b = idx >> 18;
    const int pn = idx & (P_ * N_ - 1);
    float carry = 0.f;
#pragma unroll 4
    for (int c = 0; c < NCHUNK; ++c) {
        const size_t off = (((size_t)(b * NCHUNK + c) * H_ + h)) * (P_ * N_) + pn;
        g_init[off] = carry;
        carry = fmaf(g_adec[(b * NCHUNK + c) * H_ + h], carry, g_state[off]);
    }
}

__global__ __launch_bounds__(256)
void scan_part3()
{
    const int c = blockIdx.x, h = blockIdx.y, b = blockIdx.z;
    const int tid = threadIdx.x;
    const int pgrp = tid >> 4;
    const int ngrp = tid & 15;
    const int t0 = c * TCH;

    __shared__ float sB[4][128];
    __shared__ float sC[4][128];
    __shared__ float sx[4][64];
    __shared__ float sS[4][2];

    auto issue = [&](int t, int s) {
        const float* base = g_conv + (size_t)(b * L_ + t0 + t) * CONV_DIM;
        if (tid < 32)       cp16(s2u(&sB[s][tid * 4]), base + INTER + tid * 4);
        else if (tid < 64)  cp16(s2u(&sC[s][(tid - 32) * 4]), base + INTER + N_ + (tid - 32) * 4);
        else if (tid < 80)  cp16(s2u(&sx[s][(tid - 64) * 4]), base + h * P_ + (tid - 64) * 4);
        else if (tid == 80) cp_async4(s2u(&sS[s][0]), g_dA + (size_t)(b * L_ + t0 + t) * H_ + h);
        else if (tid == 81) cp_async4(s2u(&sS[s][1]), g_dt + (size_t)(b * L_ + t0 + t) * H_ + h);
    };

    for (int t = 0; t < 3; ++t) { issue(t, t); cp_commit(); }

    float hst[4][8];
    {
        const float* st = g_init + (((size_t)(b * NCHUNK + c) * H_ + h)) * (P_ * N_);
#pragma unroll
        for (int i = 0; i < 4; ++i) {
            const float* row = st + (pgrp * 4 + i) * N_ + ngrp * 8;
            const float4 a = *(const float4*)row;
            const float4 d = *(const float4*)(row + 4);
            hst[i][0] = a.x; hst[i][1] = a.y; hst[i][2] = a.z; hst[i][3] = a.w;
            hst[i][4] = d.x; hst[i][5] = d.y; hst[i][6] = d.z; hst[i][7] = d.w;
        }
    }

    for (int t = 0; t < TCH; ++t) {
        cp_wait2();
        __syncthreads();
        if (t + 3 < TCH) issue(t + 3, (t + 3) & 3);
        cp_commit();

        const int s = t & 3;
        const float dA = sS[s][0];
        const float dtv = sS[s][1];
        const float4 xv = *(const float4*)&sx[s][pgrp * 4];
        float bv[8], cv[8];
        *(float4*)&bv[0] = *(const float4*)&sB[s][ngrp * 8];
        *(float4*)&bv[4] = *(const float4*)&sB[s][ngrp * 8 + 4];
        *(float4*)&cv[0] = *(const float4*)&sC[s][ngrp * 8];
        *(float4*)&cv[4] = *(const float4*)&sC[s][ngrp * 8 + 4];
        const float dtx[4] = {dtv * xv.x, dtv * xv.y, dtv * xv.z, dtv * xv.w};
        float y0 = 0.f, y1 = 0.f, y2 = 0.f, y3 = 0.f;
#pragma unroll
        for (int j = 0; j < 8; ++j) {
            hst[0][j] = fmaf(dA, hst[0][j], dtx[0] * bv[j]); y0 = fmaf(hst[0][j], cv[j], y0);
            hst[1][j] = fmaf(dA, hst[1][j], dtx[1] * bv[j]); y1 = fmaf(hst[1][j], cv[j], y1);
            hst[2][j] = fmaf(dA, hst[2][j], dtx[2] * bv[j]); y2 = fmaf(hst[2][j], cv[j], y2);
            hst[3][j] = fmaf(dA, hst[3][j], dtx[3] * bv[j]); y3 = fmaf(hst[3][j], cv[j], y3);
        }
#pragma unroll
        for (int o = 8; o; o >>= 1) {
            y0 += __shfl_xor_sync(0xffffffffu, y0, o);
            y1 += __shfl_xor_sync(0xffffffffu, y1, o);
            y2 += __shfl_xor_sync(0xffffffffu, y2, o);
            y3 += __shfl_xor_sync(0xffffffffu, y3, o);
        }
        if (ngrp == 0) {
            *(float4*)&g_y[(size_t)(b * L_ + t0 + t) * INTER + h * P_ + pgrp * 4] =
                make_float4(y0, y1, y2, y3);
        }
    }
}

// ---------------- y + D*xs, gate*silu, RMSNorm, fused bf16 split -------------
__global__ __launch_bounds__(256)
void gate_rms_kernel(const float* __restrict__ D_param, const float* __restrict__ norm_w)
{
    const int bl = blockIdx.x;
    const int tid = threadIdx.x;
    const float* yrow = g_y + (size_t)bl * INTER;
    const float* grow = g_proj + (size_t)bl * PROJ_PAD;
    const float* xrow = g_conv + (size_t)bl * CONV_DIM;

    float vals[8];
    float ss = 0.f;
#pragma unroll
    for (int r = 0; r < 2; ++r) {
        const int i = tid * 4 + r * 1024;
        const float4 yv = *(const float4*)(yrow + i);
        const float4 gv = *(const float4*)(grow + i);
        const float4 xv = *(const float4*)(xrow + i);
        const float d = D_param[i >> 6];
        float g0 = (yv.x + d * xv.x) * siluf(gv.x);
        float g1 = (yv.y + d * xv.y) * siluf(gv.y);
        float g2 = (yv.z + d * xv.z) * siluf(gv.z);
        float g3 = (yv.w + d * xv.w) * siluf(gv.w);
        vals[r * 4 + 0] = g0; vals[r * 4 + 1] = g1;
        vals[r * 4 + 2] = g2; vals[r * 4 + 3] = g3;
        ss += g0 * g0 + g1 * g1 + g2 * g2 + g3 * g3;
    }

    __shared__ float red[8];
    __shared__ float stot;
#pragma unroll
    for (int o = 16; o; o >>= 1) ss += __shfl_xor_sync(0xffffffffu, ss, o);
    if ((tid & 31) == 0) red[tid >> 5] = ss;
    __syncthreads();
    if (tid == 0) {
        float v = 0.f;
#pragma unroll
        for (int i = 0; i < 8; ++i) v += red[i];
        stot = rsqrtf(v * (1.f / (float)INTER) + EPSV);
    }
    __syncthreads();
    const float rs = stot;

    __nv_bfloat16* yh = g_yh + (size_t)bl * INTER;
    __nv_bfloat16* yl = g_yl + (size_t)bl * INTER;
#pragma unroll
    for (int r = 0; r < 2; ++r) {
        const int i = tid * 4 + r * 1024;
        const float4 nw = *(const float4*)(norm_w + i);
        float o0 = vals[r * 4 + 0] * rs * nw.x;
        float o1 = vals[r * 4 + 1] * rs * nw.y;
        float o2 = vals[r * 4 + 2] * rs * nw.z;
        float o3 = vals[r * 4 + 3] * rs * nw.w;
        __nv_bfloat16 h0 = __float2bfloat16(o0), h1 = __float2bfloat16(o1);
        __nv_bfloat16 h2 = __float2bfloat16(o2), h3 = __float2bfloat16(o3);
        yh[i + 0] = h0; yh[i + 1] = h1; yh[i + 2] = h2; yh[i + 3] = h3;
        yl[i + 0] = __float2bfloat16(o0 - __bfloat162float(h0));
        yl[i + 1] = __float2bfloat16(o1 - __bfloat162float(h1));
        yl[i + 2] = __float2bfloat16(o2 - __bfloat162float(h2));
        yl[i + 3] = __float2bfloat16(o3 - __bfloat162float(h3));
    }
}

// ---------------- launch -----------------------------------------------------
extern "C" void kernel_launch(void* const* d_in, const int* in_sizes, int n_in,
                              void* d_out, int out_size)
{
    const float* hs      = (const float*)d_in[0];
    const float* W_in    = (const float*)d_in[1];
    const float* conv_w  = (const float*)d_in[2];
    const float* conv_b  = (const float*)d_in[3];
    const float* dt_bias = (const float*)d_in[4];
    const float* A_log   = (const float*)d_in[5];
    const float* D_param = (const float*)d_in[6];
    const float* norm_w  = (const float*)d_in[7];
    const float* W_out   = (const float*)d_in[8];
    float* out = (float*)d_out;

    cudaFuncSetAttribute(gemm_mma3, cudaFuncAttributeMaxDynamicSharedMemorySize,
                         GEMM_SMEM_BYTES);

    void *pproj = nullptr;
    void *phh = nullptr, *phl = nullptr, *pwh = nullptr, *pwl = nullptr;
    void *pyh = nullptr, *pyl = nullptr, *poh = nullptr, *pol = nullptr;
    cudaGetSymbolAddress(&pproj, g_proj);
    cudaGetSymbolAddress(&phh, g_hs_hi);
    cudaGetSymbolAddress(&phl, g_hs_lo);
    cudaGetSymbolAddress(&pwh, g_win_hi);
    cudaGetSymbolAddress(&pwl, g_win_lo);
    cudaGetSymbolAddress(&pyh, g_yh);
    cudaGetSymbolAddress(&pyl, g_yl);
    cudaGetSymbolAddress(&poh, g_wo_hi);
    cudaGetSymbolAddress(&pol, g_wo_lo);

    // 0) splits
    {
        const int n4 = B_ * L_ * DM / 4;
        split_kernel<<<(n4 + 255) / 256, 256>>>(hs, (__nv_bfloat16*)phh, (__nv_bfloat16*)phl, n4);
    }
    split_pad_kernel<<<(PROJ_PAD * DM / 4 + 255) / 256, 256>>>(
        W_in, (__nv_bfloat16*)pwh, (__nv_bfloat16*)pwl);
    {
        const int n4 = DM * INTER / 4;
        split_kernel<<<(n4 + 255) / 256, 256>>>(W_out, (__nv_bfloat16*)poh, (__nv_bfloat16*)pol, n4);
    }

    // 1) proj = hs @ W_in^T
    {
        dim3 grid(PROJ_PAD / 128, (B_ * L_) / 128);
        gemm_mma3<<<grid, 256, GEMM_SMEM_BYTES>>>(
            (const __nv_bfloat16*)phh, (const __nv_bfloat16*)phl,
            (const __nv_bfloat16*)pwh, (const __nv_bfloat16*)pwl,
            (float*)pproj, DM, PROJ_PAD);
    }
    // 2) conv + silu
    {
        dim3 grid((CONV_DIM + 255) / 256, B_ * L_);
        conv_kernel<<<grid, 256>>>(conv_w, conv_b);
    }
    // 3) dt / dA
    dt_kernel<<<(B_ * L_ * H_ + 255) / 256, 256>>>(dt_bias, A_log);
    // 4) chunked scan
    adec_kernel<<<(B_ * NCHUNK * H_ + 255) / 256, 256>>>();
    {
        dim3 grid(NCHUNK, H_, B_);
        scan_part1<<<grid, 256>>>();
        scan_combine<<<(B_ * H_ * P_ * N_) / 256, 256>>>();
        scan_part3<<<grid, 256>>>();
    }
    // 5) gate + rmsnorm + split
    gate_rms_kernel<<<B_ * L_, 256>>>(D_param, norm_w);
    // 6) out = g @ W_out^T
    {
        dim3 grid(DM / 128, (B_ * L_) / 128);
        gemm_mma3<<<grid, 256, GEMM_SMEM_BYTES>>>(
            (const __nv_bfloat16*)pyh, (const __nv_bfloat16*)pyl,
            (const __nv_bfloat16*)poh, (const __nv_bfloat16*)pol,
            out, INTER, DM);
    }
}

// round 9
// speedup vs baseline: 1.2581x; 1.1476x over previous
#include <cuda_runtime.h>
#include <cuda_bf16.h>
#include <cstdint>
#include <cstddef>

#define B_ 2
#define L_ 4096
#define DM 2048
#define H_ 32
#define P_ 64
#define N_ 128
#define INTER 2048
#define CONV_DIM 2304
#define PROJ 4384
#define PROJ_PAD 4480
#define EPSV 1e-5f
#define NCHUNK 32
#define TCH 128

// ---------------- scratch (__device__ globals; no allocations allowed) ------
__device__ float g_proj[(size_t)B_ * L_ * PROJ_PAD];
__device__ float g_conv[(size_t)B_ * L_ * CONV_DIM];
__device__ float g_y[(size_t)B_ * L_ * INTER];
__device__ float g_dA[B_ * L_ * H_];
__device__ float g_dt[B_ * L_ * H_];
__device__ float g_G[(size_t)B_ * NCHUNK * TCH * TCH];       // C@B^T per (b,c)
__device__ float g_state[(size_t)B_ * NCHUNK * H_ * N_ * P_]; // [n][p]
__device__ float g_init[(size_t)B_ * NCHUNK * H_ * N_ * P_];
__device__ float g_adec[B_ * NCHUNK * H_];
// bf16 split operands
__device__ __nv_bfloat16 g_hs_hi[(size_t)B_ * L_ * DM];
__device__ __nv_bfloat16 g_hs_lo[(size_t)B_ * L_ * DM];
__device__ __nv_bfloat16 g_win_hi[(size_t)PROJ_PAD * DM];
__device__ __nv_bfloat16 g_win_lo[(size_t)PROJ_PAD * DM];
__device__ __nv_bfloat16 g_yh[(size_t)B_ * L_ * INTER];
__device__ __nv_bfloat16 g_yl[(size_t)B_ * L_ * INTER];
__device__ __nv_bfloat16 g_wo_hi[(size_t)DM * INTER];
__device__ __nv_bfloat16 g_wo_lo[(size_t)DM * INTER];

// ---------------- helpers ----------------------------------------------------
__device__ __forceinline__ float siluf(float x) {
    return x * (1.f / (1.f + expf(-x)));
}
__device__ __forceinline__ float softplusf(float x) {
    return (x > 20.f) ? x : log1pf(expf(x));
}
__device__ __forceinline__ uint32_t s2u(const void* p) {
    return (uint32_t)__cvta_generic_to_shared(p);
}
__device__ __forceinline__ void cp_async4(uint32_t saddr, const void* g) {
    asm volatile("cp.async.ca.shared.global [%0], [%1], 4;\n" :: "r"(saddr), "l"(g));
}
__device__ __forceinline__ void cp16(uint32_t saddr, const void* g) {
    asm volatile("cp.async.cg.shared.global [%0], [%1], 16;\n" :: "r"(saddr), "l"(g));
}
__device__ __forceinline__ void cp_commit() {
    asm volatile("cp.async.commit_group;\n" ::: "memory");
}
__device__ __forceinline__ void cp_wait2() {
    asm volatile("cp.async.wait_group 2;\n" ::: "memory");
}
__device__ __forceinline__ uint32_t lds32(uint32_t a) {
    uint32_t v;
    asm volatile("ld.shared.b32 %0, [%1];" : "=r"(v) : "r"(a));
    return v;
}
// e^d for d <= 0, rel err ~3e-7, no MUFU
__device__ __forceinline__ float fast_exp(float d) {
    float y = d * 1.44269504f;
    if (y < -126.f) return 0.f;
    float n = floorf(y);
    float f = y - n;
    float p = 1.33336498e-3f;
    p = fmaf(p, f, 9.61011667e-3f);
    p = fmaf(p, f, 5.55036329e-2f);
    p = fmaf(p, f, 2.40226507e-1f);
    p = fmaf(p, f, 6.93147182e-1f);
    p = fmaf(p, f, 1.0f);
    return p * __int_as_float(((int)n + 127) << 23);
}

// ---------------- warp-level HMMA plumbing ----------------------------------
__device__ __forceinline__ void ldm_x4(uint32_t* r, uint32_t addr) {
    asm volatile("ldmatrix.sync.aligned.m8n8.x4.shared.b16 {%0,%1,%2,%3}, [%4];"
                 : "=r"(r[0]), "=r"(r[1]), "=r"(r[2]), "=r"(r[3]) : "r"(addr));
}
__device__ __forceinline__ void mma16816(float* d, const uint32_t* a, const uint32_t* b) {
    asm volatile(
        "mma.sync.aligned.m16n8k16.row.col.f32.bf16.bf16.f32 "
        "{%0,%1,%2,%3}, {%4,%5,%6,%7}, {%8,%9}, {%0,%1,%2,%3};"
        : "+f"(d[0]), "+f"(d[1]), "+f"(d[2]), "+f"(d[3])
        : "r"(a[0]), "r"(a[1]), "r"(a[2]), "r"(a[3]), "r"(b[0]), "r"(b[1]));
}
// LDS-based fragment loads from 272B-pitch row-major bf16 tiles
__device__ __forceinline__ void ldfragA(uint32_t r[4], uint32_t base) {
    r[0] = lds32(base);        r[1] = lds32(base + 2176);
    r[2] = lds32(base + 16);   r[3] = lds32(base + 2192);
}
__device__ __forceinline__ void ldfragB(uint32_t r[2], uint32_t base) {
    r[0] = lds32(base);        r[1] = lds32(base + 16);
}
__device__ __forceinline__ void split2(float v, __nv_bfloat16* hp, __nv_bfloat16* lp) {
    __nv_bfloat16 h = __float2bfloat16(v);
    *hp = h;
    *lp = __float2bfloat16(v - __bfloat162float(h));
}

// ---------------- 3-product bf16-split GEMM, 2 CTAs/SM (unchanged, R8 winner)
#define STAGE_BYTES 32768
#define TEN_BYTES 8192
#define GEMM_SMEM_BYTES (3 * STAGE_BYTES)

__global__ __launch_bounds__(256, 2)
void gemm_mma3(const __nv_bfloat16* __restrict__ Ah, const __nv_bfloat16* __restrict__ Al,
               const __nv_bfloat16* __restrict__ Bh, const __nv_bfloat16* __restrict__ Bl,
               float* __restrict__ C, int K, int ldc)
{
    extern __shared__ __align__(1024) char smem[];
    const uint32_t sb = s2u(smem);
    const int tid = threadIdx.x;
    const int wid = tid >> 5;
    const int lane = tid & 31;
    const int bn = blockIdx.x * 128;
    const int bm = blockIdx.y * 128;
    const int chunks = K >> 5;

    const int wm = (wid & 1) * 64;
    const int wn = (wid >> 1) * 32;

    const int rA = wm + (lane & 15);
    const uint32_t selA = (lane & 16) ? 16u : 0u;
    const uint32_t xorA = (uint32_t)(((rA >> 1) & 3) * 16);
    uint32_t rowOffA[4];
#pragma unroll
    for (int mf = 0; mf < 4; ++mf) rowOffA[mf] = (uint32_t)((rA + mf * 16) * 64);

    const int rB = wn + (lane & 7) + ((lane & 16) ? 8 : 0);
    const uint32_t selB = (lane & 8) ? 16u : 0u;
    const uint32_t xorB = (uint32_t)(((rB >> 1) & 3) * 16);
    uint32_t rowOffB[2];
#pragma unroll
    for (int nb = 0; nb < 2; ++nb) rowOffB[nb] = (uint32_t)((rB + nb * 16) * 64);

    auto issue = [&](int c) {
        const int s = c % 3;
        const uint32_t base = sb + (uint32_t)s * STAGE_BYTES;
        const int k0 = c << 5;
#pragma unroll
        for (int q = 0; q < 2; ++q) {
            const int cc = q * 256 + tid;
            const int row = cc >> 2;
            const int seg = cc & 3;
            const uint32_t dst =
                (uint32_t)(row * 64 + ((seg * 16) ^ (((row >> 1) & 3) * 16)));
            const size_t goffA = (size_t)(bm + row) * K + k0 + seg * 8;
            const size_t goffB = (size_t)(bn + row) * K + k0 + seg * 8;
            cp16(base + 0 * TEN_BYTES + dst, Ah + goffA);
            cp16(base + 1 * TEN_BYTES + dst, Al + goffA);
            cp16(base + 2 * TEN_BYTES + dst, Bh + goffB);
            cp16(base + 3 * TEN_BYTES + dst, Bl + goffB);
        }
    };

    float acc[4][4][4];
#pragma unroll
    for (int i = 0; i < 4; ++i)
#pragma unroll
        for (int j = 0; j < 4; ++j)
#pragma unroll
            for (int q = 0; q < 4; ++q) acc[i][j][q] = 0.f;

    issue(0); cp_commit();
    issue(1); cp_commit();

    for (int c = 0; c < chunks; ++c) {
        if (c + 2 < chunks) issue(c + 2);
        cp_commit();
        cp_wait2();
        __syncthreads();

        const uint32_t base = sb + (uint32_t)(c % 3) * STAGE_BYTES;
        const uint32_t bAh = base;
        const uint32_t bAl = base + TEN_BYTES;
        const uint32_t bBh = base + 2 * TEN_BYTES;
        const uint32_t bBl = base + 3 * TEN_BYTES;

#pragma unroll
        for (int ks = 0; ks < 2; ++ks) {
            const uint32_t cA = ((uint32_t)(ks * 32) + selA) ^ xorA;
            const uint32_t cB = ((uint32_t)(ks * 32) + selB) ^ xorB;
            uint32_t ah[4][4], al[4][4];
#pragma unroll
            for (int mf = 0; mf < 4; ++mf) {
                ldm_x4(ah[mf], bAh + rowOffA[mf] + cA);
                ldm_x4(al[mf], bAl + rowOffA[mf] + cA);
            }
            uint32_t bh[4][2], bl[4][2];
#pragma unroll
            for (int nb = 0; nb < 2; ++nb) {
                uint32_t t[4];
                ldm_x4(t, bBh + rowOffB[nb] + cB);
                bh[nb * 2][0] = t[0]; bh[nb * 2][1] = t[1];
                bh[nb * 2 + 1][0] = t[2]; bh[nb * 2 + 1][1] = t[3];
                ldm_x4(t, bBl + rowOffB[nb] + cB);
                bl[nb * 2][0] = t[0]; bl[nb * 2][1] = t[1];
                bl[nb * 2 + 1][0] = t[2]; bl[nb * 2 + 1][1] = t[3];
            }
#pragma unroll
            for (int mf = 0; mf < 4; ++mf)
#pragma unroll
                for (int nf = 0; nf < 4; ++nf) {
                    mma16816(acc[mf][nf], ah[mf], bh[nf]);
                    mma16816(acc[mf][nf], ah[mf], bl[nf]);
                    mma16816(acc[mf][nf], al[mf], bh[nf]);
                }
        }
        __syncthreads();
    }

    const int g = lane >> 2;
    const int t2 = (lane & 3) * 2;
#pragma unroll
    for (int mf = 0; mf < 4; ++mf) {
#pragma unroll
        for (int nf = 0; nf < 4; ++nf) {
            const int col = bn + wn + nf * 8 + t2;
            const int row0 = bm + wm + mf * 16 + g;
            *(float2*)(C + (size_t)row0 * ldc + col) =
                make_float2(acc[mf][nf][0], acc[mf][nf][1]);
            *(float2*)(C + (size_t)(row0 + 8) * ldc + col) =
                make_float2(acc[mf][nf][2], acc[mf][nf][3]);
        }
    }
}

// ---------------- fp32 -> bf16 hi/lo splits ---------------------------------
__global__ __launch_bounds__(256)
void split_kernel(const float* __restrict__ src, __nv_bfloat16* __restrict__ hi,
                  __nv_bfloat16* __restrict__ lo, int n4)
{
    const int i = blockIdx.x * 256 + threadIdx.x;
    if (i >= n4) return;
    const float4 v = ((const float4*)src)[i];
    __nv_bfloat16 h0 = __float2bfloat16(v.x), h1 = __float2bfloat16(v.y);
    __nv_bfloat16 h2 = __float2bfloat16(v.z), h3 = __float2bfloat16(v.w);
    hi[i * 4 + 0] = h0; hi[i * 4 + 1] = h1; hi[i * 4 + 2] = h2; hi[i * 4 + 3] = h3;
    lo[i * 4 + 0] = __float2bfloat16(v.x - __bfloat162float(h0));
    lo[i * 4 + 1] = __float2bfloat16(v.y - __bfloat162float(h1));
    lo[i * 4 + 2] = __float2bfloat16(v.z - __bfloat162float(h2));
    lo[i * 4 + 3] = __float2bfloat16(v.w - __bfloat162float(h3));
}

__global__ __launch_bounds__(256)
void split_pad_kernel(const float* __restrict__ src, __nv_bfloat16* __restrict__ hi,
                      __nv_bfloat16* __restrict__ lo)
{
    const int i = blockIdx.x * 256 + threadIdx.x;
    if (i >= PROJ_PAD * DM / 4) return;
    const int row = i / (DM / 4);
    float4 v = make_float4(0.f, 0.f, 0.f, 0.f);
    if (row < PROJ) v = ((const float4*)src)[i];
    __nv_bfloat16 h0 = __float2bfloat16(v.x), h1 = __float2bfloat16(v.y);
    __nv_bfloat16 h2 = __float2bfloat16(v.z), h3 = __float2bfloat16(v.w);
    hi[i * 4 + 0] = h0; hi[i * 4 + 1] = h1; hi[i * 4 + 2] = h2; hi[i * 4 + 3] = h3;
    lo[i * 4 + 0] = __float2bfloat16(v.x - __bfloat162float(h0));
    lo[i * 4 + 1] = __float2bfloat16(v.y - __bfloat162float(h1));
    lo[i * 4 + 2] = __float2bfloat16(v.z - __bfloat162float(h2));
    lo[i * 4 + 3] = __float2bfloat16(v.w - __bfloat162float(h3));
}

// ---------------- depthwise causal conv (K=4) + bias + SiLU ------------------
__global__ __launch_bounds__(256)
void conv_kernel(const float* __restrict__ conv_w, const float* __restrict__ conv_b)
{
    const int c = blockIdx.x * 256 + threadIdx.x;
    if (c >= CONV_DIM) return;
    const int bl = blockIdx.y;
    const int l = bl & (L_ - 1);
    float acc = conv_b[c];
    const float* w = conv_w + c * 4;
#pragma unroll
    for (int j = 0; j < 4; ++j) {
        const int ll = l - 3 + j;
        if (ll >= 0)
            acc = fmaf(g_proj[(size_t)(bl + j - 3) * PROJ_PAD + INTER + c], w[j], acc);
    }
    g_conv[(size_t)bl * CONV_DIM + c] = siluf(acc);
}

// ---------------- dt = softplus(dt_raw + bias); dA = exp(dt*A) ---------------
__global__ __launch_bounds__(256)
void dt_kernel(const float* __restrict__ dt_bias, const float* __restrict__ A_log)
{
    const int idx = blockIdx.x * 256 + threadIdx.x;
    if (idx >= B_ * L_ * H_) return;
    const int hh = idx & (H_ - 1);
    const int bl = idx >> 5;
    const float x = g_proj[(size_t)bl * PROJ_PAD + INTER + CONV_DIM + hh] + dt_bias[hh];
    const float dt = softplusf(x);
    const float A = -expf(A_log[hh]);
    g_dt[idx] = dt;
    g_dA[idx] = expf(dt * A);
}

// ---------------- SSD chunked scan ------------------------------------------
__global__ __launch_bounds__(256)
void adec_kernel()
{
    const int i = blockIdx.x * 256 + threadIdx.x;
    if (i >= B_ * NCHUNK * H_) return;
    const int h = i & (H_ - 1);
    const int c = (i >> 5) & (NCHUNK - 1);
    const int b = i >> 10;
    float p = 1.f;
    const float* base = g_dA + ((size_t)(b * L_ + c * TCH)) * H_ + h;
    for (int t = 0; t < TCH; ++t) p *= base[(size_t)t * H_];
    g_adec[i] = p;
}

// G[b][c][t][s] = sum_n C[t][n] * B[s][n]  (h-independent; FFMA SGEMM)
#define G_SMEM (2 * 128 * 129 * 4)
__global__ __launch_bounds__(256, 1)
void chunk_G_kernel()
{
    const int c = blockIdx.x, b = blockIdx.y;
    extern __shared__ float sg[];
    float* sC = sg;
    float* sB = sg + 128 * 129;
    const int tid = threadIdx.x;
    const int bl0 = b * L_ + c * TCH;
    for (int idx = tid; idx < 128 * 128; idx += 256) {
        const int t = idx >> 7, n = idx & 127;
        const float* row = g_conv + (size_t)(bl0 + t) * CONV_DIM + INTER;
        sB[t * 129 + n] = row[n];
        sC[t * 129 + n] = row[N_ + n];
    }
    __syncthreads();
    const int tt = (tid >> 4) * 8, ss = (tid & 15) * 8;
    float acc[8][8];
#pragma unroll
    for (int i = 0; i < 8; ++i)
#pragma unroll
        for (int j = 0; j < 8; ++j) acc[i][j] = 0.f;
    for (int k = 0; k < 128; ++k) {
        float rc[8], rb[8];
#pragma unroll
        for (int i = 0; i < 8; ++i) rc[i] = sC[(tt + i) * 129 + k];
#pragma unroll
        for (int j = 0; j < 8; ++j) rb[j] = sB[(ss + j) * 129 + k];
#pragma unroll
        for (int i = 0; i < 8; ++i)
#pragma unroll
            for (int j = 0; j < 8; ++j) acc[i][j] = fmaf(rc[i], rb[j], acc[i][j]);
    }
    float* Gp = g_G + (size_t)(b * NCHUNK + c) * (TCH * TCH);
#pragma unroll
    for (int i = 0; i < 8; ++i)
#pragma unroll
        for (int j = 0; j < 8; ++j) Gp[(tt + i) * 128 + ss + j] = acc[i][j];
}

// smem offsets for chunk_state / chunk_y (272B pitch rows)
#define OFF_AH 0
#define OFF_AL 34816
#define OFF_BH 69632
#define OFF_BL 87040
#define OFF_LC 104448
#define OFF_DT 104960
#define OFF_CUM 105472
#define PH_SMEM 105984

// S_partial[n][p] = sum_s exp(lc[127]-lc[s]) dt[s] B[s][n] x[s][p]
__global__ __launch_bounds__(256, 2)
void chunk_state_kernel(const float* __restrict__ A_log)
{
    const int c = blockIdx.x, h = blockIdx.y, b = blockIdx.z;
    extern __shared__ __align__(1024) char sm[];
    const uint32_t sb = s2u(sm);
    float* slc = (float*)(sm + OFF_LC);
    float* sdt = (float*)(sm + OFF_DT);
    const int tid = threadIdx.x;
    const int bl0 = b * L_ + c * TCH;
    const float A = -expf(A_log[h]);

    if (tid < 128) {
        const float d = g_dt[(size_t)(bl0 + tid) * H_ + h];
        sdt[tid] = d;
        slc[tid] = d * A;
    }
    __syncthreads();
    for (int off = 1; off < 128; off <<= 1) {
        float v = 0.f;
        if (tid < 128 && tid >= off) v = slc[tid - off];
        __syncthreads();
        if (tid < 128 && tid >= off) slc[tid] += v;
        __syncthreads();
    }
    const float lcT = slc[127];

    // build wB^T [n][s] and X^T [p][s], bf16 hi/lo
    for (int idx = tid; idx < 128 * 128; idx += 256) {
        const int s = idx >> 7, n = idx & 127;
        const float w = fast_exp(lcT - slc[s]) * sdt[s];
        const float v = g_conv[(size_t)(bl0 + s) * CONV_DIM + INTER + n] * w;
        split2(v, (__nv_bfloat16*)(sm + OFF_AH + n * 272 + s * 2),
                  (__nv_bfloat16*)(sm + OFF_AL + n * 272 + s * 2));
    }
    for (int idx = tid; idx < 128 * 64; idx += 256) {
        const int s = idx >> 6, p = idx & 63;
        const float v = g_conv[(size_t)(bl0 + s) * CONV_DIM + h * P_ + p];
        split2(v, (__nv_bfloat16*)(sm + OFF_BH + p * 272 + s * 2),
                  (__nv_bfloat16*)(sm + OFF_BL + p * 272 + s * 2));
    }
    __syncthreads();

    const int wid = tid >> 5, lane = tid & 31;
    const int wm = (wid & 3) * 32;         // n rows
    const int wn = (wid >> 2) * 32;        // p cols
    const uint32_t laneoff = (uint32_t)((lane >> 2) * 272 + (lane & 3) * 4);

    float acc[2][4][4];
#pragma unroll
    for (int i = 0; i < 2; ++i)
#pragma unroll
        for (int j = 0; j < 4; ++j)
#pragma unroll
            for (int q = 0; q < 4; ++q) acc[i][j][q] = 0.f;

#pragma unroll
    for (int k0 = 0; k0 < 128; k0 += 16) {
        const uint32_t ko = (uint32_t)(k0 * 2) + laneoff;
        uint32_t ah[2][4], al[2][4];
#pragma unroll
        for (int mf = 0; mf < 2; ++mf) {
            const uint32_t rb = (uint32_t)((wm + mf * 16) * 272) + ko;
            ldfragA(ah[mf], sb + OFF_AH + rb);
            ldfragA(al[mf], sb + OFF_AL + rb);
        }
        uint32_t bh[4][2], bl[4][2];
#pragma unroll
        for (int nf = 0; nf < 4; ++nf) {
            const uint32_t pb = (uint32_t)((wn + nf * 8) * 272) + ko;
            ldfragB(bh[nf], sb + OFF_BH + pb);
            ldfragB(bl[nf], sb + OFF_BL + pb);
        }
#pragma unroll
        for (int mf = 0; mf < 2; ++mf)
#pragma unroll
            for (int nf = 0; nf < 4; ++nf) {
                mma16816(acc[mf][nf], ah[mf], bh[nf]);
                mma16816(acc[mf][nf], ah[mf], bl[nf]);
                mma16816(acc[mf][nf], al[mf], bh[nf]);
            }
    }

    float* st = g_state + (size_t)((b * NCHUNK + c) * H_ + h) * (N_ * P_);
    const int g = lane >> 2;
    const int t2 = (lane & 3) * 2;
#pragma unroll
    for (int mf = 0; mf < 2; ++mf)
#pragma unroll
        for (int nf = 0; nf < 4; ++nf) {
            const int n0 = wm + mf * 16 + g;
            const int col = wn + nf * 8 + t2;
            *(float2*)(st + n0 * P_ + col) = make_float2(acc[mf][nf][0], acc[mf][nf][1]);
            *(float2*)(st + (n0 + 8) * P_ + col) = make_float2(acc[mf][nf][2], acc[mf][nf][3]);
        }
}

// combine chunk states sequentially
__global__ __launch_bounds__(256)
void scan_combine()
{
    const int idx = blockIdx.x * 256 + threadIdx.x;
    if (idx >= B_ * H_ * P_ * N_) return;
    const int h = (idx >> 13) & (H_ - 1);
    const int b = idx >> 18;
    const int pn = idx & (P_ * N_ - 1);
    float carry = 0.f;
#pragma unroll 4
    for (int c = 0; c < NCHUNK; ++c) {
        const size_t off = (size_t)((b * NCHUNK + c) * H_ + h) * (P_ * N_) + pn;
        g_init[off] = carry;
        carry = fmaf(g_adec[(b * NCHUNK + c) * H_ + h], carry, g_state[off]);
    }
}

// Y[t][p] = cum[t]*(C @ S_init)[t][p] + ((Gamma.*G) @ X)[t][p]
__global__ __launch_bounds__(256, 2)
void chunk_y_kernel(const float* __restrict__ A_log)
{
    const int c = blockIdx.x, h = blockIdx.y, b = blockIdx.z;
    extern __shared__ __align__(1024) char sm[];
    const uint32_t sb = s2u(sm);
    float* slc = (float*)(sm + OFF_LC);
    float* sdt = (float*)(sm + OFF_DT);
    float* scum = (float*)(sm + OFF_CUM);
    const int tid = threadIdx.x;
    const int bl0 = b * L_ + c * TCH;
    const float A = -expf(A_log[h]);

    if (tid < 128) {
        const float d = g_dt[(size_t)(bl0 + tid) * H_ + h];
        sdt[tid] = d;
        slc[tid] = d * A;
    }
    __syncthreads();
    for (int off = 1; off < 128; off <<= 1) {
        float v = 0.f;
        if (tid < 128 && tid >= off) v = slc[tid - off];
        __syncthreads();
        if (tid < 128 && tid >= off) slc[tid] += v;
        __syncthreads();
    }
    if (tid < 128) scum[tid] = fast_exp(slc[tid]);

    // ---- stage 1: A=C [t][n], B=S_init^T [p][n]
    for (int idx = tid; idx < 128 * 128; idx += 256) {
        const int t = idx >> 7, n = idx & 127;
        const float v = g_conv[(size_t)(bl0 + t) * CONV_DIM + INTER + N_ + n];
        split2(v, (__nv_bfloat16*)(sm + OFF_AH + t * 272 + n * 2),
                  (__nv_bfloat16*)(sm + OFF_AL + t * 272 + n * 2));
    }
    const float* Sini = g_init + (size_t)((b * NCHUNK + c) * H_ + h) * (N_ * P_);
    for (int idx = tid; idx < 128 * 64; idx += 256) {
        const int n = idx >> 6, p = idx & 63;
        const float v = Sini[n * P_ + p];
        split2(v, (__nv_bfloat16*)(sm + OFF_BH + p * 272 + n * 2),
                  (__nv_bfloat16*)(sm + OFF_BL + p * 272 + n * 2));
    }
    __syncthreads();

    const int wid = tid >> 5, lane = tid & 31;
    const int wm = (wid & 3) * 32;     // t rows
    const int wn = (wid >> 2) * 32;    // p cols
    const uint32_t laneoff = (uint32_t)((lane >> 2) * 272 + (lane & 3) * 4);

    float acc[2][4][4];
#pragma unroll
    for (int i = 0; i < 2; ++i)
#pragma unroll
        for (int j = 0; j < 4; ++j)
#pragma unroll
            for (int q = 0; q < 4; ++q) acc[i][j][q] = 0.f;

#pragma unroll
    for (int k0 = 0; k0 < 128; k0 += 16) {
        const uint32_t ko = (uint32_t)(k0 * 2) + laneoff;
        uint32_t ah[2][4], al[2][4];
#pragma unroll
        for (int mf = 0; mf < 2; ++mf) {
            const uint32_t rb = (uint32_t)((wm + mf * 16) * 272) + ko;
            ldfragA(ah[mf], sb + OFF_AH + rb);
            ldfragA(al[mf], sb + OFF_AL + rb);
        }
        uint32_t bh[4][2], bl[4][2];
#pragma unroll
        for (int nf = 0; nf < 4; ++nf) {
            const uint32_t pb = (uint32_t)((wn + nf * 8) * 272) + ko;
            ldfragB(bh[nf], sb + OFF_BH + pb);
            ldfragB(bl[nf], sb + OFF_BL + pb);
        }
#pragma unroll
        for (int mf = 0; mf < 2; ++mf)
#pragma unroll
            for (int nf = 0; nf < 4; ++nf) {
                mma16816(acc[mf][nf], ah[mf], bh[nf]);
                mma16816(acc[mf][nf], ah[mf], bl[nf]);
                mma16816(acc[mf][nf], al[mf], bh[nf]);
            }
    }
    __syncthreads();   // done reading stage-1 smem

    // scale Y_inter rows by cum[t]
    const int g = lane >> 2;
#pragma unroll
    for (int mf = 0; mf < 2; ++mf) {
        const float s0 = scum[wm + mf * 16 + g];
        const float s1 = scum[wm + mf * 16 + g + 8];
#pragma unroll
        for (int nf = 0; nf < 4; ++nf) {
            acc[mf][nf][0] *= s0; acc[mf][nf][1] *= s0;
            acc[mf][nf][2] *= s1; acc[mf][nf][3] *= s1;
        }
    }

    // ---- stage 2: A = Gamma.*G [t][s], B = X^T [p][s]
    const float* Gp = g_G + (size_t)(b * NCHUNK + c) * (TCH * TCH);
    for (int idx = tid; idx < 128 * 128; idx += 256) {
        const int t = idx >> 7, s = idx & 127;
        float val = 0.f;
        if (s <= t) val = fast_exp(slc[t] - slc[s]) * sdt[s] * Gp[idx];
        split2(val, (__nv_bfloat16*)(sm + OFF_AH + t * 272 + s * 2),
                    (__nv_bfloat16*)(sm + OFF_AL + t * 272 + s * 2));
    }
    for (int idx = tid; idx < 128 * 64; idx += 256) {
        const int s = idx >> 6, p = idx & 63;
        const float v = g_conv[(size_t)(bl0 + s) * CONV_DIM + h * P_ + p];
        split2(v, (__nv_bfloat16*)(sm + OFF_BH + p * 272 + s * 2),
                  (__nv_bfloat16*)(sm + OFF_BL + p * 272 + s * 2));
    }
    __syncthreads();

#pragma unroll
    for (int k0 = 0; k0 < 128; k0 += 16) {
        const uint32_t ko = (uint32_t)(k0 * 2) + laneoff;
        uint32_t ah[2][4], al[2][4];
#pragma unroll
        for (int mf = 0; mf < 2; ++mf) {
            const uint32_t rb = (uint32_t)((wm + mf * 16) * 272) + ko;
            ldfragA(ah[mf], sb + OFF_AH + rb);
            ldfragA(al[mf], sb + OFF_AL + rb);
        }
        uint32_t bh[4][2], bl[4][2];
#pragma unroll
        for (int nf = 0; nf < 4; ++nf) {
            const uint32_t pb = (uint32_t)((wn + nf * 8) * 272) + ko;
            ldfragB(bh[nf], sb + OFF_BH + pb);
            ldfragB(bl[nf], sb + OFF_BL + pb);
        }
#pragma unroll
        for (int mf = 0; mf < 2; ++mf)
#pragma unroll
            for (int nf = 0; nf < 4; ++nf) {
                mma16816(acc[mf][nf], ah[mf], bh[nf]);
                mma16816(acc[mf][nf], ah[mf], bl[nf]);
                mma16816(acc[mf][nf], al[mf], bh[nf]);
            }
    }

    const int t2 = (lane & 3) * 2;
#pragma unroll
    for (int mf = 0; mf < 2; ++mf)
#pragma unroll
        for (int nf = 0; nf < 4; ++nf) {
            const int row0 = wm + mf * 16 + g;
            const int col = h * P_ + wn + nf * 8 + t2;
            *(float2*)(g_y + (size_t)(bl0 + row0) * INTER + col) =
                make_float2(acc[mf][nf][0], acc[mf][nf][1]);
            *(float2*)(g_y + (size_t)(bl0 + row0 + 8) * INTER + col) =
                make_float2(acc[mf][nf][2], acc[mf][nf][3]);
        }
}

// ---------------- y + D*xs, gate*silu, RMSNorm, fused bf16 split -------------
__global__ __launch_bounds__(256)
void gate_rms_kernel(const float* __restrict__ D_param, const float* __restrict__ norm_w)
{
    const int bl = blockIdx.x;
    const int tid = threadIdx.x;
    const float* yrow = g_y + (size_t)bl * INTER;
    const float* grow = g_proj + (size_t)bl * PROJ_PAD;
    const float* xrow = g_conv + (size_t)bl * CONV_DIM;

    float vals[8];
    float ss = 0.f;
#pragma unroll
    for (int r = 0; r < 2; ++r) {
        const int i = tid * 4 + r * 1024;
        const float4 yv = *(const float4*)(yrow + i);
        const float4 gv = *(const float4*)(grow + i);
        const float4 xv = *(const float4*)(xrow + i);
        const float d = D_param[i >> 6];
        float g0 = (yv.x + d * xv.x) * siluf(gv.x);
        float g1 = (yv.y + d * xv.y) * siluf(gv.y);
        float g2 = (yv.z + d * xv.z) * siluf(gv.z);
        float g3 = (yv.w + d * xv.w) * siluf(gv.w);
        vals[r * 4 + 0] = g0; vals[r * 4 + 1] = g1;
        vals[r * 4 + 2] = g2; vals[r * 4 + 3] = g3;
        ss += g0 * g0 + g1 * g1 + g2 * g2 + g3 * g3;
    }

    __shared__ float red[8];
    __shared__ float stot;
#pragma unroll
    for (int o = 16; o; o >>= 1) ss += __shfl_xor_sync(0xffffffffu, ss, o);
    if ((tid & 31) == 0) red[tid >> 5] = ss;
    __syncthreads();
    if (tid == 0) {
        float v = 0.f;
#pragma unroll
        for (int i = 0; i < 8; ++i) v += red[i];
        stot = rsqrtf(v * (1.f / (float)INTER) + EPSV);
    }
    __syncthreads();
    const float rs = stot;

    __nv_bfloat16* yh = g_yh + (size_t)bl * INTER;
    __nv_bfloat16* yl = g_yl + (size_t)bl * INTER;
#pragma unroll
    for (int r = 0; r < 2; ++r) {
        const int i = tid * 4 + r * 1024;
        const float4 nw = *(const float4*)(norm_w + i);
        float o0 = vals[r * 4 + 0] * rs * nw.x;
        float o1 = vals[r * 4 + 1] * rs * nw.y;
        float o2 = vals[r * 4 + 2] * rs * nw.z;
        float o3 = vals[r * 4 + 3] * rs * nw.w;
        __nv_bfloat16 h0 = __float2bfloat16(o0), h1 = __float2bfloat16(o1);
        __nv_bfloat16 h2 = __float2bfloat16(o2), h3 = __float2bfloat16(o3);
        yh[i + 0] = h0; yh[i + 1] = h1; yh[i + 2] = h2; yh[i + 3] = h3;
        yl[i + 0] = __float2bfloat16(o0 - __bfloat162float(h0));
        yl[i + 1] = __float2bfloat16(o1 - __bfloat162float(h1));
        yl[i + 2] = __float2bfloat16(o2 - __bfloat162float(h2));
        yl[i + 3] = __float2bfloat16(o3 - __bfloat162float(h3));
    }
}

// ---------------- launch -----------------------------------------------------
extern "C" void kernel_launch(void* const* d_in, const int* in_sizes, int n_in,
                              void* d_out, int out_size)
{
    const float* hs      = (const float*)d_in[0];
    const float* W_in    = (const float*)d_in[1];
    const float* conv_w  = (const float*)d_in[2];
    const float* conv_b  = (const float*)d_in[3];
    const float* dt_bias = (const float*)d_in[4];
    const float* A_log   = (const float*)d_in[5];
    const float* D_param = (const float*)d_in[6];
    const float* norm_w  = (const float*)d_in[7];
    const float* W_out   = (const float*)d_in[8];
    float* out = (float*)d_out;

    cudaFuncSetAttribute(gemm_mma3, cudaFuncAttributeMaxDynamicSharedMemorySize,
                         GEMM_SMEM_BYTES);
    cudaFuncSetAttribute(chunk_G_kernel, cudaFuncAttributeMaxDynamicSharedMemorySize,
                         G_SMEM);
    cudaFuncSetAttribute(chunk_state_kernel, cudaFuncAttributeMaxDynamicSharedMemorySize,
                         PH_SMEM);
    cudaFuncSetAttribute(chunk_y_kernel, cudaFuncAttributeMaxDynamicSharedMemorySize,
                         PH_SMEM);

    void *pproj = nullptr;
    void *phh = nullptr, *phl = nullptr, *pwh = nullptr, *pwl = nullptr;
    void *pyh = nullptr, *pyl = nullptr, *poh = nullptr, *pol = nullptr;
    cudaGetSymbolAddress(&pproj, g_proj);
    cudaGetSymbolAddress(&phh, g_hs_hi);
    cudaGetSymbolAddress(&phl, g_hs_lo);
    cudaGetSymbolAddress(&pwh, g_win_hi);
    cudaGetSymbolAddress(&pwl, g_win_lo);
    cudaGetSymbolAddress(&pyh, g_yh);
    cudaGetSymbolAddress(&pyl, g_yl);
    cudaGetSymbolAddress(&poh, g_wo_hi);
    cudaGetSymbolAddress(&pol, g_wo_lo);

    // 0) splits
    {
        const int n4 = B_ * L_ * DM / 4;
        split_kernel<<<(n4 + 255) / 256, 256>>>(hs, (__nv_bfloat16*)phh, (__nv_bfloat16*)phl, n4);
    }
    split_pad_kernel<<<(PROJ_PAD * DM / 4 + 255) / 256, 256>>>(
        W_in, (__nv_bfloat16*)pwh, (__nv_bfloat16*)pwl);
    {
        const int n4 = DM * INTER / 4;
        split_kernel<<<(n4 + 255) / 256, 256>>>(W_out, (__nv_bfloat16*)poh, (__nv_bfloat16*)pol, n4);
    }

    // 1) proj = hs @ W_in^T
    {
        dim3 grid(PROJ_PAD / 128, (B_ * L_) / 128);
        gemm_mma3<<<grid, 256, GEMM_SMEM_BYTES>>>(
            (const __nv_bfloat16*)phh, (const __nv_bfloat16*)phl,
            (const __nv_bfloat16*)pwh, (const __nv_bfloat16*)pwl,
            (float*)pproj, DM, PROJ_PAD);
    }
    // 2) conv + silu
    {
        dim3 grid((CONV_DIM + 255) / 256, B_ * L_);
        conv_kernel<<<grid, 256>>>(conv_w, conv_b);
    }
    // 3) dt / dA
    dt_kernel<<<(B_ * L_ * H_ + 255) / 256, 256>>>(dt_bias, A_log);
    // 4) SSD chunked scan
    adec_kernel<<<(B_ * NCHUNK * H_ + 255) / 256, 256>>>();
    chunk_G_kernel<<<dim3(NCHUNK, B_), 256, G_SMEM>>>();
    chunk_state_kernel<<<dim3(NCHUNK, H_, B_), 256, PH_SMEM>>>(A_log);
    scan_combine<<<(B_ * H_ * P_ * N_) / 256, 256>>>();
    chunk_y_kernel<<<dim3(NCHUNK, H_, B_), 256, PH_SMEM>>>(A_log);
    // 5) gate + rmsnorm + split
    gate_rms_kernel<<<B_ * L_, 256>>>(D_param, norm_w);
    // 6) out = g @ W_out^T
    {
        dim3 grid(DM / 128, (B_ * L_) / 128);
        gemm_mma3<<<grid, 256, GEMM_SMEM_BYTES>>>(
            (const __nv_bfloat16*)pyh, (const __nv_bfloat16*)pyl,
            (const __nv_bfloat16*)poh, (const __nv_bfloat16*)pol,
            out, INTER, DM);
    }
}

// round 10
// speedup vs baseline: 1.6109x; 1.2805x over previous
#include <cuda_runtime.h>
#include <cuda_bf16.h>
#include <cuda_fp16.h>
#include <cstdint>
#include <cstddef>

#define B_ 2
#define L_ 4096
#define DM 2048
#define H_ 32
#define P_ 64
#define N_ 128
#define INTER 2048
#define CONV_DIM 2304
#define PROJ 4384
#define PROJ_PAD 4480
#define EPSV 1e-5f
#define NCHUNK 32
#define TCH 128

// ---------------- scratch (__device__ globals; no allocations allowed) ------
__device__ float g_proj[(size_t)B_ * L_ * PROJ_PAD];
__device__ float g_conv[(size_t)B_ * L_ * CONV_DIM];
__device__ float g_y[(size_t)B_ * L_ * INTER];
__device__ float g_dA[B_ * L_ * H_];
__device__ float g_dt[B_ * L_ * H_];
__device__ float g_G[(size_t)B_ * NCHUNK * TCH * TCH];
__device__ float g_state[(size_t)B_ * NCHUNK * H_ * N_ * P_];
__device__ float g_init[(size_t)B_ * NCHUNK * H_ * N_ * P_];
__device__ float g_adec[B_ * NCHUNK * H_];
// fp16 GEMM operands (A rounded; B split hi/lo)
__device__ __half g_hs_h[(size_t)B_ * L_ * DM];
__device__ __half g_win_h[(size_t)PROJ_PAD * DM];
__device__ __half g_win_l[(size_t)PROJ_PAD * DM];
__device__ __half g_gate_h[(size_t)B_ * L_ * INTER];
__device__ __half g_wo_h[(size_t)DM * INTER];
__device__ __half g_wo_l[(size_t)DM * INTER];

// ---------------- helpers ----------------------------------------------------
__device__ __forceinline__ float siluf(float x) {
    return x * (1.f / (1.f + expf(-x)));
}
__device__ __forceinline__ float softplusf(float x) {
    return (x > 20.f) ? x : log1pf(expf(x));
}
__device__ __forceinline__ uint32_t s2u(const void* p) {
    return (uint32_t)__cvta_generic_to_shared(p);
}
__device__ __forceinline__ void cp_async4(uint32_t saddr, const void* g) {
    asm volatile("cp.async.ca.shared.global [%0], [%1], 4;\n" :: "r"(saddr), "l"(g));
}
__device__ __forceinline__ void cp16(uint32_t saddr, const void* g) {
    asm volatile("cp.async.cg.shared.global [%0], [%1], 16;\n" :: "r"(saddr), "l"(g));
}
__device__ __forceinline__ void cp_commit() {
    asm volatile("cp.async.commit_group;\n" ::: "memory");
}
__device__ __forceinline__ void cp_wait2() {
    asm volatile("cp.async.wait_group 2;\n" ::: "memory");
}
__device__ __forceinline__ void cp_wait3() {
    asm volatile("cp.async.wait_group 3;\n" ::: "memory");
}
__device__ __forceinline__ uint32_t lds32(uint32_t a) {
    uint32_t v;
    asm volatile("ld.shared.b32 %0, [%1];" : "=r"(v) : "r"(a));
    return v;
}
// e^d for d <= 0, rel err ~3e-7, no MUFU
__device__ __forceinline__ float fast_exp(float d) {
    float y = d * 1.44269504f;
    if (y < -126.f) return 0.f;
    float n = floorf(y);
    float f = y - n;
    float p = 1.33336498e-3f;
    p = fmaf(p, f, 9.61011667e-3f);
    p = fmaf(p, f, 5.55036329e-2f);
    p = fmaf(p, f, 2.40226507e-1f);
    p = fmaf(p, f, 6.93147182e-1f);
    p = fmaf(p, f, 1.0f);
    return p * __int_as_float(((int)n + 127) << 23);
}

// ---------------- warp-level HMMA plumbing ----------------------------------
__device__ __forceinline__ void ldm_x4(uint32_t* r, uint32_t addr) {
    asm volatile("ldmatrix.sync.aligned.m8n8.x4.shared.b16 {%0,%1,%2,%3}, [%4];"
                 : "=r"(r[0]), "=r"(r[1]), "=r"(r[2]), "=r"(r[3]) : "r"(addr));
}
__device__ __forceinline__ void mma16816(float* d, const uint32_t* a, const uint32_t* b) {
    asm volatile(
        "mma.sync.aligned.m16n8k16.row.col.f32.bf16.bf16.f32 "
        "{%0,%1,%2,%3}, {%4,%5,%6,%7}, {%8,%9}, {%0,%1,%2,%3};"
        : "+f"(d[0]), "+f"(d[1]), "+f"(d[2]), "+f"(d[3])
        : "r"(a[0]), "r"(a[1]), "r"(a[2]), "r"(a[3]), "r"(b[0]), "r"(b[1]));
}
__device__ __forceinline__ void mma16816h(float* d, const uint32_t* a, const uint32_t* b) {
    asm volatile(
        "mma.sync.aligned.m16n8k16.row.col.f32.f16.f16.f32 "
        "{%0,%1,%2,%3}, {%4,%5,%6,%7}, {%8,%9}, {%0,%1,%2,%3};"
        : "+f"(d[0]), "+f"(d[1]), "+f"(d[2]), "+f"(d[3])
        : "r"(a[0]), "r"(a[1]), "r"(a[2]), "r"(a[3]), "r"(b[0]), "r"(b[1]));
}
// LDS-based fragment loads from 272B-pitch row-major bf16 tiles
__device__ __forceinline__ void ldfragA(uint32_t r[4], uint32_t base) {
    r[0] = lds32(base);        r[1] = lds32(base + 2176);
    r[2] = lds32(base + 16);   r[3] = lds32(base + 2192);
}
__device__ __forceinline__ void ldfragB(uint32_t r[2], uint32_t base) {
    r[0] = lds32(base);        r[1] = lds32(base + 16);
}
__device__ __forceinline__ void split2(float v, __nv_bfloat16* hp, __nv_bfloat16* lp) {
    __nv_bfloat16 h = __float2bfloat16(v);
    *hp = h;
    *lp = __float2bfloat16(v - __bfloat162float(h));
}

// ---------------- 2-product fp16 GEMM, 4-stage, 2 CTAs/SM -------------------
// C = Ah @ (Bh + Bl)^T ; A rounded to fp16, B split hi/lo fp16.
// CTA tile 128x128, BK=32 (64B rows, SW64), 8 warps, warp tile 64x32.
#define STAGE_BYTES 24576
#define TEN_BYTES 8192
#define GEMM_SMEM_BYTES (4 * STAGE_BYTES)

__global__ __launch_bounds__(256, 2)
void gemm_mma2(const __half* __restrict__ Ah,
               const __half* __restrict__ Bh, const __half* __restrict__ Bl,
               float* __restrict__ C, int K, int ldc)
{
    extern __shared__ __align__(1024) char smem[];
    const uint32_t sb = s2u(smem);
    const int tid = threadIdx.x;
    const int wid = tid >> 5;
    const int lane = tid & 31;
    const int bn = blockIdx.x * 128;
    const int bm = blockIdx.y * 128;
    const int chunks = K >> 5;

    const int wm = (wid & 1) * 64;
    const int wn = (wid >> 1) * 32;

    const int rA = wm + (lane & 15);
    const uint32_t selA = (lane & 16) ? 16u : 0u;
    const uint32_t xorA = (uint32_t)(((rA >> 1) & 3) * 16);
    uint32_t rowOffA[4];
#pragma unroll
    for (int mf = 0; mf < 4; ++mf) rowOffA[mf] = (uint32_t)((rA + mf * 16) * 64);

    const int rB = wn + (lane & 7) + ((lane & 16) ? 8 : 0);
    const uint32_t selB = (lane & 8) ? 16u : 0u;
    const uint32_t xorB = (uint32_t)(((rB >> 1) & 3) * 16);
    uint32_t rowOffB[2];
#pragma unroll
    for (int nb = 0; nb < 2; ++nb) rowOffB[nb] = (uint32_t)((rB + nb * 16) * 64);

    // per stage: 3 tensors x 512 x 16B; 6 cp16 per thread
    auto issue = [&](int c) {
        const int s = c & 3;
        const uint32_t base = sb + (uint32_t)s * STAGE_BYTES;
        const int k0 = c << 5;
#pragma unroll
        for (int q = 0; q < 2; ++q) {
            const int cc = q * 256 + tid;       // 0..511
            const int row = cc >> 2;
            const int seg = cc & 3;
            const uint32_t dst =
                (uint32_t)(row * 64 + ((seg * 16) ^ (((row >> 1) & 3) * 16)));
            const size_t goffA = (size_t)(bm + row) * K + k0 + seg * 8;
            const size_t goffB = (size_t)(bn + row) * K + k0 + seg * 8;
            cp16(base + 0 * TEN_BYTES + dst, Ah + goffA);
            cp16(base + 1 * TEN_BYTES + dst, Bh + goffB);
            cp16(base + 2 * TEN_BYTES + dst, Bl + goffB);
        }
    };

    float acc[4][4][4];
#pragma unroll
    for (int i = 0; i < 4; ++i)
#pragma unroll
        for (int j = 0; j < 4; ++j)
#pragma unroll
            for (int q = 0; q < 4; ++q) acc[i][j][q] = 0.f;

    issue(0); cp_commit();
    issue(1); cp_commit();
    issue(2); cp_commit();

    for (int c = 0; c < chunks; ++c) {
        if (c + 3 < chunks) issue(c + 3);
        cp_commit();
        cp_wait3();
        __syncthreads();

        const uint32_t base = sb + (uint32_t)(c & 3) * STAGE_BYTES;
        const uint32_t bAh = base;
        const uint32_t bBh = base + TEN_BYTES;
        const uint32_t bBl = base + 2 * TEN_BYTES;

#pragma unroll
        for (int ks = 0; ks < 2; ++ks) {
            const uint32_t cA = ((uint32_t)(ks * 32) + selA) ^ xorA;
            const uint32_t cB = ((uint32_t)(ks * 32) + selB) ^ xorB;
            uint32_t ah[4][4];
#pragma unroll
            for (int mf = 0; mf < 4; ++mf)
                ldm_x4(ah[mf], bAh + rowOffA[mf] + cA);
            uint32_t bh[4][2], bl[4][2];
#pragma unroll
            for (int nb = 0; nb < 2; ++nb) {
                uint32_t t[4];
                ldm_x4(t, bBh + rowOffB[nb] + cB);
                bh[nb * 2][0] = t[0]; bh[nb * 2][1] = t[1];
                bh[nb * 2 + 1][0] = t[2]; bh[nb * 2 + 1][1] = t[3];
                ldm_x4(t, bBl + rowOffB[nb] + cB);
                bl[nb * 2][0] = t[0]; bl[nb * 2][1] = t[1];
                bl[nb * 2 + 1][0] = t[2]; bl[nb * 2 + 1][1] = t[3];
            }
#pragma unroll
            for (int mf = 0; mf < 4; ++mf)
#pragma unroll
                for (int nf = 0; nf < 4; ++nf) {
                    mma16816h(acc[mf][nf], ah[mf], bh[nf]);
                    mma16816h(acc[mf][nf], ah[mf], bl[nf]);
                }
        }
        __syncthreads();
    }

    const int g = lane >> 2;
    const int t2 = (lane & 3) * 2;
#pragma unroll
    for (int mf = 0; mf < 4; ++mf) {
#pragma unroll
        for (int nf = 0; nf < 4; ++nf) {
            const int col = bn + wn + nf * 8 + t2;
            const int row0 = bm + wm + mf * 16 + g;
            *(float2*)(C + (size_t)row0 * ldc + col) =
                make_float2(acc[mf][nf][0], acc[mf][nf][1]);
            *(float2*)(C + (size_t)(row0 + 8) * ldc + col) =
                make_float2(acc[mf][nf][2], acc[mf][nf][3]);
        }
    }
}

// ---------------- fp32 -> fp16 conversions ----------------------------------
__global__ __launch_bounds__(256)
void round_h_kernel(const float* __restrict__ src, __half* __restrict__ hi, int n4)
{
    const int i = blockIdx.x * 256 + threadIdx.x;
    if (i >= n4) return;
    const float4 v = ((const float4*)src)[i];
    hi[i * 4 + 0] = __float2half_rn(v.x);
    hi[i * 4 + 1] = __float2half_rn(v.y);
    hi[i * 4 + 2] = __float2half_rn(v.z);
    hi[i * 4 + 3] = __float2half_rn(v.w);
}

__global__ __launch_bounds__(256)
void split_h_kernel(const float* __restrict__ src, __half* __restrict__ hi,
                    __half* __restrict__ lo, int n4)
{
    const int i = blockIdx.x * 256 + threadIdx.x;
    if (i >= n4) return;
    const float4 v = ((const float4*)src)[i];
    __half h0 = __float2half_rn(v.x), h1 = __float2half_rn(v.y);
    __half h2 = __float2half_rn(v.z), h3 = __float2half_rn(v.w);
    hi[i * 4 + 0] = h0; hi[i * 4 + 1] = h1; hi[i * 4 + 2] = h2; hi[i * 4 + 3] = h3;
    lo[i * 4 + 0] = __float2half_rn(v.x - __half2float(h0));
    lo[i * 4 + 1] = __float2half_rn(v.y - __half2float(h1));
    lo[i * 4 + 2] = __float2half_rn(v.z - __half2float(h2));
    lo[i * 4 + 3] = __float2half_rn(v.w - __half2float(h3));
}

__global__ __launch_bounds__(256)
void split_pad_h_kernel(const float* __restrict__ src, __half* __restrict__ hi,
                        __half* __restrict__ lo)
{
    const int i = blockIdx.x * 256 + threadIdx.x;
    if (i >= PROJ_PAD * DM / 4) return;
    const int row = i / (DM / 4);
    float4 v = make_float4(0.f, 0.f, 0.f, 0.f);
    if (row < PROJ) v = ((const float4*)src)[i];
    __half h0 = __float2half_rn(v.x), h1 = __float2half_rn(v.y);
    __half h2 = __float2half_rn(v.z), h3 = __float2half_rn(v.w);
    hi[i * 4 + 0] = h0; hi[i * 4 + 1] = h1; hi[i * 4 + 2] = h2; hi[i * 4 + 3] = h3;
    lo[i * 4 + 0] = __float2half_rn(v.x - __half2float(h0));
    lo[i * 4 + 1] = __float2half_rn(v.y - __half2float(h1));
    lo[i * 4 + 2] = __float2half_rn(v.z - __half2float(h2));
    lo[i * 4 + 3] = __float2half_rn(v.w - __half2float(h3));
}

// ---------------- depthwise causal conv (K=4) + bias + SiLU ------------------
__global__ __launch_bounds__(256)
void conv_kernel(const float* __restrict__ conv_w, const float* __restrict__ conv_b)
{
    const int c = blockIdx.x * 256 + threadIdx.x;
    if (c >= CONV_DIM) return;
    const int bl = blockIdx.y;
    const int l = bl & (L_ - 1);
    float acc = conv_b[c];
    const float* w = conv_w + c * 4;
#pragma unroll
    for (int j = 0; j < 4; ++j) {
        const int ll = l - 3 + j;
        if (ll >= 0)
            acc = fmaf(g_proj[(size_t)(bl + j - 3) * PROJ_PAD + INTER + c], w[j], acc);
    }
    g_conv[(size_t)bl * CONV_DIM + c] = siluf(acc);
}

// ---------------- dt = softplus(dt_raw + bias); dA = exp(dt*A) ---------------
__global__ __launch_bounds__(256)
void dt_kernel(const float* __restrict__ dt_bias, const float* __restrict__ A_log)
{
    const int idx = blockIdx.x * 256 + threadIdx.x;
    if (idx >= B_ * L_ * H_) return;
    const int hh = idx & (H_ - 1);
    const int bl = idx >> 5;
    const float x = g_proj[(size_t)bl * PROJ_PAD + INTER + CONV_DIM + hh] + dt_bias[hh];
    const float dt = softplusf(x);
    const float A = -expf(A_log[hh]);
    g_dt[idx] = dt;
    g_dA[idx] = expf(dt * A);
}

// ---------------- SSD chunked scan ------------------------------------------
__global__ __launch_bounds__(256)
void adec_kernel()
{
    const int i = blockIdx.x * 256 + threadIdx.x;
    if (i >= B_ * NCHUNK * H_) return;
    const int h = i & (H_ - 1);
    const int c = (i >> 5) & (NCHUNK - 1);
    const int b = i >> 10;
    float p = 1.f;
    const float* base = g_dA + ((size_t)(b * L_ + c * TCH)) * H_ + h;
    for (int t = 0; t < TCH; ++t) p *= base[(size_t)t * H_];
    g_adec[i] = p;
}

#define G_SMEM (2 * 128 * 129 * 4)
__global__ __launch_bounds__(256, 1)
void chunk_G_kernel()
{
    const int c = blockIdx.x, b = blockIdx.y;
    extern __shared__ float sg[];
    float* sC = sg;
    float* sB = sg + 128 * 129;
    const int tid = threadIdx.x;
    const int bl0 = b * L_ + c * TCH;
    for (int idx = tid; idx < 128 * 128; idx += 256) {
        const int t = idx >> 7, n = idx & 127;
        const float* row = g_conv + (size_t)(bl0 + t) * CONV_DIM + INTER;
        sB[t * 129 + n] = row[n];
        sC[t * 129 + n] = row[N_ + n];
    }
    __syncthreads();
    const int tt = (tid >> 4) * 8, ss = (tid & 15) * 8;
    float acc[8][8];
#pragma unroll
    for (int i = 0; i < 8; ++i)
#pragma unroll
        for (int j = 0; j < 8; ++j) acc[i][j] = 0.f;
    for (int k = 0; k < 128; ++k) {
        float rc[8], rb[8];
#pragma unroll
        for (int i = 0; i < 8; ++i) rc[i] = sC[(tt + i) * 129 + k];
#pragma unroll
        for (int j = 0; j < 8; ++j) rb[j] = sB[(ss + j) * 129 + k];
#pragma unroll
        for (int i = 0; i < 8; ++i)
#pragma unroll
            for (int j = 0; j < 8; ++j) acc[i][j] = fmaf(rc[i], rb[j], acc[i][j]);
    }
    float* Gp = g_G + (size_t)(b * NCHUNK + c) * (TCH * TCH);
#pragma unroll
    for (int i = 0; i < 8; ++i)
#pragma unroll
        for (int j = 0; j < 8; ++j) Gp[(tt + i) * 128 + ss + j] = acc[i][j];
}

// smem offsets for chunk_state / chunk_y (272B pitch rows)
#define OFF_AH 0
#define OFF_AL 34816
#define OFF_BH 69632
#define OFF_BL 87040
#define OFF_LC 104448
#define OFF_DT 104960
#define OFF_CUM 105472
#define PH_SMEM 105984

__global__ __launch_bounds__(256, 2)
void chunk_state_kernel(const float* __restrict__ A_log)
{
    const int c = blockIdx.x, h = blockIdx.y, b = blockIdx.z;
    extern __shared__ __align__(1024) char sm[];
    const uint32_t sb = s2u(sm);
    float* slc = (float*)(sm + OFF_LC);
    float* sdt = (float*)(sm + OFF_DT);
    const int tid = threadIdx.x;
    const int bl0 = b * L_ + c * TCH;
    const float A = -expf(A_log[h]);

    if (tid < 128) {
        const float d = g_dt[(size_t)(bl0 + tid) * H_ + h];
        sdt[tid] = d;
        slc[tid] = d * A;
    }
    __syncthreads();
    for (int off = 1; off < 128; off <<= 1) {
        float v = 0.f;
        if (tid < 128 && tid >= off) v = slc[tid - off];
        __syncthreads();
        if (tid < 128 && tid >= off) slc[tid] += v;
        __syncthreads();
    }
    const float lcT = slc[127];

    for (int idx = tid; idx < 128 * 128; idx += 256) {
        const int s = idx >> 7, n = idx & 127;
        const float w = fast_exp(lcT - slc[s]) * sdt[s];
        const float v = g_conv[(size_t)(bl0 + s) * CONV_DIM + INTER + n] * w;
        split2(v, (__nv_bfloat16*)(sm + OFF_AH + n * 272 + s * 2),
                  (__nv_bfloat16*)(sm + OFF_AL + n * 272 + s * 2));
    }
    for (int idx = tid; idx < 128 * 64; idx += 256) {
        const int s = idx >> 6, p = idx & 63;
        const float v = g_conv[(size_t)(bl0 + s) * CONV_DIM + h * P_ + p];
        split2(v, (__nv_bfloat16*)(sm + OFF_BH + p * 272 + s * 2),
                  (__nv_bfloat16*)(sm + OFF_BL + p * 272 + s * 2));
    }
    __syncthreads();

    const int wid = tid >> 5, lane = tid & 31;
    const int wm = (wid & 3) * 32;
    const int wn = (wid >> 2) * 32;
    const uint32_t laneoff = (uint32_t)((lane >> 2) * 272 + (lane & 3) * 4);

    float acc[2][4][4];
#pragma unroll
    for (int i = 0; i < 2; ++i)
#pragma unroll
        for (int j = 0; j < 4; ++j)
#pragma unroll
            for (int q = 0; q < 4; ++q) acc[i][j][q] = 0.f;

#pragma unroll
    for (int k0 = 0; k0 < 128; k0 += 16) {
        const uint32_t ko = (uint32_t)(k0 * 2) + laneoff;
        uint32_t ah[2][4], al[2][4];
#pragma unroll
        for (int mf = 0; mf < 2; ++mf) {
            const uint32_t rb = (uint32_t)((wm + mf * 16) * 272) + ko;
            ldfragA(ah[mf], sb + OFF_AH + rb);
            ldfragA(al[mf], sb + OFF_AL + rb);
        }
        uint32_t bh[4][2], bl[4][2];
#pragma unroll
        for (int nf = 0; nf < 4; ++nf) {
            const uint32_t pb = (uint32_t)((wn + nf * 8) * 272) + ko;
            ldfragB(bh[nf], sb + OFF_BH + pb);
            ldfragB(bl[nf], sb + OFF_BL + pb);
        }
#pragma unroll
        for (int mf = 0; mf < 2; ++mf)
#pragma unroll
            for (int nf = 0; nf < 4; ++nf) {
                mma16816(acc[mf][nf], ah[mf], bh[nf]);
                mma16816(acc[mf][nf], ah[mf], bl[nf]);
                mma16816(acc[mf][nf], al[mf], bh[nf]);
            }
    }

    float* st = g_state + (size_t)((b * NCHUNK + c) * H_ + h) * (N_ * P_);
    const int g = lane >> 2;
    const int t2 = (lane & 3) * 2;
#pragma unroll
    for (int mf = 0; mf < 2; ++mf)
#pragma unroll
        for (int nf = 0; nf < 4; ++nf) {
            const int n0 = wm + mf * 16 + g;
            const int col = wn + nf * 8 + t2;
            *(float2*)(st + n0 * P_ + col) = make_float2(acc[mf][nf][0], acc[mf][nf][1]);
            *(float2*)(st + (n0 + 8) * P_ + col) = make_float2(acc[mf][nf][2], acc[mf][nf][3]);
        }
}

__global__ __launch_bounds__(256)
void scan_combine()
{
    const int idx = blockIdx.x * 256 + threadIdx.x;
    if (idx >= B_ * H_ * P_ * N_) return;
    const int h = (idx >> 13) & (H_ - 1);
    const int b = idx >> 18;
    const int pn = idx & (P_ * N_ - 1);
    float carry = 0.f;
#pragma unroll 4
    for (int c = 0; c < NCHUNK; ++c) {
        const size_t off = (size_t)((b * NCHUNK + c) * H_ + h) * (P_ * N_) + pn;
        g_init[off] = carry;
        carry = fmaf(g_adec[(b * NCHUNK + c) * H_ + h], carry, g_state[off]);
    }
}

__global__ __launch_bounds__(256, 2)
void chunk_y_kernel(const float* __restrict__ A_log)
{
    const int c = blockIdx.x, h = blockIdx.y, b = blockIdx.z;
    extern __shared__ __align__(1024) char sm[];
    const uint32_t sb = s2u(sm);
    float* slc = (float*)(sm + OFF_LC);
    float* sdt = (float*)(sm + OFF_DT);
    float* scum = (float*)(sm + OFF_CUM);
    const int tid = threadIdx.x;
    const int bl0 = b * L_ + c * TCH;
    const float A = -expf(A_log[h]);

    if (tid < 128) {
        const float d = g_dt[(size_t)(bl0 + tid) * H_ + h];
        sdt[tid] = d;
        slc[tid] = d * A;
    }
    __syncthreads();
    for (int off = 1; off < 128; off <<= 1) {
        float v = 0.f;
        if (tid < 128 && tid >= off) v = slc[tid - off];
        __syncthreads();
        if (tid < 128 && tid >= off) slc[tid] += v;
        __syncthreads();
    }
    if (tid < 128) scum[tid] = fast_exp(slc[tid]);

    for (int idx = tid; idx < 128 * 128; idx += 256) {
        const int t = idx >> 7, n = idx & 127;
        const float v = g_conv[(size_t)(bl0 + t) * CONV_DIM + INTER + N_ + n];
        split2(v, (__nv_bfloat16*)(sm + OFF_AH + t * 272 + n * 2),
                  (__nv_bfloat16*)(sm + OFF_AL + t * 272 + n * 2));
    }
    const float* Sini = g_init + (size_t)((b * NCHUNK + c) * H_ + h) * (N_ * P_);
    for (int idx = tid; idx < 128 * 64; idx += 256) {
        const int n = idx >> 6, p = idx & 63;
        const float v = Sini[n * P_ + p];
        split2(v, (__nv_bfloat16*)(sm + OFF_BH + p * 272 + n * 2),
                  (__nv_bfloat16*)(sm + OFF_BL + p * 272 + n * 2));
    }
    __syncthreads();

    const int wid = tid >> 5, lane = tid & 31;
    const int wm = (wid & 3) * 32;
    const int wn = (wid >> 2) * 32;
    const uint32_t laneoff = (uint32_t)((lane >> 2) * 272 + (lane & 3) * 4);

    float acc[2][4][4];
#pragma unroll
    for (int i = 0; i < 2; ++i)
#pragma unroll
        for (int j = 0; j < 4; ++j)
#pragma unroll
            for (int q = 0; q < 4; ++q) acc[i][j][q] = 0.f;

#pragma unroll
    for (int k0 = 0; k0 < 128; k0 += 16) {
        const uint32_t ko = (uint32_t)(k0 * 2) + laneoff;
        uint32_t ah[2][4], al[2][4];
#pragma unroll
        for (int mf = 0; mf < 2; ++mf) {
            const uint32_t rb = (uint32_t)((wm + mf * 16) * 272) + ko;
            ldfragA(ah[mf], sb + OFF_AH + rb);
            ldfragA(al[mf], sb + OFF_AL + rb);
        }
        uint32_t bh[4][2], bl[4][2];
#pragma unroll
        for (int nf = 0; nf < 4; ++nf) {
            const uint32_t pb = (uint32_t)((wn + nf * 8) * 272) + ko;
            ldfragB(bh[nf], sb + OFF_BH + pb);
            ldfragB(bl[nf], sb + OFF_BL + pb);
        }
#pragma unroll
        for (int mf = 0; mf < 2; ++mf)
#pragma unroll
            for (int nf = 0; nf < 4; ++nf) {
                mma16816(acc[mf][nf], ah[mf], bh[nf]);
                mma16816(acc[mf][nf], ah[mf], bl[nf]);
                mma16816(acc[mf][nf], al[mf], bh[nf]);
            }
    }
    __syncthreads();

    const int g = lane >> 2;
#pragma unroll
    for (int mf = 0; mf < 2; ++mf) {
        const float s0 = scum[wm + mf * 16 + g];
        const float s1 = scum[wm + mf * 16 + g + 8];
#pragma unroll
        for (int nf = 0; nf < 4; ++nf) {
            acc[mf][nf][0] *= s0; acc[mf][nf][1] *= s0;
            acc[mf][nf][2] *= s1; acc[mf][nf][3] *= s1;
        }
    }

    const float* Gp = g_G + (size_t)(b * NCHUNK + c) * (TCH * TCH);
    for (int idx = tid; idx < 128 * 128; idx += 256) {
        const int t = idx >> 7, s = idx & 127;
        float val = 0.f;
        if (s <= t) val = fast_exp(slc[t] - slc[s]) * sdt[s] * Gp[idx];
        split2(val, (__nv_bfloat16*)(sm + OFF_AH + t * 272 + s * 2),
                    (__nv_bfloat16*)(sm + OFF_AL + t * 272 + s * 2));
    }
    for (int idx = tid; idx < 128 * 64; idx += 256) {
        const int s = idx >> 6, p = idx & 63;
        const float v = g_conv[(size_t)(bl0 + s) * CONV_DIM + h * P_ + p];
        split2(v, (__nv_bfloat16*)(sm + OFF_BH + p * 272 + s * 2),
                  (__nv_bfloat16*)(sm + OFF_BL + p * 272 + s * 2));
    }
    __syncthreads();

#pragma unroll
    for (int k0 = 0; k0 < 128; k0 += 16) {
        const uint32_t ko = (uint32_t)(k0 * 2) + laneoff;
        uint32_t ah[2][4], al[2][4];
#pragma unroll
        for (int mf = 0; mf < 2; ++mf) {
            const uint32_t rb = (uint32_t)((wm + mf * 16) * 272) + ko;
            ldfragA(ah[mf], sb + OFF_AH + rb);
            ldfragA(al[mf], sb + OFF_AL + rb);
        }
        uint32_t bh[4][2], bl[4][2];
#pragma unroll
        for (int nf = 0; nf < 4; ++nf) {
            const uint32_t pb = (uint32_t)((wn + nf * 8) * 272) + ko;
            ldfragB(bh[nf], sb + OFF_BH + pb);
            ldfragB(bl[nf], sb + OFF_BL + pb);
        }
#pragma unroll
        for (int mf = 0; mf < 2; ++mf)
#pragma unroll
            for (int nf = 0; nf < 4; ++nf) {
                mma16816(acc[mf][nf], ah[mf], bh[nf]);
                mma16816(acc[mf][nf], ah[mf], bl[nf]);
                mma16816(acc[mf][nf], al[mf], bh[nf]);
            }
    }

    const int t2 = (lane & 3) * 2;
#pragma unroll
    for (int mf = 0; mf < 2; ++mf)
#pragma unroll
        for (int nf = 0; nf < 4; ++nf) {
            const int row0 = wm + mf * 16 + g;
            const int col = h * P_ + wn + nf * 8 + t2;
            *(float2*)(g_y + (size_t)(bl0 + row0) * INTER + col) =
                make_float2(acc[mf][nf][0], acc[mf][nf][1]);
            *(float2*)(g_y + (size_t)(bl0 + row0 + 8) * INTER + col) =
                make_float2(acc[mf][nf][2], acc[mf][nf][3]);
        }
}

// ---------------- y + D*xs, gate*silu, RMSNorm, fp16 round ------------------
__global__ __launch_bounds__(256)
void gate_rms_kernel(const float* __restrict__ D_param, const float* __restrict__ norm_w)
{
    const int bl = blockIdx.x;
    const int tid = threadIdx.x;
    const float* yrow = g_y + (size_t)bl * INTER;
    const float* grow = g_proj + (size_t)bl * PROJ_PAD;
    const float* xrow = g_conv + (size_t)bl * CONV_DIM;

    float vals[8];
    float ss = 0.f;
#pragma unroll
    for (int r = 0; r < 2; ++r) {
        const int i = tid * 4 + r * 1024;
        const float4 yv = *(const float4*)(yrow + i);
        const float4 gv = *(const float4*)(grow + i);
        const float4 xv = *(const float4*)(xrow + i);
        const float d = D_param[i >> 6];
        float g0 = (yv.x + d * xv.x) * siluf(gv.x);
        float g1 = (yv.y + d * xv.y) * siluf(gv.y);
        float g2 = (yv.z + d * xv.z) * siluf(gv.z);
        float g3 = (yv.w + d * xv.w) * siluf(gv.w);
        vals[r * 4 + 0] = g0; vals[r * 4 + 1] = g1;
        vals[r * 4 + 2] = g2; vals[r * 4 + 3] = g3;
        ss += g0 * g0 + g1 * g1 + g2 * g2 + g3 * g3;
    }

    __shared__ float red[8];
    __shared__ float stot;
#pragma unroll
    for (int o = 16; o; o >>= 1) ss += __shfl_xor_sync(0xffffffffu, ss, o);
    if ((tid & 31) == 0) red[tid >> 5] = ss;
    __syncthreads();
    if (tid == 0) {
        float v = 0.f;
#pragma unroll
        for (int i = 0; i < 8; ++i) v += red[i];
        stot = rsqrtf(v * (1.f / (float)INTER) + EPSV);
    }
    __syncthreads();
    const float rs = stot;

    __half* gh = g_gate_h + (size_t)bl * INTER;
#pragma unroll
    for (int r = 0; r < 2; ++r) {
        const int i = tid * 4 + r * 1024;
        const float4 nw = *(const float4*)(norm_w + i);
        gh[i + 0] = __float2half_rn(vals[r * 4 + 0] * rs * nw.x);
        gh[i + 1] = __float2half_rn(vals[r * 4 + 1] * rs * nw.y);
        gh[i + 2] = __float2half_rn(vals[r * 4 + 2] * rs * nw.z);
        gh[i + 3] = __float2half_rn(vals[r * 4 + 3] * rs * nw.w);
    }
}

// ---------------- launch -----------------------------------------------------
extern "C" void kernel_launch(void* const* d_in, const int* in_sizes, int n_in,
                              void* d_out, int out_size)
{
    const float* hs      = (const float*)d_in[0];
    const float* W_in    = (const float*)d_in[1];
    const float* conv_w  = (const float*)d_in[2];
    const float* conv_b  = (const float*)d_in[3];
    const float* dt_bias = (const float*)d_in[4];
    const float* A_log   = (const float*)d_in[5];
    const float* D_param = (const float*)d_in[6];
    const float* norm_w  = (const float*)d_in[7];
    const float* W_out   = (const float*)d_in[8];
    float* out = (float*)d_out;

    cudaFuncSetAttribute(gemm_mma2, cudaFuncAttributeMaxDynamicSharedMemorySize,
                         GEMM_SMEM_BYTES);
    cudaFuncSetAttribute(chunk_G_kernel, cudaFuncAttributeMaxDynamicSharedMemorySize,
                         G_SMEM);
    cudaFuncSetAttribute(chunk_state_kernel, cudaFuncAttributeMaxDynamicSharedMemorySize,
                         PH_SMEM);
    cudaFuncSetAttribute(chunk_y_kernel, cudaFuncAttributeMaxDynamicSharedMemorySize,
                         PH_SMEM);

    void *pproj = nullptr;
    void *phh = nullptr, *pwh = nullptr, *pwl = nullptr;
    void *pgh = nullptr, *poh = nullptr, *pol = nullptr;
    cudaGetSymbolAddress(&pproj, g_proj);
    cudaGetSymbolAddress(&phh, g_hs_h);
    cudaGetSymbolAddress(&pwh, g_win_h);
    cudaGetSymbolAddress(&pwl, g_win_l);
    cudaGetSymbolAddress(&pgh, g_gate_h);
    cudaGetSymbolAddress(&poh, g_wo_h);
    cudaGetSymbolAddress(&pol, g_wo_l);

    // 0) conversions
    {
        const int n4 = B_ * L_ * DM / 4;
        round_h_kernel<<<(n4 + 255) / 256, 256>>>(hs, (__half*)phh, n4);
    }
    split_pad_h_kernel<<<(PROJ_PAD * DM / 4 + 255) / 256, 256>>>(
        W_in, (__half*)pwh, (__half*)pwl);
    {
        const int n4 = DM * INTER / 4;
        split_h_kernel<<<(n4 + 255) / 256, 256>>>(W_out, (__half*)poh, (__half*)pol, n4);
    }

    // 1) proj = hs @ W_in^T
    {
        dim3 grid(PROJ_PAD / 128, (B_ * L_) / 128);
        gemm_mma2<<<grid, 256, GEMM_SMEM_BYTES>>>(
            (const __half*)phh, (const __half*)pwh, (const __half*)pwl,
            (float*)pproj, DM, PROJ_PAD);
    }
    // 2) conv + silu
    {
        dim3 grid((CONV_DIM + 255) / 256, B_ * L_);
        conv_kernel<<<grid, 256>>>(conv_w, conv_b);
    }
    // 3) dt / dA
    dt_kernel<<<(B_ * L_ * H_ + 255) / 256, 256>>>(dt_bias, A_log);
    // 4) SSD chunked scan
    adec_kernel<<<(B_ * NCHUNK * H_ + 255) / 256, 256>>>();
    chunk_G_kernel<<<dim3(NCHUNK, B_), 256, G_SMEM>>>();
    chunk_state_kernel<<<dim3(NCHUNK, H_, B_), 256, PH_SMEM>>>(A_log);
    scan_combine<<<(B_ * H_ * P_ * N_) / 256, 256>>>();
    chunk_y_kernel<<<dim3(NCHUNK, H_, B_), 256, PH_SMEM>>>(A_log);
    // 5) gate + rmsnorm + fp16 round
    gate_rms_kernel<<<B_ * L_, 256>>>(D_param, norm_w);
    // 6) out = g @ W_out^T
    {
        dim3 grid(DM / 128, (B_ * L_) / 128);
        gemm_mma2<<<grid, 256, GEMM_SMEM_BYTES>>>(
            (const __half*)pgh, (const __half*)poh, (const __half*)pol,
            out, INTER, DM);
    }
}

// round 11
// speedup vs baseline: 1.6434x; 1.0201x over previous
#include <cuda_runtime.h>
#include <cuda_bf16.h>
#include <cuda_fp16.h>
#include <cstdint>
#include <cstddef>

#define B_ 2
#define L_ 4096
#define DM 2048
#define H_ 32
#define P_ 64
#define N_ 128
#define INTER 2048
#define CONV_DIM 2304
#define PROJ 4384
#define PROJ_PAD 4480
#define EPSV 1e-5f
#define NCHUNK 32
#define TCH 128

// ---------------- scratch (__device__ globals; no allocations allowed) ------
__device__ float g_proj[(size_t)B_ * L_ * PROJ_PAD];
__device__ float g_conv[(size_t)B_ * L_ * CONV_DIM];
__device__ float g_y[(size_t)B_ * L_ * INTER];
__device__ float g_dA[B_ * L_ * H_];
__device__ float g_dt[B_ * L_ * H_];
__device__ float g_G[(size_t)B_ * NCHUNK * TCH * TCH];
__device__ float g_state[(size_t)B_ * NCHUNK * H_ * N_ * P_];
__device__ float g_init[(size_t)B_ * NCHUNK * H_ * N_ * P_];
__device__ float g_adec[B_ * NCHUNK * H_];
// fp16 GEMM operands (A rounded; B split hi/lo)
__device__ __half g_hs_h[(size_t)B_ * L_ * DM];
__device__ __half g_win_h[(size_t)PROJ_PAD * DM];
__device__ __half g_win_l[(size_t)PROJ_PAD * DM];
__device__ __half g_gate_h[(size_t)B_ * L_ * INTER];
__device__ __half g_wo_h[(size_t)DM * INTER];
__device__ __half g_wo_l[(size_t)DM * INTER];

// ---------------- helpers ----------------------------------------------------
__device__ __forceinline__ float siluf(float x) {
    return x * (1.f / (1.f + expf(-x)));
}
__device__ __forceinline__ float softplusf(float x) {
    return (x > 20.f) ? x : log1pf(expf(x));
}
__device__ __forceinline__ uint32_t s2u(const void* p) {
    return (uint32_t)__cvta_generic_to_shared(p);
}
__device__ __forceinline__ void cp_async4(uint32_t saddr, const void* g) {
    asm volatile("cp.async.ca.shared.global [%0], [%1], 4;\n" :: "r"(saddr), "l"(g));
}
__device__ __forceinline__ void cp16(uint32_t saddr, const void* g) {
    asm volatile("cp.async.cg.shared.global [%0], [%1], 16;\n" :: "r"(saddr), "l"(g));
}
__device__ __forceinline__ void cp_commit() {
    asm volatile("cp.async.commit_group;\n" ::: "memory");
}
__device__ __forceinline__ void cp_wait2() {
    asm volatile("cp.async.wait_group 2;\n" ::: "memory");
}
__device__ __forceinline__ uint32_t lds32(uint32_t a) {
    uint32_t v;
    asm volatile("ld.shared.b32 %0, [%1];" : "=r"(v) : "r"(a));
    return v;
}
// e^d for d <= 0, rel err ~3e-7, no MUFU
__device__ __forceinline__ float fast_exp(float d) {
    float y = d * 1.44269504f;
    if (y < -126.f) return 0.f;
    float n = floorf(y);
    float f = y - n;
    float p = 1.33336498e-3f;
    p = fmaf(p, f, 9.61011667e-3f);
    p = fmaf(p, f, 5.55036329e-2f);
    p = fmaf(p, f, 2.40226507e-1f);
    p = fmaf(p, f, 6.93147182e-1f);
    p = fmaf(p, f, 1.0f);
    return p * __int_as_float(((int)n + 127) << 23);
}

// ---------------- warp-level HMMA plumbing ----------------------------------
__device__ __forceinline__ void ldm_x4(uint32_t* r, uint32_t addr) {
    asm volatile("ldmatrix.sync.aligned.m8n8.x4.shared.b16 {%0,%1,%2,%3}, [%4];"
                 : "=r"(r[0]), "=r"(r[1]), "=r"(r[2]), "=r"(r[3]) : "r"(addr));
}
__device__ __forceinline__ void mma16816(float* d, const uint32_t* a, const uint32_t* b) {
    asm volatile(
        "mma.sync.aligned.m16n8k16.row.col.f32.bf16.bf16.f32 "
        "{%0,%1,%2,%3}, {%4,%5,%6,%7}, {%8,%9}, {%0,%1,%2,%3};"
        : "+f"(d[0]), "+f"(d[1]), "+f"(d[2]), "+f"(d[3])
        : "r"(a[0]), "r"(a[1]), "r"(a[2]), "r"(a[3]), "r"(b[0]), "r"(b[1]));
}
__device__ __forceinline__ void mma16816h(float* d, const uint32_t* a, const uint32_t* b) {
    asm volatile(
        "mma.sync.aligned.m16n8k16.row.col.f32.f16.f16.f32 "
        "{%0,%1,%2,%3}, {%4,%5,%6,%7}, {%8,%9}, {%0,%1,%2,%3};"
        : "+f"(d[0]), "+f"(d[1]), "+f"(d[2]), "+f"(d[3])
        : "r"(a[0]), "r"(a[1]), "r"(a[2]), "r"(a[3]), "r"(b[0]), "r"(b[1]));
}
// LDS-based fragment loads from 272B-pitch row-major bf16 tiles
__device__ __forceinline__ void ldfragA(uint32_t r[4], uint32_t base) {
    r[0] = lds32(base);        r[1] = lds32(base + 2176);
    r[2] = lds32(base + 16);   r[3] = lds32(base + 2192);
}
__device__ __forceinline__ void ldfragB(uint32_t r[2], uint32_t base) {
    r[0] = lds32(base);        r[1] = lds32(base + 16);
}
__device__ __forceinline__ void split2(float v, __nv_bfloat16* hp, __nv_bfloat16* lp) {
    __nv_bfloat16 h = __float2bfloat16(v);
    *hp = h;
    *lp = __float2bfloat16(v - __bfloat162float(h));
}

// ---------------- 2-product fp16 GEMM, 4-stage, 2 CTAs/SM, 1 barrier/chunk --
// C = Ah @ (Bh + Bl)^T ; A rounded to fp16, B split hi/lo fp16.
// CTA tile 128x128, BK=32 (64B rows, SW64), 8 warps, warp tile 64x32.
// Loop: wait(<=2 outstanding) -> barrier -> issue next -> compute. The single
// barrier orders both "stage c data visible to all" and "all readers of the
// stage about to be overwritten are done" (write target is (c-1)&3, whose
// readers finished before this barrier).
#define STAGE_BYTES 24576
#define TEN_BYTES 8192
#define GEMM_SMEM_BYTES (4 * STAGE_BYTES)

__global__ __launch_bounds__(256, 2)
void gemm_mma2(const __half* __restrict__ Ah,
               const __half* __restrict__ Bh, const __half* __restrict__ Bl,
               float* __restrict__ C, int K, int ldc)
{
    extern __shared__ __align__(1024) char smem[];
    const uint32_t sb = s2u(smem);
    const int tid = threadIdx.x;
    const int wid = tid >> 5;
    const int lane = tid & 31;
    const int bn = blockIdx.x * 128;
    const int bm = blockIdx.y * 128;
    const int chunks = K >> 5;

    const int wm = (wid & 1) * 64;
    const int wn = (wid >> 1) * 32;

    const int rA = wm + (lane & 15);
    const uint32_t selA = (lane & 16) ? 16u : 0u;
    const uint32_t xorA = (uint32_t)(((rA >> 1) & 3) * 16);
    uint32_t rowOffA[4];
#pragma unroll
    for (int mf = 0; mf < 4; ++mf) rowOffA[mf] = (uint32_t)((rA + mf * 16) * 64);

    const int rB = wn + (lane & 7) + ((lane & 16) ? 8 : 0);
    const uint32_t selB = (lane & 8) ? 16u : 0u;
    const uint32_t xorB = (uint32_t)(((rB >> 1) & 3) * 16);
    uint32_t rowOffB[2];
#pragma unroll
    for (int nb = 0; nb < 2; ++nb) rowOffB[nb] = (uint32_t)((rB + nb * 16) * 64);

    auto issue = [&](int c) {
        const int s = c & 3;
        const uint32_t base = sb + (uint32_t)s * STAGE_BYTES;
        const int k0 = c << 5;
#pragma unroll
        for (int q = 0; q < 2; ++q) {
            const int cc = q * 256 + tid;       // 0..511
            const int row = cc >> 2;
            const int seg = cc & 3;
            const uint32_t dst =
                (uint32_t)(row * 64 + ((seg * 16) ^ (((row >> 1) & 3) * 16)));
            const size_t goffA = (size_t)(bm + row) * K + k0 + seg * 8;
            const size_t goffB = (size_t)(bn + row) * K + k0 + seg * 8;
            cp16(base + 0 * TEN_BYTES + dst, Ah + goffA);
            cp16(base + 1 * TEN_BYTES + dst, Bh + goffB);
            cp16(base + 2 * TEN_BYTES + dst, Bl + goffB);
        }
    };

    float acc[4][4][4];
#pragma unroll
    for (int i = 0; i < 4; ++i)
#pragma unroll
        for (int j = 0; j < 4; ++j)
#pragma unroll
            for (int q = 0; q < 4; ++q) acc[i][j][q] = 0.f;

    issue(0); cp_commit();
    issue(1); cp_commit();
    issue(2); cp_commit();

    for (int c = 0; c < chunks; ++c) {
        cp_wait2();           // <=2 groups pending -> stage c complete
        __syncthreads();      // data visible; prior-iteration readers done
        if (c + 3 < chunks) issue(c + 3);
        cp_commit();          // keep group count consistent (may be empty)

        const uint32_t base = sb + (uint32_t)(c & 3) * STAGE_BYTES;
        const uint32_t bAh = base;
        const uint32_t bBh = base + TEN_BYTES;
        const uint32_t bBl = base + 2 * TEN_BYTES;

#pragma unroll
        for (int ks = 0; ks < 2; ++ks) {
            const uint32_t cA = ((uint32_t)(ks * 32) + selA) ^ xorA;
            const uint32_t cB = ((uint32_t)(ks * 32) + selB) ^ xorB;
            uint32_t ah[4][4];
#pragma unroll
            for (int mf = 0; mf < 4; ++mf)
                ldm_x4(ah[mf], bAh + rowOffA[mf] + cA);
            uint32_t bh[4][2], bl[4][2];
#pragma unroll
            for (int nb = 0; nb < 2; ++nb) {
                uint32_t t[4];
                ldm_x4(t, bBh + rowOffB[nb] + cB);
                bh[nb * 2][0] = t[0]; bh[nb * 2][1] = t[1];
                bh[nb * 2 + 1][0] = t[2]; bh[nb * 2 + 1][1] = t[3];
                ldm_x4(t, bBl + rowOffB[nb] + cB);
                bl[nb * 2][0] = t[0]; bl[nb * 2][1] = t[1];
                bl[nb * 2 + 1][0] = t[2]; bl[nb * 2 + 1][1] = t[3];
            }
#pragma unroll
            for (int mf = 0; mf < 4; ++mf)
#pragma unroll
                for (int nf = 0; nf < 4; ++nf) {
                    mma16816h(acc[mf][nf], ah[mf], bh[nf]);
                    mma16816h(acc[mf][nf], ah[mf], bl[nf]);
                }
        }
    }

    const int g = lane >> 2;
    const int t2 = (lane & 3) * 2;
#pragma unroll
    for (int mf = 0; mf < 4; ++mf) {
#pragma unroll
        for (int nf = 0; nf < 4; ++nf) {
            const int col = bn + wn + nf * 8 + t2;
            const int row0 = bm + wm + mf * 16 + g;
            *(float2*)(C + (size_t)row0 * ldc + col) =
                make_float2(acc[mf][nf][0], acc[mf][nf][1]);
            *(float2*)(C + (size_t)(row0 + 8) * ldc + col) =
                make_float2(acc[mf][nf][2], acc[mf][nf][3]);
        }
    }
}

// ---------------- fp32 -> fp16 conversions ----------------------------------
__global__ __launch_bounds__(256)
void round_h_kernel(const float* __restrict__ src, __half* __restrict__ hi, int n4)
{
    const int i = blockIdx.x * 256 + threadIdx.x;
    if (i >= n4) return;
    const float4 v = ((const float4*)src)[i];
    hi[i * 4 + 0] = __float2half_rn(v.x);
    hi[i * 4 + 1] = __float2half_rn(v.y);
    hi[i * 4 + 2] = __float2half_rn(v.z);
    hi[i * 4 + 3] = __float2half_rn(v.w);
}

__global__ __launch_bounds__(256)
void split_h_kernel(const float* __restrict__ src, __half* __restrict__ hi,
                    __half* __restrict__ lo, int n4)
{
    const int i = blockIdx.x * 256 + threadIdx.x;
    if (i >= n4) return;
    const float4 v = ((const float4*)src)[i];
    __half h0 = __float2half_rn(v.x), h1 = __float2half_rn(v.y);
    __half h2 = __float2half_rn(v.z), h3 = __float2half_rn(v.w);
    hi[i * 4 + 0] = h0; hi[i * 4 + 1] = h1; hi[i * 4 + 2] = h2; hi[i * 4 + 3] = h3;
    lo[i * 4 + 0] = __float2half_rn(v.x - __half2float(h0));
    lo[i * 4 + 1] = __float2half_rn(v.y - __half2float(h1));
    lo[i * 4 + 2] = __float2half_rn(v.z - __half2float(h2));
    lo[i * 4 + 3] = __float2half_rn(v.w - __half2float(h3));
}

__global__ __launch_bounds__(256)
void split_pad_h_kernel(const float* __restrict__ src, __half* __restrict__ hi,
                        __half* __restrict__ lo)
{
    const int i = blockIdx.x * 256 + threadIdx.x;
    if (i >= PROJ_PAD * DM / 4) return;
    const int row = i / (DM / 4);
    float4 v = make_float4(0.f, 0.f, 0.f, 0.f);
    if (row < PROJ) v = ((const float4*)src)[i];
    __half h0 = __float2half_rn(v.x), h1 = __float2half_rn(v.y);
    __half h2 = __float2half_rn(v.z), h3 = __float2half_rn(v.w);
    hi[i * 4 + 0] = h0; hi[i * 4 + 1] = h1; hi[i * 4 + 2] = h2; hi[i * 4 + 3] = h3;
    lo[i * 4 + 0] = __float2half_rn(v.x - __half2float(h0));
    lo[i * 4 + 1] = __float2half_rn(v.y - __half2float(h1));
    lo[i * 4 + 2] = __float2half_rn(v.z - __half2float(h2));
    lo[i * 4 + 3] = __float2half_rn(v.w - __half2float(h3));
}

// ---------------- depthwise causal conv (K=4) + bias + SiLU + dt/dA ----------
// blockIdx.x < 9: conv channels; blockIdx.x == 9: dt/dA for this (b,l).
__global__ __launch_bounds__(256)
void conv_dt_kernel(const float* __restrict__ conv_w, const float* __restrict__ conv_b,
                    const float* __restrict__ dt_bias, const float* __restrict__ A_log)
{
    const int bl = blockIdx.y;
    if (blockIdx.x == 9) {
        const int hh = threadIdx.x;
        if (hh >= H_) return;
        const float x = g_proj[(size_t)bl * PROJ_PAD + INTER + CONV_DIM + hh] + dt_bias[hh];
        const float dt = softplusf(x);
        const float A = -expf(A_log[hh]);
        g_dt[bl * H_ + hh] = dt;
        g_dA[bl * H_ + hh] = expf(dt * A);
        return;
    }
    const int c = blockIdx.x * 256 + threadIdx.x;
    if (c >= CONV_DIM) return;
    const int l = bl & (L_ - 1);
    float acc = conv_b[c];
    const float* w = conv_w + c * 4;
#pragma unroll
    for (int j = 0; j < 4; ++j) {
        const int ll = l - 3 + j;
        if (ll >= 0)
            acc = fmaf(g_proj[(size_t)(bl + j - 3) * PROJ_PAD + INTER + c], w[j], acc);
    }
    g_conv[(size_t)bl * CONV_DIM + c] = siluf(acc);
}

// ---------------- SSD chunked scan ------------------------------------------
__global__ __launch_bounds__(256)
void adec_kernel()
{
    const int i = blockIdx.x * 256 + threadIdx.x;
    if (i >= B_ * NCHUNK * H_) return;
    const int h = i & (H_ - 1);
    const int c = (i >> 5) & (NCHUNK - 1);
    const int b = i >> 10;
    float p = 1.f;
    const float* base = g_dA + ((size_t)(b * L_ + c * TCH)) * H_ + h;
    for (int t = 0; t < TCH; ++t) p *= base[(size_t)t * H_];
    g_adec[i] = p;
}

#define G_SMEM (2 * 128 * 129 * 4)
__global__ __launch_bounds__(256, 1)
void chunk_G_kernel()
{
    const int c = blockIdx.x, b = blockIdx.y;
    extern __shared__ float sg[];
    float* sC = sg;
    float* sB = sg + 128 * 129;
    const int tid = threadIdx.x;
    const int bl0 = b * L_ + c * TCH;
    for (int idx = tid; idx < 128 * 128; idx += 256) {
        const int t = idx >> 7, n = idx & 127;
        const float* row = g_conv + (size_t)(bl0 + t) * CONV_DIM + INTER;
        sB[t * 129 + n] = row[n];
        sC[t * 129 + n] = row[N_ + n];
    }
    __syncthreads();
    const int tt = (tid >> 4) * 8, ss = (tid & 15) * 8;
    float acc[8][8];
#pragma unroll
    for (int i = 0; i < 8; ++i)
#pragma unroll
        for (int j = 0; j < 8; ++j) acc[i][j] = 0.f;
    for (int k = 0; k < 128; ++k) {
        float rc[8], rb[8];
#pragma unroll
        for (int i = 0; i < 8; ++i) rc[i] = sC[(tt + i) * 129 + k];
#pragma unroll
        for (int j = 0; j < 8; ++j) rb[j] = sB[(ss + j) * 129 + k];
#pragma unroll
        for (int i = 0; i < 8; ++i)
#pragma unroll
            for (int j = 0; j < 8; ++j) acc[i][j] = fmaf(rc[i], rb[j], acc[i][j]);
    }
    float* Gp = g_G + (size_t)(b * NCHUNK + c) * (TCH * TCH);
#pragma unroll
    for (int i = 0; i < 8; ++i)
#pragma unroll
        for (int j = 0; j < 8; ++j) Gp[(tt + i) * 128 + ss + j] = acc[i][j];
}

// smem offsets for chunk_state / chunk_y (272B pitch rows)
#define OFF_AH 0
#define OFF_AL 34816
#define OFF_BH 69632
#define OFF_BL 87040
#define OFF_LC 104448
#define OFF_DT 104960
#define OFF_CUM 105472
#define PH_SMEM 105984

__global__ __launch_bounds__(256, 2)
void chunk_state_kernel(const float* __restrict__ A_log)
{
    const int c = blockIdx.x, h = blockIdx.y, b = blockIdx.z;
    extern __shared__ __align__(1024) char sm[];
    const uint32_t sb = s2u(sm);
    float* slc = (float*)(sm + OFF_LC);
    float* sdt = (float*)(sm + OFF_DT);
    const int tid = threadIdx.x;
    const int bl0 = b * L_ + c * TCH;
    const float A = -expf(A_log[h]);

    if (tid < 128) {
        const float d = g_dt[(size_t)(bl0 + tid) * H_ + h];
        sdt[tid] = d;
        slc[tid] = d * A;
    }
    __syncthreads();
    for (int off = 1; off < 128; off <<= 1) {
        float v = 0.f;
        if (tid < 128 && tid >= off) v = slc[tid - off];
        __syncthreads();
        if (tid < 128 && tid >= off) slc[tid] += v;
        __syncthreads();
    }
    const float lcT = slc[127];

    for (int idx = tid; idx < 128 * 128; idx += 256) {
        const int s = idx >> 7, n = idx & 127;
        const float w = fast_exp(lcT - slc[s]) * sdt[s];
        const float v = g_conv[(size_t)(bl0 + s) * CONV_DIM + INTER + n] * w;
        split2(v, (__nv_bfloat16*)(sm + OFF_AH + n * 272 + s * 2),
                  (__nv_bfloat16*)(sm + OFF_AL + n * 272 + s * 2));
    }
    for (int idx = tid; idx < 128 * 64; idx += 256) {
        const int s = idx >> 6, p = idx & 63;
        const float v = g_conv[(size_t)(bl0 + s) * CONV_DIM + h * P_ + p];
        split2(v, (__nv_bfloat16*)(sm + OFF_BH + p * 272 + s * 2),
                  (__nv_bfloat16*)(sm + OFF_BL + p * 272 + s * 2));
    }
    __syncthreads();

    const int wid = tid >> 5, lane = tid & 31;
    const int wm = (wid & 3) * 32;
    const int wn = (wid >> 2) * 32;
    const uint32_t laneoff = (uint32_t)((lane >> 2) * 272 + (lane & 3) * 4);

    float acc[2][4][4];
#pragma unroll
    for (int i = 0; i < 2; ++i)
#pragma unroll
        for (int j = 0; j < 4; ++j)
#pragma unroll
            for (int q = 0; q < 4; ++q) acc[i][j][q] = 0.f;

#pragma unroll
    for (int k0 = 0; k0 < 128; k0 += 16) {
        const uint32_t ko = (uint32_t)(k0 * 2) + laneoff;
        uint32_t ah[2][4], al[2][4];
#pragma unroll
        for (int mf = 0; mf < 2; ++mf) {
            const uint32_t rb = (uint32_t)((wm + mf * 16) * 272) + ko;
            ldfragA(ah[mf], sb + OFF_AH + rb);
            ldfragA(al[mf], sb + OFF_AL + rb);
        }
        uint32_t bh[4][2], bl[4][2];
#pragma unroll
        for (int nf = 0; nf < 4; ++nf) {
            const uint32_t pb = (uint32_t)((wn + nf * 8) * 272) + ko;
            ldfragB(bh[nf], sb + OFF_BH + pb);
            ldfragB(bl[nf], sb + OFF_BL + pb);
        }
#pragma unroll
        for (int mf = 0; mf < 2; ++mf)
#pragma unroll
            for (int nf = 0; nf < 4; ++nf) {
                mma16816(acc[mf][nf], ah[mf], bh[nf]);
                mma16816(acc[mf][nf], ah[mf], bl[nf]);
                mma16816(acc[mf][nf], al[mf], bh[nf]);
            }
    }

    float* st = g_state + (size_t)((b * NCHUNK + c) * H_ + h) * (N_ * P_);
    const int g = lane >> 2;
    const int t2 = (lane & 3) * 2;
#pragma unroll
    for (int mf = 0; mf < 2; ++mf)
#pragma unroll
        for (int nf = 0; nf < 4; ++nf) {
            const int n0 = wm + mf * 16 + g;
            const int col = wn + nf * 8 + t2;
            *(float2*)(st + n0 * P_ + col) = make_float2(acc[mf][nf][0], acc[mf][nf][1]);
            *(float2*)(st + (n0 + 8) * P_ + col) = make_float2(acc[mf][nf][2], acc[mf][nf][3]);
        }
}

__global__ __launch_bounds__(256)
void scan_combine()
{
    const int idx = blockIdx.x * 256 + threadIdx.x;
    if (idx >= B_ * H_ * P_ * N_) return;
    const int h = (idx >> 13) & (H_ - 1);
    const int b = idx >> 18;
    const int pn = idx & (P_ * N_ - 1);
    float carry = 0.f;
#pragma unroll 4
    for (int c = 0; c < NCHUNK; ++c) {
        const size_t off = (size_t)((b * NCHUNK + c) * H_ + h) * (P_ * N_) + pn;
        g_init[off] = carry;
        carry = fmaf(g_adec[(b * NCHUNK + c) * H_ + h], carry, g_state[off]);
    }
}

__global__ __launch_bounds__(256, 2)
void chunk_y_kernel(const float* __restrict__ A_log)
{
    const int c = blockIdx.x, h = blockIdx.y, b = blockIdx.z;
    extern __shared__ __align__(1024) char sm[];
    const uint32_t sb = s2u(sm);
    float* slc = (float*)(sm + OFF_LC);
    float* sdt = (float*)(sm + OFF_DT);
    float* scum = (float*)(sm + OFF_CUM);
    const int tid = threadIdx.x;
    const int bl0 = b * L_ + c * TCH;
    const float A = -expf(A_log[h]);

    if (tid < 128) {
        const float d = g_dt[(size_t)(bl0 + tid) * H_ + h];
        sdt[tid] = d;
        slc[tid] = d * A;
    }
    __syncthreads();
    for (int off = 1; off < 128; off <<= 1) {
        float v = 0.f;
        if (tid < 128 && tid >= off) v = slc[tid - off];
        __syncthreads();
        if (tid < 128 && tid >= off) slc[tid] += v;
        __syncthreads();
    }
    if (tid < 128) scum[tid] = fast_exp(slc[tid]);

    for (int idx = tid; idx < 128 * 128; idx += 256) {
        const int t = idx >> 7, n = idx & 127;
        const float v = g_conv[(size_t)(bl0 + t) * CONV_DIM + INTER + N_ + n];
        split2(v, (__nv_bfloat16*)(sm + OFF_AH + t * 272 + n * 2),
                  (__nv_bfloat16*)(sm + OFF_AL + t * 272 + n * 2));
    }
    const float* Sini = g_init + (size_t)((b * NCHUNK + c) * H_ + h) * (N_ * P_);
    for (int idx = tid; idx < 128 * 64; idx += 256) {
        const int n = idx >> 6, p = idx & 63;
        const float v = Sini[n * P_ + p];
        split2(v, (__nv_bfloat16*)(sm + OFF_BH + p * 272 + n * 2),
                  (__nv_bfloat16*)(sm + OFF_BL + p * 272 + n * 2));
    }
    __syncthreads();

    const int wid = tid >> 5, lane = tid & 31;
    const int wm = (wid & 3) * 32;
    const int wn = (wid >> 2) * 32;
    const uint32_t laneoff = (uint32_t)((lane >> 2) * 272 + (lane & 3) * 4);

    float acc[2][4][4];
#pragma unroll
    for (int i = 0; i < 2; ++i)
#pragma unroll
        for (int j = 0; j < 4; ++j)
#pragma unroll
            for (int q = 0; q < 4; ++q) acc[i][j][q] = 0.f;

#pragma unroll
    for (int k0 = 0; k0 < 128; k0 += 16) {
        const uint32_t ko = (uint32_t)(k0 * 2) + laneoff;
        uint32_t ah[2][4], al[2][4];
#pragma unroll
        for (int mf = 0; mf < 2; ++mf) {
            const uint32_t rb = (uint32_t)((wm + mf * 16) * 272) + ko;
            ldfragA(ah[mf], sb + OFF_AH + rb);
            ldfragA(al[mf], sb + OFF_AL + rb);
        }
        uint32_t bh[4][2], bl[4][2];
#pragma unroll
        for (int nf = 0; nf < 4; ++nf) {
            const uint32_t pb = (uint32_t)((wn + nf * 8) * 272) + ko;
            ldfragB(bh[nf], sb + OFF_BH + pb);
            ldfragB(bl[nf], sb + OFF_BL + pb);
        }
#pragma unroll
        for (int mf = 0; mf < 2; ++mf)
#pragma unroll
            for (int nf = 0; nf < 4; ++nf) {
                mma16816(acc[mf][nf], ah[mf], bh[nf]);
                mma16816(acc[mf][nf], ah[mf], bl[nf]);
                mma16816(acc[mf][nf], al[mf], bh[nf]);
            }
    }
    __syncthreads();

    const int g = lane >> 2;
#pragma unroll
    for (int mf = 0; mf < 2; ++mf) {
        const float s0 = scum[wm + mf * 16 + g];
        const float s1 = scum[wm + mf * 16 + g + 8];
#pragma unroll
        for (int nf = 0; nf < 4; ++nf) {
            acc[mf][nf][0] *= s0; acc[mf][nf][1] *= s0;
            acc[mf][nf][2] *= s1; acc[mf][nf][3] *= s1;
        }
    }

    const float* Gp = g_G + (size_t)(b * NCHUNK + c) * (TCH * TCH);
    for (int idx = tid; idx < 128 * 128; idx += 256) {
        const int t = idx >> 7, s = idx & 127;
        float val = 0.f;
        if (s <= t) val = fast_exp(slc[t] - slc[s]) * sdt[s] * Gp[idx];
        split2(val, (__nv_bfloat16*)(sm + OFF_AH + t * 272 + s * 2),
                    (__nv_bfloat16*)(sm + OFF_AL + t * 272 + s * 2));
    }
    for (int idx = tid; idx < 128 * 64; idx += 256) {
        const int s = idx >> 6, p = idx & 63;
        const float v = g_conv[(size_t)(bl0 + s) * CONV_DIM + h * P_ + p];
        split2(v, (__nv_bfloat16*)(sm + OFF_BH + p * 272 + s * 2),
                  (__nv_bfloat16*)(sm + OFF_BL + p * 272 + s * 2));
    }
    __syncthreads();

#pragma unroll
    for (int k0 = 0; k0 < 128; k0 += 16) {
        const uint32_t ko = (uint32_t)(k0 * 2) + laneoff;
        uint32_t ah[2][4], al[2][4];
#pragma unroll
        for (int mf = 0; mf < 2; ++mf) {
            const uint32_t rb = (uint32_t)((wm + mf * 16) * 272) + ko;
            ldfragA(ah[mf], sb + OFF_AH + rb);
            ldfragA(al[mf], sb + OFF_AL + rb);
        }
        uint32_t bh[4][2], bl[4][2];
#pragma unroll
        for (int nf = 0; nf < 4; ++nf) {
            const uint32_t pb = (uint32_t)((wn + nf * 8) * 272) + ko;
            ldfragB(bh[nf], sb + OFF_BH + pb);
            ldfragB(bl[nf], sb + OFF_BL + pb);
        }
#pragma unroll
        for (int mf = 0; mf < 2; ++mf)
#pragma unroll
            for (int nf = 0; nf < 4; ++nf) {
                mma16816(acc[mf][nf], ah[mf], bh[nf]);
                mma16816(acc[mf][nf], ah[mf], bl[nf]);
                mma16816(acc[mf][nf], al[mf], bh[nf]);
            }
    }

    const int t2 = (lane & 3) * 2;
#pragma unroll
    for (int mf = 0; mf < 2; ++mf)
#pragma unroll
        for (int nf = 0; nf < 4; ++nf) {
            const int row0 = wm + mf * 16 + g;
            const int col = h * P_ + wn + nf * 8 + t2;
            *(float2*)(g_y + (size_t)(bl0 + row0) * INTER + col) =
                make_float2(acc[mf][nf][0], acc[mf][nf][1]);
            *(float2*)(g_y + (size_t)(bl0 + row0 + 8) * INTER + col) =
                make_float2(acc[mf][nf][2], acc[mf][nf][3]);
        }
}

// ---------------- y + D*xs, gate*silu, RMSNorm, fp16 round ------------------
__global__ __launch_bounds__(256)
void gate_rms_kernel(const float* __restrict__ D_param, const float* __restrict__ norm_w)
{
    const int bl = blockIdx.x;
    const int tid = threadIdx.x;
    const float* yrow = g_y + (size_t)bl * INTER;
    const float* grow = g_proj + (size_t)bl * PROJ_PAD;
    const float* xrow = g_conv + (size_t)bl * CONV_DIM;

    float vals[8];
    float ss = 0.f;
#pragma unroll
    for (int r = 0; r < 2; ++r) {
        const int i = tid * 4 + r * 1024;
        const float4 yv = *(const float4*)(yrow + i);
        const float4 gv = *(const float4*)(grow + i);
        const float4 xv = *(const float4*)(xrow + i);
        const float d = D_param[i >> 6];
        float g0 = (yv.x + d * xv.x) * siluf(gv.x);
        float g1 = (yv.y + d * xv.y) * siluf(gv.y);
        float g2 = (yv.z + d * xv.z) * siluf(gv.z);
        float g3 = (yv.w + d * xv.w) * siluf(gv.w);
        vals[r * 4 + 0] = g0; vals[r * 4 + 1] = g1;
        vals[r * 4 + 2] = g2; vals[r * 4 + 3] = g3;
        ss += g0 * g0 + g1 * g1 + g2 * g2 + g3 * g3;
    }

    __shared__ float red[8];
    __shared__ float stot;
#pragma unroll
    for (int o = 16; o; o >>= 1) ss += __shfl_xor_sync(0xffffffffu, ss, o);
    if ((tid & 31) == 0) red[tid >> 5] = ss;
    __syncthreads();
    if (tid == 0) {
        float v = 0.f;
#pragma unroll
        for (int i = 0; i < 8; ++i) v += red[i];
        stot = rsqrtf(v * (1.f / (float)INTER) + EPSV);
    }
    __syncthreads();
    const float rs = stot;

    __half* gh = g_gate_h + (size_t)bl * INTER;
#pragma unroll
    for (int r = 0; r < 2; ++r) {
        const int i = tid * 4 + r * 1024;
        const float4 nw = *(const float4*)(norm_w + i);
        gh[i + 0] = __float2half_rn(vals[r * 4 + 0] * rs * nw.x);
        gh[i + 1] = __float2half_rn(vals[r * 4 + 1] * rs * nw.y);
        gh[i + 2] = __float2half_rn(vals[r * 4 + 2] * rs * nw.z);
        gh[i + 3] = __float2half_rn(vals[r * 4 + 3] * rs * nw.w);
    }
}

// ---------------- launch -----------------------------------------------------
extern "C" void kernel_launch(void* const* d_in, const int* in_sizes, int n_in,
                              void* d_out, int out_size)
{
    const float* hs      = (const float*)d_in[0];
    const float* W_in    = (const float*)d_in[1];
    const float* conv_w  = (const float*)d_in[2];
    const float* conv_b  = (const float*)d_in[3];
    const float* dt_bias = (const float*)d_in[4];
    const float* A_log   = (const float*)d_in[5];
    const float* D_param = (const float*)d_in[6];
    const float* norm_w  = (const float*)d_in[7];
    const float* W_out   = (const float*)d_in[8];
    float* out = (float*)d_out;

    cudaFuncSetAttribute(gemm_mma2, cudaFuncAttributeMaxDynamicSharedMemorySize,
                         GEMM_SMEM_BYTES);
    cudaFuncSetAttribute(chunk_G_kernel, cudaFuncAttributeMaxDynamicSharedMemorySize,
                         G_SMEM);
    cudaFuncSetAttribute(chunk_state_kernel, cudaFuncAttributeMaxDynamicSharedMemorySize,
                         PH_SMEM);
    cudaFuncSetAttribute(chunk_y_kernel, cudaFuncAttributeMaxDynamicSharedMemorySize,
                         PH_SMEM);

    void *pproj = nullptr;
    void *phh = nullptr, *pwh = nullptr, *pwl = nullptr;
    void *pgh = nullptr, *poh = nullptr, *pol = nullptr;
    cudaGetSymbolAddress(&pproj, g_proj);
    cudaGetSymbolAddress(&phh, g_hs_h);
    cudaGetSymbolAddress(&pwh, g_win_h);
    cudaGetSymbolAddress(&pwl, g_win_l);
    cudaGetSymbolAddress(&pgh, g_gate_h);
    cudaGetSymbolAddress(&poh, g_wo_h);
    cudaGetSymbolAddress(&pol, g_wo_l);

    // 0) conversions
    {
        const int n4 = B_ * L_ * DM / 4;
        round_h_kernel<<<(n4 + 255) / 256, 256>>>(hs, (__half*)phh, n4);
    }
    split_pad_h_kernel<<<(PROJ_PAD * DM / 4 + 255) / 256, 256>>>(
        W_in, (__half*)pwh, (__half*)pwl);
    {
        const int n4 = DM * INTER / 4;
        split_h_kernel<<<(n4 + 255) / 256, 256>>>(W_out, (__half*)poh, (__half*)pol, n4);
    }

    // 1) proj = hs @ W_in^T
    {
        dim3 grid(PROJ_PAD / 128, (B_ * L_) / 128);
        gemm_mma2<<<grid, 256, GEMM_SMEM_BYTES>>>(
            (const __half*)phh, (const __half*)pwh, (const __half*)pwl,
            (float*)pproj, DM, PROJ_PAD);
    }
    // 2) conv + silu + dt/dA (fused)
    {
        dim3 grid(10, B_ * L_);
        conv_dt_kernel<<<grid, 256>>>(conv_w, conv_b, dt_bias, A_log);
    }
    // 3) SSD chunked scan
    adec_kernel<<<(B_ * NCHUNK * H_ + 255) / 256, 256>>>();
    chunk_G_kernel<<<dim3(NCHUNK, B_), 256, G_SMEM>>>();
    chunk_state_kernel<<<dim3(NCHUNK, H_, B_), 256, PH_SMEM>>>(A_log);
    scan_combine<<<(B_ * H_ * P_ * N_) / 256, 256>>>();
    chunk_y_kernel<<<dim3(NCHUNK, H_, B_), 256, PH_SMEM>>>(A_log);
    // 4) gate + rmsnorm + fp16 round
    gate_rms_kernel<<<B_ * L_, 256>>>(D_param, norm_w);
    // 5) out = g @ W_out^T
    {
        dim3 grid(DM / 128, (B_ * L_) / 128);
        gemm_mma2<<<grid, 256, GEMM_SMEM_BYTES>>>(
            (const __half*)pgh, (const __half*)poh, (const __half*)pol,
            out, INTER, DM);
    }
}

// round 12
// speedup vs baseline: 1.6702x; 1.0163x over previous
#include <cuda_runtime.h>
#include <cuda_bf16.h>
#include <cuda_fp16.h>
#include <cstdint>
#include <cstddef>

#define B_ 2
#define L_ 4096
#define DM 2048
#define H_ 32
#define P_ 64
#define N_ 128
#define INTER 2048
#define CONV_DIM 2304
#define PROJ 4384
#define PROJ_PAD 4480
#define EPSV 1e-5f
#define NCHUNK 32
#define TCH 128

// ---------------- scratch (__device__ globals; no allocations allowed) ------
__device__ float g_proj[(size_t)B_ * L_ * PROJ_PAD];
__device__ float g_conv[(size_t)B_ * L_ * CONV_DIM];
__device__ float g_y[(size_t)B_ * L_ * INTER];
__device__ float g_dt[B_ * L_ * H_];
__device__ float g_G[(size_t)B_ * NCHUNK * TCH * TCH];
__device__ float g_state[(size_t)B_ * NCHUNK * H_ * N_ * P_];
__device__ float g_init[(size_t)B_ * NCHUNK * H_ * N_ * P_];
__device__ float g_adec[B_ * NCHUNK * H_];
// fp16 GEMM operands (A rounded; B split hi/lo)
__device__ __half g_hs_h[(size_t)B_ * L_ * DM];
__device__ __half g_win_h[(size_t)PROJ_PAD * DM];
__device__ __half g_win_l[(size_t)PROJ_PAD * DM];
__device__ __half g_gate_h[(size_t)B_ * L_ * INTER];
__device__ __half g_wo_h[(size_t)DM * INTER];
__device__ __half g_wo_l[(size_t)DM * INTER];

// ---------------- helpers ----------------------------------------------------
__device__ __forceinline__ float siluf(float x) {
    return x * (1.f / (1.f + expf(-x)));
}
__device__ __forceinline__ float softplusf(float x) {
    return (x > 20.f) ? x : log1pf(expf(x));
}
__device__ __forceinline__ uint32_t s2u(const void* p) {
    return (uint32_t)__cvta_generic_to_shared(p);
}
__device__ __forceinline__ void cp16(uint32_t saddr, const void* g) {
    asm volatile("cp.async.cg.shared.global [%0], [%1], 16;\n" :: "r"(saddr), "l"(g));
}
__device__ __forceinline__ void cp_commit() {
    asm volatile("cp.async.commit_group;\n" ::: "memory");
}
__device__ __forceinline__ void cp_wait2() {
    asm volatile("cp.async.wait_group 2;\n" ::: "memory");
}
__device__ __forceinline__ uint32_t lds32(uint32_t a) {
    uint32_t v;
    asm volatile("ld.shared.b32 %0, [%1];" : "=r"(v) : "r"(a));
    return v;
}
// e^d for d <= 0, rel err ~3e-7, no MUFU
__device__ __forceinline__ float fast_exp(float d) {
    float y = d * 1.44269504f;
    if (y < -126.f) return 0.f;
    float n = floorf(y);
    float f = y - n;
    float p = 1.33336498e-3f;
    p = fmaf(p, f, 9.61011667e-3f);
    p = fmaf(p, f, 5.55036329e-2f);
    p = fmaf(p, f, 2.40226507e-1f);
    p = fmaf(p, f, 6.93147182e-1f);
    p = fmaf(p, f, 1.0f);
    return p * __int_as_float(((int)n + 127) << 23);
}

// ---------------- warp-level HMMA plumbing ----------------------------------
__device__ __forceinline__ void ldm_x4(uint32_t* r, uint32_t addr) {
    asm volatile("ldmatrix.sync.aligned.m8n8.x4.shared.b16 {%0,%1,%2,%3}, [%4];"
                 : "=r"(r[0]), "=r"(r[1]), "=r"(r[2]), "=r"(r[3]) : "r"(addr));
}
__device__ __forceinline__ void mma16816h(float* d, const uint32_t* a, const uint32_t* b) {
    asm volatile(
        "mma.sync.aligned.m16n8k16.row.col.f32.f16.f16.f32 "
        "{%0,%1,%2,%3}, {%4,%5,%6,%7}, {%8,%9}, {%0,%1,%2,%3};"
        : "+f"(d[0]), "+f"(d[1]), "+f"(d[2]), "+f"(d[3])
        : "r"(a[0]), "r"(a[1]), "r"(a[2]), "r"(a[3]), "r"(b[0]), "r"(b[1]));
}
// LDS-based fragment loads from 272B-pitch row-major fp16 tiles
__device__ __forceinline__ void ldfragA(uint32_t r[4], uint32_t base) {
    r[0] = lds32(base);        r[1] = lds32(base + 2176);
    r[2] = lds32(base + 16);   r[3] = lds32(base + 2192);
}
__device__ __forceinline__ void ldfragB(uint32_t r[2], uint32_t base) {
    r[0] = lds32(base);        r[1] = lds32(base + 16);
}
__device__ __forceinline__ void split2h(float v, __half* hp, __half* lp) {
    __half h = __float2half_rn(v);
    *hp = h;
    *lp = __float2half_rn(v - __half2float(h));
}

// ---------------- 2-product fp16 GEMM, 4-stage, 2 CTAs/SM, 1 barrier/chunk --
#define STAGE_BYTES 24576
#define TEN_BYTES 8192
#define GEMM_SMEM_BYTES (4 * STAGE_BYTES)

__global__ __launch_bounds__(256, 2)
void gemm_mma2(const __half* __restrict__ Ah,
               const __half* __restrict__ Bh, const __half* __restrict__ Bl,
               float* __restrict__ C, int K, int ldc)
{
    extern __shared__ __align__(1024) char smem[];
    const uint32_t sb = s2u(smem);
    const int tid = threadIdx.x;
    const int wid = tid >> 5;
    const int lane = tid & 31;
    const int bn = blockIdx.x * 128;
    const int bm = blockIdx.y * 128;
    const int chunks = K >> 5;

    const int wm = (wid & 1) * 64;
    const int wn = (wid >> 1) * 32;

    const int rA = wm + (lane & 15);
    const uint32_t selA = (lane & 16) ? 16u : 0u;
    const uint32_t xorA = (uint32_t)(((rA >> 1) & 3) * 16);
    uint32_t rowOffA[4];
#pragma unroll
    for (int mf = 0; mf < 4; ++mf) rowOffA[mf] = (uint32_t)((rA + mf * 16) * 64);

    const int rB = wn + (lane & 7) + ((lane & 16) ? 8 : 0);
    const uint32_t selB = (lane & 8) ? 16u : 0u;
    const uint32_t xorB = (uint32_t)(((rB >> 1) & 3) * 16);
    uint32_t rowOffB[2];
#pragma unroll
    for (int nb = 0; nb < 2; ++nb) rowOffB[nb] = (uint32_t)((rB + nb * 16) * 64);

    auto issue = [&](int c) {
        const int s = c & 3;
        const uint32_t base = sb + (uint32_t)s * STAGE_BYTES;
        const int k0 = c << 5;
#pragma unroll
        for (int q = 0; q < 2; ++q) {
            const int cc = q * 256 + tid;
            const int row = cc >> 2;
            const int seg = cc & 3;
            const uint32_t dst =
                (uint32_t)(row * 64 + ((seg * 16) ^ (((row >> 1) & 3) * 16)));
            const size_t goffA = (size_t)(bm + row) * K + k0 + seg * 8;
            const size_t goffB = (size_t)(bn + row) * K + k0 + seg * 8;
            cp16(base + 0 * TEN_BYTES + dst, Ah + goffA);
            cp16(base + 1 * TEN_BYTES + dst, Bh + goffB);
            cp16(base + 2 * TEN_BYTES + dst, Bl + goffB);
        }
    };

    float acc[4][4][4];
#pragma unroll
    for (int i = 0; i < 4; ++i)
#pragma unroll
        for (int j = 0; j < 4; ++j)
#pragma unroll
            for (int q = 0; q < 4; ++q) acc[i][j][q] = 0.f;

    issue(0); cp_commit();
    issue(1); cp_commit();
    issue(2); cp_commit();

    for (int c = 0; c < chunks; ++c) {
        cp_wait2();
        __syncthreads();
        if (c + 3 < chunks) issue(c + 3);
        cp_commit();

        const uint32_t base = sb + (uint32_t)(c & 3) * STAGE_BYTES;
        const uint32_t bAh = base;
        const uint32_t bBh = base + TEN_BYTES;
        const uint32_t bBl = base + 2 * TEN_BYTES;

#pragma unroll
        for (int ks = 0; ks < 2; ++ks) {
            const uint32_t cA = ((uint32_t)(ks * 32) + selA) ^ xorA;
            const uint32_t cB = ((uint32_t)(ks * 32) + selB) ^ xorB;
            uint32_t ah[4][4];
#pragma unroll
            for (int mf = 0; mf < 4; ++mf)
                ldm_x4(ah[mf], bAh + rowOffA[mf] + cA);
            uint32_t bh[4][2], bl[4][2];
#pragma unroll
            for (int nb = 0; nb < 2; ++nb) {
                uint32_t t[4];
                ldm_x4(t, bBh + rowOffB[nb] + cB);
                bh[nb * 2][0] = t[0]; bh[nb * 2][1] = t[1];
                bh[nb * 2 + 1][0] = t[2]; bh[nb * 2 + 1][1] = t[3];
                ldm_x4(t, bBl + rowOffB[nb] + cB);
                bl[nb * 2][0] = t[0]; bl[nb * 2][1] = t[1];
                bl[nb * 2 + 1][0] = t[2]; bl[nb * 2 + 1][1] = t[3];
            }
#pragma unroll
            for (int mf = 0; mf < 4; ++mf)
#pragma unroll
                for (int nf = 0; nf < 4; ++nf) {
                    mma16816h(acc[mf][nf], ah[mf], bh[nf]);
                    mma16816h(acc[mf][nf], ah[mf], bl[nf]);
                }
        }
    }

    const int g = lane >> 2;
    const int t2 = (lane & 3) * 2;
#pragma unroll
    for (int mf = 0; mf < 4; ++mf) {
#pragma unroll
        for (int nf = 0; nf < 4; ++nf) {
            const int col = bn + wn + nf * 8 + t2;
            const int row0 = bm + wm + mf * 16 + g;
            *(float2*)(C + (size_t)row0 * ldc + col) =
                make_float2(acc[mf][nf][0], acc[mf][nf][1]);
            *(float2*)(C + (size_t)(row0 + 8) * ldc + col) =
                make_float2(acc[mf][nf][2], acc[mf][nf][3]);
        }
    }
}

// ---------------- fp32 -> fp16 conversions ----------------------------------
__global__ __launch_bounds__(256)
void round_h_kernel(const float* __restrict__ src, __half* __restrict__ hi, int n4)
{
    const int i = blockIdx.x * 256 + threadIdx.x;
    if (i >= n4) return;
    const float4 v = ((const float4*)src)[i];
    hi[i * 4 + 0] = __float2half_rn(v.x);
    hi[i * 4 + 1] = __float2half_rn(v.y);
    hi[i * 4 + 2] = __float2half_rn(v.z);
    hi[i * 4 + 3] = __float2half_rn(v.w);
}

__global__ __launch_bounds__(256)
void split_h_kernel(const float* __restrict__ src, __half* __restrict__ hi,
                    __half* __restrict__ lo, int n4)
{
    const int i = blockIdx.x * 256 + threadIdx.x;
    if (i >= n4) return;
    const float4 v = ((const float4*)src)[i];
    split2h(v.x, &hi[i * 4 + 0], &lo[i * 4 + 0]);
    split2h(v.y, &hi[i * 4 + 1], &lo[i * 4 + 1]);
    split2h(v.z, &hi[i * 4 + 2], &lo[i * 4 + 2]);
    split2h(v.w, &hi[i * 4 + 3], &lo[i * 4 + 3]);
}

__global__ __launch_bounds__(256)
void split_pad_h_kernel(const float* __restrict__ src, __half* __restrict__ hi,
                        __half* __restrict__ lo)
{
    const int i = blockIdx.x * 256 + threadIdx.x;
    if (i >= PROJ_PAD * DM / 4) return;
    const int row = i / (DM / 4);
    float4 v = make_float4(0.f, 0.f, 0.f, 0.f);
    if (row < PROJ) v = ((const float4*)src)[i];
    split2h(v.x, &hi[i * 4 + 0], &lo[i * 4 + 0]);
    split2h(v.y, &hi[i * 4 + 1], &lo[i * 4 + 1]);
    split2h(v.z, &hi[i * 4 + 2], &lo[i * 4 + 2]);
    split2h(v.w, &hi[i * 4 + 3], &lo[i * 4 + 3]);
}

// ---------------- depthwise causal conv (K=4) + bias + SiLU + dt -------------
__global__ __launch_bounds__(256)
void conv_dt_kernel(const float* __restrict__ conv_w, const float* __restrict__ conv_b,
                    const float* __restrict__ dt_bias)
{
    const int bl = blockIdx.y;
    if (blockIdx.x == 9) {
        const int hh = threadIdx.x;
        if (hh >= H_) return;
        const float x = g_proj[(size_t)bl * PROJ_PAD + INTER + CONV_DIM + hh] + dt_bias[hh];
        g_dt[bl * H_ + hh] = softplusf(x);
        return;
    }
    const int c = blockIdx.x * 256 + threadIdx.x;
    if (c >= CONV_DIM) return;
    const int l = bl & (L_ - 1);
    float acc = conv_b[c];
    const float* w = conv_w + c * 4;
#pragma unroll
    for (int j = 0; j < 4; ++j) {
        const int ll = l - 3 + j;
        if (ll >= 0)
            acc = fmaf(g_proj[(size_t)(bl + j - 3) * PROJ_PAD + INTER + c], w[j], acc);
    }
    g_conv[(size_t)bl * CONV_DIM + c] = siluf(acc);
}

// ---------------- SSD chunked scan ------------------------------------------
#define G_SMEM (2 * 128 * 129 * 4)
__global__ __launch_bounds__(256, 1)
void chunk_G_kernel()
{
    const int c = blockIdx.x, b = blockIdx.y;
    extern __shared__ float sg[];
    float* sC = sg;
    float* sB = sg + 128 * 129;
    const int tid = threadIdx.x;
    const int bl0 = b * L_ + c * TCH;
    for (int idx = tid; idx < 128 * 128; idx += 256) {
        const int t = idx >> 7, n = idx & 127;
        const float* row = g_conv + (size_t)(bl0 + t) * CONV_DIM + INTER;
        sB[t * 129 + n] = row[n];
        sC[t * 129 + n] = row[N_ + n];
    }
    __syncthreads();
    const int tt = (tid >> 4) * 8, ss = (tid & 15) * 8;
    float acc[8][8];
#pragma unroll
    for (int i = 0; i < 8; ++i)
#pragma unroll
        for (int j = 0; j < 8; ++j) acc[i][j] = 0.f;
    for (int k = 0; k < 128; ++k) {
        float rc[8], rb[8];
#pragma unroll
        for (int i = 0; i < 8; ++i) rc[i] = sC[(tt + i) * 129 + k];
#pragma unroll
        for (int j = 0; j < 8; ++j) rb[j] = sB[(ss + j) * 129 + k];
#pragma unroll
        for (int i = 0; i < 8; ++i)
#pragma unroll
            for (int j = 0; j < 8; ++j) acc[i][j] = fmaf(rc[i], rb[j], acc[i][j]);
    }
    float* Gp = g_G + (size_t)(b * NCHUNK + c) * (TCH * TCH);
#pragma unroll
    for (int i = 0; i < 8; ++i)
#pragma unroll
        for (int j = 0; j < 8; ++j) Gp[(tt + i) * 128 + ss + j] = acc[i][j];
}

// smem offsets for chunk_state / chunk_y (272B pitch rows; fp16 A single buf)
#define OFF_AH 0
#define OFF_BH 34816
#define OFF_BL 52224
#define OFF_LC 69632
#define OFF_DT 70144
#define OFF_CUM 70656
#define PH_SMEM 71168

// S_partial[n][p] = sum_s exp(lc[127]-lc[s]) dt[s] B[s][n] x[s][p]
// A = wB^T rounded fp16; B operand = X^T split hi/lo fp16 (2-product).
__global__ __launch_bounds__(256, 2)
void chunk_state_kernel(const float* __restrict__ A_log)
{
    const int c = blockIdx.x, h = blockIdx.y, b = blockIdx.z;
    extern __shared__ __align__(1024) char sm[];
    const uint32_t sb = s2u(sm);
    float* slc = (float*)(sm + OFF_LC);
    float* sdt = (float*)(sm + OFF_DT);
    const int tid = threadIdx.x;
    const int bl0 = b * L_ + c * TCH;
    const float A = -expf(A_log[h]);

    if (tid < 128) {
        const float d = g_dt[(size_t)(bl0 + tid) * H_ + h];
        sdt[tid] = d;
        slc[tid] = d * A;
    }
    __syncthreads();
    for (int off = 1; off < 128; off <<= 1) {
        float v = 0.f;
        if (tid < 128 && tid >= off) v = slc[tid - off];
        __syncthreads();
        if (tid < 128 && tid >= off) slc[tid] += v;
        __syncthreads();
    }
    const float lcT = slc[127];
    if (tid == 0) g_adec[(b * NCHUNK + c) * H_ + h] = fast_exp(lcT);

    for (int idx = tid; idx < 128 * 128; idx += 256) {
        const int s = idx >> 7, n = idx & 127;
        const float w = fast_exp(lcT - slc[s]) * sdt[s];
        const float v = g_conv[(size_t)(bl0 + s) * CONV_DIM + INTER + n] * w;
        *(__half*)(sm + OFF_AH + n * 272 + s * 2) = __float2half_rn(v);
    }
    for (int idx = tid; idx < 128 * 64; idx += 256) {
        const int s = idx >> 6, p = idx & 63;
        const float v = g_conv[(size_t)(bl0 + s) * CONV_DIM + h * P_ + p];
        split2h(v, (__half*)(sm + OFF_BH + p * 272 + s * 2),
                   (__half*)(sm + OFF_BL + p * 272 + s * 2));
    }
    __syncthreads();

    const int wid = tid >> 5, lane = tid & 31;
    const int wm = (wid & 3) * 32;
    const int wn = (wid >> 2) * 32;
    const uint32_t laneoff = (uint32_t)((lane >> 2) * 272 + (lane & 3) * 4);

    float acc[2][4][4];
#pragma unroll
    for (int i = 0; i < 2; ++i)
#pragma unroll
        for (int j = 0; j < 4; ++j)
#pragma unroll
            for (int q = 0; q < 4; ++q) acc[i][j][q] = 0.f;

#pragma unroll
    for (int k0 = 0; k0 < 128; k0 += 16) {
        const uint32_t ko = (uint32_t)(k0 * 2) + laneoff;
        uint32_t ah[2][4];
#pragma unroll
        for (int mf = 0; mf < 2; ++mf)
            ldfragA(ah[mf], sb + OFF_AH + (uint32_t)((wm + mf * 16) * 272) + ko);
        uint32_t bh[4][2], bl[4][2];
#pragma unroll
        for (int nf = 0; nf < 4; ++nf) {
            const uint32_t pb = (uint32_t)((wn + nf * 8) * 272) + ko;
            ldfragB(bh[nf], sb + OFF_BH + pb);
            ldfragB(bl[nf], sb + OFF_BL + pb);
        }
#pragma unroll
        for (int mf = 0; mf < 2; ++mf)
#pragma unroll
            for (int nf = 0; nf < 4; ++nf) {
                mma16816h(acc[mf][nf], ah[mf], bh[nf]);
                mma16816h(acc[mf][nf], ah[mf], bl[nf]);
            }
    }

    float* st = g_state + (size_t)((b * NCHUNK + c) * H_ + h) * (N_ * P_);
    const int g = lane >> 2;
    const int t2 = (lane & 3) * 2;
#pragma unroll
    for (int mf = 0; mf < 2; ++mf)
#pragma unroll
        for (int nf = 0; nf < 4; ++nf) {
            const int n0 = wm + mf * 16 + g;
            const int col = wn + nf * 8 + t2;
            *(float2*)(st + n0 * P_ + col) = make_float2(acc[mf][nf][0], acc[mf][nf][1]);
            *(float2*)(st + (n0 + 8) * P_ + col) = make_float2(acc[mf][nf][2], acc[mf][nf][3]);
        }
}

__global__ __launch_bounds__(256)
void scan_combine()
{
    const int idx = blockIdx.x * 256 + threadIdx.x;
    if (idx >= B_ * H_ * P_ * N_) return;
    const int h = (idx >> 13) & (H_ - 1);
    const int b = idx >> 18;
    const int pn = idx & (P_ * N_ - 1);
    float carry = 0.f;
#pragma unroll 4
    for (int c = 0; c < NCHUNK; ++c) {
        const size_t off = (size_t)((b * NCHUNK + c) * H_ + h) * (P_ * N_) + pn;
        g_init[off] = carry;
        carry = fmaf(g_adec[(b * NCHUNK + c) * H_ + h], carry, g_state[off]);
    }
}

// Y[t][p] = cum[t]*(C @ S_init)[t][p] + ((Gamma.*G) @ X)[t][p], fp16 2-product
__global__ __launch_bounds__(256, 2)
void chunk_y_kernel(const float* __restrict__ A_log)
{
    const int c = blockIdx.x, h = blockIdx.y, b = blockIdx.z;
    extern __shared__ __align__(1024) char sm[];
    const uint32_t sb = s2u(sm);
    float* slc = (float*)(sm + OFF_LC);
    float* sdt = (float*)(sm + OFF_DT);
    float* scum = (float*)(sm + OFF_CUM);
    const int tid = threadIdx.x;
    const int bl0 = b * L_ + c * TCH;
    const float A = -expf(A_log[h]);

    if (tid < 128) {
        const float d = g_dt[(size_t)(bl0 + tid) * H_ + h];
        sdt[tid] = d;
        slc[tid] = d * A;
    }
    __syncthreads();
    for (int off = 1; off < 128; off <<= 1) {
        float v = 0.f;
        if (tid < 128 && tid >= off) v = slc[tid - off];
        __syncthreads();
        if (tid < 128 && tid >= off) slc[tid] += v;
        __syncthreads();
    }
    if (tid < 128) scum[tid] = fast_exp(slc[tid]);

    // stage 1: A = C [t][n] fp16; B = S_init^T [p][n] split
    for (int idx = tid; idx < 128 * 128; idx += 256) {
        const int t = idx >> 7, n = idx & 127;
        const float v = g_conv[(size_t)(bl0 + t) * CONV_DIM + INTER + N_ + n];
        *(__half*)(sm + OFF_AH + t * 272 + n * 2) = __float2half_rn(v);
    }
    const float* Sini = g_init + (size_t)((b * NCHUNK + c) * H_ + h) * (N_ * P_);
    for (int idx = tid; idx < 128 * 64; idx += 256) {
        const int n = idx >> 6, p = idx & 63;
        split2h(Sini[n * P_ + p], (__half*)(sm + OFF_BH + p * 272 + n * 2),
                                   (__half*)(sm + OFF_BL + p * 272 + n * 2));
    }
    __syncthreads();

    const int wid = tid >> 5, lane = tid & 31;
    const int wm = (wid & 3) * 32;
    const int wn = (wid >> 2) * 32;
    const uint32_t laneoff = (uint32_t)((lane >> 2) * 272 + (lane & 3) * 4);

    float acc[2][4][4];
#pragma unroll
    for (int i = 0; i < 2; ++i)
#pragma unroll
        for (int j = 0; j < 4; ++j)
#pragma unroll
            for (int q = 0; q < 4; ++q) acc[i][j][q] = 0.f;

#pragma unroll
    for (int k0 = 0; k0 < 128; k0 += 16) {
        const uint32_t ko = (uint32_t)(k0 * 2) + laneoff;
        uint32_t ah[2][4];
#pragma unroll
        for (int mf = 0; mf < 2; ++mf)
            ldfragA(ah[mf], sb + OFF_AH + (uint32_t)((wm + mf * 16) * 272) + ko);
        uint32_t bh[4][2], bl[4][2];
#pragma unroll
        for (int nf = 0; nf < 4; ++nf) {
            const uint32_t pb = (uint32_t)((wn + nf * 8) * 272) + ko;
            ldfragB(bh[nf], sb + OFF_BH + pb);
            ldfragB(bl[nf], sb + OFF_BL + pb);
        }
#pragma unroll
        for (int mf = 0; mf < 2; ++mf)
#pragma unroll
            for (int nf = 0; nf < 4; ++nf) {
                mma16816h(acc[mf][nf], ah[mf], bh[nf]);
                mma16816h(acc[mf][nf], ah[mf], bl[nf]);
            }
    }
    __syncthreads();

    const int g = lane >> 2;
#pragma unroll
    for (int mf = 0; mf < 2; ++mf) {
        const float s0 = scum[wm + mf * 16 + g];
        const float s1 = scum[wm + mf * 16 + g + 8];
#pragma unroll
        for (int nf = 0; nf < 4; ++nf) {
            acc[mf][nf][0] *= s0; acc[mf][nf][1] *= s0;
            acc[mf][nf][2] *= s1; acc[mf][nf][3] *= s1;
        }
    }

    // stage 2: A = Gamma.*G [t][s] fp16; B = X^T [p][s] split
    const float* Gp = g_G + (size_t)(b * NCHUNK + c) * (TCH * TCH);
    for (int idx = tid; idx < 128 * 128; idx += 256) {
        const int t = idx >> 7, s = idx & 127;
        float val = 0.f;
        if (s <= t) val = fast_exp(slc[t] - slc[s]) * sdt[s] * Gp[idx];
        *(__half*)(sm + OFF_AH + t * 272 + s * 2) = __float2half_rn(val);
    }
    for (int idx = tid; idx < 128 * 64; idx += 256) {
        const int s = idx >> 6, p = idx & 63;
        const float v = g_conv[(size_t)(bl0 + s) * CONV_DIM + h * P_ + p];
        split2h(v, (__half*)(sm + OFF_BH + p * 272 + s * 2),
                   (__half*)(sm + OFF_BL + p * 272 + s * 2));
    }
    __syncthreads();

#pragma unroll
    for (int k0 = 0; k0 < 128; k0 += 16) {
        const uint32_t ko = (uint32_t)(k0 * 2) + laneoff;
        uint32_t ah[2][4];
#pragma unroll
        for (int mf = 0; mf < 2; ++mf)
            ldfragA(ah[mf], sb + OFF_AH + (uint32_t)((wm + mf * 16) * 272) + ko);
        uint32_t bh[4][2], bl[4][2];
#pragma unroll
        for (int nf = 0; nf < 4; ++nf) {
            const uint32_t pb = (uint32_t)((wn + nf * 8) * 272) + ko;
            ldfragB(bh[nf], sb + OFF_BH + pb);
            ldfragB(bl[nf], sb + OFF_BL + pb);
        }
#pragma unroll
        for (int mf = 0; mf < 2; ++mf)
#pragma unroll
            for (int nf = 0; nf < 4; ++nf) {
                mma16816h(acc[mf][nf], ah[mf], bh[nf]);
                mma16816h(acc[mf][nf], ah[mf], bl[nf]);
            }
    }

    const int t2 = (lane & 3) * 2;
#pragma unroll
    for (int mf = 0; mf < 2; ++mf)
#pragma unroll
        for (int nf = 0; nf < 4; ++nf) {
            const int row0 = wm + mf * 16 + g;
            const int col = h * P_ + wn + nf * 8 + t2;
            *(float2*)(g_y + (size_t)(bl0 + row0) * INTER + col) =
                make_float2(acc[mf][nf][0], acc[mf][nf][1]);
            *(float2*)(g_y + (size_t)(bl0 + row0 + 8) * INTER + col) =
                make_float2(acc[mf][nf][2], acc[mf][nf][3]);
        }
}

// ---------------- y + D*xs, gate*silu, RMSNorm, fp16 round ------------------
__global__ __launch_bounds__(256)
void gate_rms_kernel(const float* __restrict__ D_param, const float* __restrict__ norm_w)
{
    const int bl = blockIdx.x;
    const int tid = threadIdx.x;
    const float* yrow = g_y + (size_t)bl * INTER;
    const float* grow = g_proj + (size_t)bl * PROJ_PAD;
    const float* xrow = g_conv + (size_t)bl * CONV_DIM;

    float vals[8];
    float ss = 0.f;
#pragma unroll
    for (int r = 0; r < 2; ++r) {
        const int i = tid * 4 + r * 1024;
        const float4 yv = *(const float4*)(yrow + i);
        const float4 gv = *(const float4*)(grow + i);
        const float4 xv = *(const float4*)(xrow + i);
        const float d = D_param[i >> 6];
        float g0 = (yv.x + d * xv.x) * siluf(gv.x);
        float g1 = (yv.y + d * xv.y) * siluf(gv.y);
        float g2 = (yv.z + d * xv.z) * siluf(gv.z);
        float g3 = (yv.w + d * xv.w) * siluf(gv.w);
        vals[r * 4 + 0] = g0; vals[r * 4 + 1] = g1;
        vals[r * 4 + 2] = g2; vals[r * 4 + 3] = g3;
        ss += g0 * g0 + g1 * g1 + g2 * g2 + g3 * g3;
    }

    __shared__ float red[8];
    __shared__ float stot;
#pragma unroll
    for (int o = 16; o; o >>= 1) ss += __shfl_xor_sync(0xffffffffu, ss, o);
    if ((tid & 31) == 0) red[tid >> 5] = ss;
    __syncthreads();
    if (tid == 0) {
        float v = 0.f;
#pragma unroll
        for (int i = 0; i < 8; ++i) v += red[i];
        stot = rsqrtf(v * (1.f / (float)INTER) + EPSV);
    }
    __syncthreads();
    const float rs = stot;

    __half* gh = g_gate_h + (size_t)bl * INTER;
#pragma unroll
    for (int r = 0; r < 2; ++r) {
        const int i = tid * 4 + r * 1024;
        const float4 nw = *(const float4*)(norm_w + i);
        gh[i + 0] = __float2half_rn(vals[r * 4 + 0] * rs * nw.x);
        gh[i + 1] = __float2half_rn(vals[r * 4 + 1] * rs * nw.y);
        gh[i + 2] = __float2half_rn(vals[r * 4 + 2] * rs * nw.z);
        gh[i + 3] = __float2half_rn(vals[r * 4 + 3] * rs * nw.w);
    }
}

// ---------------- launch -----------------------------------------------------
extern "C" void kernel_launch(void* const* d_in, const int* in_sizes, int n_in,
                              void* d_out, int out_size)
{
    const float* hs      = (const float*)d_in[0];
    const float* W_in    = (const float*)d_in[1];
    const float* conv_w  = (const float*)d_in[2];
    const float* conv_b  = (const float*)d_in[3];
    const float* dt_bias = (const float*)d_in[4];
    const float* A_log   = (const float*)d_in[5];
    const float* D_param = (const float*)d_in[6];
    const float* norm_w  = (const float*)d_in[7];
    const float* W_out   = (const float*)d_in[8];
    float* out = (float*)d_out;

    cudaFuncSetAttribute(gemm_mma2, cudaFuncAttributeMaxDynamicSharedMemorySize,
                         GEMM_SMEM_BYTES);
    cudaFuncSetAttribute(chunk_G_kernel, cudaFuncAttributeMaxDynamicSharedMemorySize,
                         G_SMEM);
    cudaFuncSetAttribute(chunk_state_kernel, cudaFuncAttributeMaxDynamicSharedMemorySize,
                         PH_SMEM);
    cudaFuncSetAttribute(chunk_y_kernel, cudaFuncAttributeMaxDynamicSharedMemorySize,
                         PH_SMEM);

    void *pproj = nullptr;
    void *phh = nullptr, *pwh = nullptr, *pwl = nullptr;
    void *pgh = nullptr, *poh = nullptr, *pol = nullptr;
    cudaGetSymbolAddress(&pproj, g_proj);
    cudaGetSymbolAddress(&phh, g_hs_h);
    cudaGetSymbolAddress(&pwh, g_win_h);
    cudaGetSymbolAddress(&pwl, g_win_l);
    cudaGetSymbolAddress(&pgh, g_gate_h);
    cudaGetSymbolAddress(&poh, g_wo_h);
    cudaGetSymbolAddress(&pol, g_wo_l);

    // 0) conversions
    {
        const int n4 = B_ * L_ * DM / 4;
        round_h_kernel<<<(n4 + 255) / 256, 256>>>(hs, (__half*)phh, n4);
    }
    split_pad_h_kernel<<<(PROJ_PAD * DM / 4 + 255) / 256, 256>>>(
        W_in, (__half*)pwh, (__half*)pwl);
    {
        const int n4 = DM * INTER / 4;
        split_h_kernel<<<(n4 + 255) / 256, 256>>>(W_out, (__half*)poh, (__half*)pol, n4);
    }

    // 1) proj = hs @ W_in^T
    {
        dim3 grid(PROJ_PAD / 128, (B_ * L_) / 128);
        gemm_mma2<<<grid, 256, GEMM_SMEM_BYTES>>>(
            (const __half*)phh, (const __half*)pwh, (const __half*)pwl,
            (float*)pproj, DM, PROJ_PAD);
    }
    // 2) conv + silu + dt (fused)
    {
        dim3 grid(10, B_ * L_);
        conv_dt_kernel<<<grid, 256>>>(conv_w, conv_b, dt_bias);
    }
    // 3) SSD chunked scan (adec produced inside chunk_state)
    chunk_G_kernel<<<dim3(NCHUNK, B_), 256, G_SMEM>>>();
    chunk_state_kernel<<<dim3(NCHUNK, H_, B_), 256, PH_SMEM>>>(A_log);
    scan_combine<<<(B_ * H_ * P_ * N_) / 256, 256>>>();
    chunk_y_kernel<<<dim3(NCHUNK, H_, B_), 256, PH_SMEM>>>(A_log);
    // 4) gate + rmsnorm + fp16 round
    gate_rms_kernel<<<B_ * L_, 256>>>(D_param, norm_w);
    // 5) out = g @ W_out^T
    {
        dim3 grid(DM / 128, (B_ * L_) / 128);
        gemm_mma2<<<grid, 256, GEMM_SMEM_BYTES>>>(
            (const __half*)pgh, (const __half*)poh, (const __half*)pol,
            out, INTER, DM);
    }
}

// round 13
// speedup vs baseline: 2.2609x; 1.3537x over previous
#include <cuda_runtime.h>
#include <cuda_bf16.h>
#include <cuda_fp16.h>
#include <cstdint>
#include <cstddef>

#define B_ 2
#define L_ 4096
#define DM 2048
#define H_ 32
#define P_ 64
#define N_ 128
#define INTER 2048
#define CONV_DIM 2304
#define PROJ 4384
#define PROJ_PAD 4480
#define EPSV 1e-5f
#define NCHUNK 32
#define TCH 128

// ---------------- scratch (__device__ globals; no allocations allowed) ------
__device__ float g_proj[(size_t)B_ * L_ * PROJ_PAD];
__device__ float g_conv[(size_t)B_ * L_ * CONV_DIM];
__device__ float g_y[(size_t)B_ * L_ * INTER];
__device__ float g_dt[B_ * L_ * H_];
__device__ float g_G[(size_t)B_ * NCHUNK * TCH * TCH];
__device__ float g_state[(size_t)B_ * NCHUNK * H_ * N_ * P_];
__device__ float g_init[(size_t)B_ * NCHUNK * H_ * N_ * P_];
__device__ float g_adec[B_ * NCHUNK * H_];
// fp16 GEMM operands (all rounded; single-product)
__device__ __half g_hs_h[(size_t)B_ * L_ * DM];
__device__ __half g_win_h[(size_t)PROJ_PAD * DM];
__device__ __half g_gate_h[(size_t)B_ * L_ * INTER];
__device__ __half g_wo_h[(size_t)DM * INTER];

// ---------------- helpers ----------------------------------------------------
__device__ __forceinline__ float siluf(float x) {
    return x * (1.f / (1.f + expf(-x)));
}
__device__ __forceinline__ float softplusf(float x) {
    return (x > 20.f) ? x : log1pf(expf(x));
}
__device__ __forceinline__ uint32_t s2u(const void* p) {
    return (uint32_t)__cvta_generic_to_shared(p);
}
__device__ __forceinline__ void cp16(uint32_t saddr, const void* g) {
    asm volatile("cp.async.cg.shared.global [%0], [%1], 16;\n" :: "r"(saddr), "l"(g));
}
__device__ __forceinline__ void cp_commit() {
    asm volatile("cp.async.commit_group;\n" ::: "memory");
}
__device__ __forceinline__ void cp_wait2() {
    asm volatile("cp.async.wait_group 2;\n" ::: "memory");
}
__device__ __forceinline__ uint32_t lds32(uint32_t a) {
    uint32_t v;
    asm volatile("ld.shared.b32 %0, [%1];" : "=r"(v) : "r"(a));
    return v;
}
// e^d for d <= 0, rel err ~3e-7, no MUFU
__device__ __forceinline__ float fast_exp(float d) {
    float y = d * 1.44269504f;
    if (y < -126.f) return 0.f;
    float n = floorf(y);
    float f = y - n;
    float p = 1.33336498e-3f;
    p = fmaf(p, f, 9.61011667e-3f);
    p = fmaf(p, f, 5.55036329e-2f);
    p = fmaf(p, f, 2.40226507e-1f);
    p = fmaf(p, f, 6.93147182e-1f);
    p = fmaf(p, f, 1.0f);
    return p * __int_as_float(((int)n + 127) << 23);
}

// ---------------- warp-level HMMA plumbing ----------------------------------
__device__ __forceinline__ void ldm_x4(uint32_t* r, uint32_t addr) {
    asm volatile("ldmatrix.sync.aligned.m8n8.x4.shared.b16 {%0,%1,%2,%3}, [%4];"
                 : "=r"(r[0]), "=r"(r[1]), "=r"(r[2]), "=r"(r[3]) : "r"(addr));
}
__device__ __forceinline__ void mma16816h(float* d, const uint32_t* a, const uint32_t* b) {
    asm volatile(
        "mma.sync.aligned.m16n8k16.row.col.f32.f16.f16.f32 "
        "{%0,%1,%2,%3}, {%4,%5,%6,%7}, {%8,%9}, {%0,%1,%2,%3};"
        : "+f"(d[0]), "+f"(d[1]), "+f"(d[2]), "+f"(d[3])
        : "r"(a[0]), "r"(a[1]), "r"(a[2]), "r"(a[3]), "r"(b[0]), "r"(b[1]));
}
// LDS-based fragment loads from 272B-pitch row-major fp16 tiles
__device__ __forceinline__ void ldfragA(uint32_t r[4], uint32_t base) {
    r[0] = lds32(base);        r[1] = lds32(base + 2176);
    r[2] = lds32(base + 16);   r[3] = lds32(base + 2192);
}
__device__ __forceinline__ void ldfragB(uint32_t r[2], uint32_t base) {
    r[0] = lds32(base);        r[1] = lds32(base + 16);
}
__device__ __forceinline__ void split2h(float v, __half* hp, __half* lp) {
    __half h = __float2half_rn(v);
    *hp = h;
    *lp = __float2half_rn(v - __half2float(h));
}

// ---------------- single-product fp16 GEMM, 4-stage, 2 CTAs/SM --------------
// C = Ah @ Bh^T ; both operands rounded to fp16.
// CTA tile 128x128, BK=32 (64B rows, SW64), 8 warps, warp tile 64x32.
#define STAGE_BYTES 16384
#define TEN_BYTES 8192
#define GEMM_SMEM_BYTES (4 * STAGE_BYTES)

__global__ __launch_bounds__(256, 2)
void gemm_mma1(const __half* __restrict__ Ah, const __half* __restrict__ Bh,
               float* __restrict__ C, int K, int ldc)
{
    extern __shared__ __align__(1024) char smem[];
    const uint32_t sb = s2u(smem);
    const int tid = threadIdx.x;
    const int wid = tid >> 5;
    const int lane = tid & 31;
    const int bn = blockIdx.x * 128;
    const int bm = blockIdx.y * 128;
    const int chunks = K >> 5;

    const int wm = (wid & 1) * 64;
    const int wn = (wid >> 1) * 32;

    const int rA = wm + (lane & 15);
    const uint32_t selA = (lane & 16) ? 16u : 0u;
    const uint32_t xorA = (uint32_t)(((rA >> 1) & 3) * 16);
    uint32_t rowOffA[4];
#pragma unroll
    for (int mf = 0; mf < 4; ++mf) rowOffA[mf] = (uint32_t)((rA + mf * 16) * 64);

    const int rB = wn + (lane & 7) + ((lane & 16) ? 8 : 0);
    const uint32_t selB = (lane & 8) ? 16u : 0u;
    const uint32_t xorB = (uint32_t)(((rB >> 1) & 3) * 16);
    uint32_t rowOffB[2];
#pragma unroll
    for (int nb = 0; nb < 2; ++nb) rowOffB[nb] = (uint32_t)((rB + nb * 16) * 64);

    auto issue = [&](int c) {
        const int s = c & 3;
        const uint32_t base = sb + (uint32_t)s * STAGE_BYTES;
        const int k0 = c << 5;
#pragma unroll
        for (int q = 0; q < 2; ++q) {
            const int cc = q * 256 + tid;
            const int row = cc >> 2;
            const int seg = cc & 3;
            const uint32_t dst =
                (uint32_t)(row * 64 + ((seg * 16) ^ (((row >> 1) & 3) * 16)));
            cp16(base + 0 * TEN_BYTES + dst, Ah + (size_t)(bm + row) * K + k0 + seg * 8);
            cp16(base + 1 * TEN_BYTES + dst, Bh + (size_t)(bn + row) * K + k0 + seg * 8);
        }
    };

    float acc[4][4][4];
#pragma unroll
    for (int i = 0; i < 4; ++i)
#pragma unroll
        for (int j = 0; j < 4; ++j)
#pragma unroll
            for (int q = 0; q < 4; ++q) acc[i][j][q] = 0.f;

    issue(0); cp_commit();
    issue(1); cp_commit();
    issue(2); cp_commit();

    for (int c = 0; c < chunks; ++c) {
        cp_wait2();
        __syncthreads();
        if (c + 3 < chunks) issue(c + 3);
        cp_commit();

        const uint32_t base = sb + (uint32_t)(c & 3) * STAGE_BYTES;
        const uint32_t bAh = base;
        const uint32_t bBh = base + TEN_BYTES;

#pragma unroll
        for (int ks = 0; ks < 2; ++ks) {
            const uint32_t cA = ((uint32_t)(ks * 32) + selA) ^ xorA;
            const uint32_t cB = ((uint32_t)(ks * 32) + selB) ^ xorB;
            uint32_t ah[4][4];
#pragma unroll
            for (int mf = 0; mf < 4; ++mf)
                ldm_x4(ah[mf], bAh + rowOffA[mf] + cA);
            uint32_t bh[4][2];
#pragma unroll
            for (int nb = 0; nb < 2; ++nb) {
                uint32_t t[4];
                ldm_x4(t, bBh + rowOffB[nb] + cB);
                bh[nb * 2][0] = t[0]; bh[nb * 2][1] = t[1];
                bh[nb * 2 + 1][0] = t[2]; bh[nb * 2 + 1][1] = t[3];
            }
#pragma unroll
            for (int mf = 0; mf < 4; ++mf)
#pragma unroll
                for (int nf = 0; nf < 4; ++nf)
                    mma16816h(acc[mf][nf], ah[mf], bh[nf]);
        }
    }

    const int g = lane >> 2;
    const int t2 = (lane & 3) * 2;
#pragma unroll
    for (int mf = 0; mf < 4; ++mf) {
#pragma unroll
        for (int nf = 0; nf < 4; ++nf) {
            const int col = bn + wn + nf * 8 + t2;
            const int row0 = bm + wm + mf * 16 + g;
            *(float2*)(C + (size_t)row0 * ldc + col) =
                make_float2(acc[mf][nf][0], acc[mf][nf][1]);
            *(float2*)(C + (size_t)(row0 + 8) * ldc + col) =
                make_float2(acc[mf][nf][2], acc[mf][nf][3]);
        }
    }
}

// ---------------- fp32 -> fp16 conversions ----------------------------------
__global__ __launch_bounds__(256)
void round_h_kernel(const float* __restrict__ src, __half* __restrict__ hi, int n4)
{
    const int i = blockIdx.x * 256 + threadIdx.x;
    if (i >= n4) return;
    const float4 v = ((const float4*)src)[i];
    hi[i * 4 + 0] = __float2half_rn(v.x);
    hi[i * 4 + 1] = __float2half_rn(v.y);
    hi[i * 4 + 2] = __float2half_rn(v.z);
    hi[i * 4 + 3] = __float2half_rn(v.w);
}

__global__ __launch_bounds__(256)
void round_pad_h_kernel(const float* __restrict__ src, __half* __restrict__ hi)
{
    const int i = blockIdx.x * 256 + threadIdx.x;
    if (i >= PROJ_PAD * DM / 4) return;
    const int row = i / (DM / 4);
    float4 v = make_float4(0.f, 0.f, 0.f, 0.f);
    if (row < PROJ) v = ((const float4*)src)[i];
    hi[i * 4 + 0] = __float2half_rn(v.x);
    hi[i * 4 + 1] = __float2half_rn(v.y);
    hi[i * 4 + 2] = __float2half_rn(v.z);
    hi[i * 4 + 3] = __float2half_rn(v.w);
}

// ---------------- depthwise causal conv (K=4) + bias + SiLU + dt -------------
__global__ __launch_bounds__(256)
void conv_dt_kernel(const float* __restrict__ conv_w, const float* __restrict__ conv_b,
                    const float* __restrict__ dt_bias)
{
    const int bl = blockIdx.y;
    if (blockIdx.x == 9) {
        const int hh = threadIdx.x;
        if (hh >= H_) return;
        const float x = g_proj[(size_t)bl * PROJ_PAD + INTER + CONV_DIM + hh] + dt_bias[hh];
        g_dt[bl * H_ + hh] = softplusf(x);
        return;
    }
    const int c = blockIdx.x * 256 + threadIdx.x;
    if (c >= CONV_DIM) return;
    const int l = bl & (L_ - 1);
    float acc = conv_b[c];
    const float* w = conv_w + c * 4;
#pragma unroll
    for (int j = 0; j < 4; ++j) {
        const int ll = l - 3 + j;
        if (ll >= 0)
            acc = fmaf(g_proj[(size_t)(bl + j - 3) * PROJ_PAD + INTER + c], w[j], acc);
    }
    g_conv[(size_t)bl * CONV_DIM + c] = siluf(acc);
}

// ---------------- SSD chunked scan ------------------------------------------
#define G_SMEM (2 * 128 * 129 * 4)
__global__ __launch_bounds__(256, 1)
void chunk_G_kernel()
{
    const int c = blockIdx.x, b = blockIdx.y;
    extern __shared__ float sg[];
    float* sC = sg;
    float* sB = sg + 128 * 129;
    const int tid = threadIdx.x;
    const int bl0 = b * L_ + c * TCH;
    for (int idx = tid; idx < 128 * 128; idx += 256) {
        const int t = idx >> 7, n = idx & 127;
        const float* row = g_conv + (size_t)(bl0 + t) * CONV_DIM + INTER;
        sB[t * 129 + n] = row[n];
        sC[t * 129 + n] = row[N_ + n];
    }
    __syncthreads();
    const int tt = (tid >> 4) * 8, ss = (tid & 15) * 8;
    float acc[8][8];
#pragma unroll
    for (int i = 0; i < 8; ++i)
#pragma unroll
        for (int j = 0; j < 8; ++j) acc[i][j] = 0.f;
    for (int k = 0; k < 128; ++k) {
        float rc[8], rb[8];
#pragma unroll
        for (int i = 0; i < 8; ++i) rc[i] = sC[(tt + i) * 129 + k];
#pragma unroll
        for (int j = 0; j < 8; ++j) rb[j] = sB[(ss + j) * 129 + k];
#pragma unroll
        for (int i = 0; i < 8; ++i)
#pragma unroll
            for (int j = 0; j < 8; ++j) acc[i][j] = fmaf(rc[i], rb[j], acc[i][j]);
    }
    float* Gp = g_G + (size_t)(b * NCHUNK + c) * (TCH * TCH);
#pragma unroll
    for (int i = 0; i < 8; ++i)
#pragma unroll
        for (int j = 0; j < 8; ++j) Gp[(tt + i) * 128 + ss + j] = acc[i][j];
}

// smem offsets for chunk_state / chunk_y (272B pitch rows; fp16 A single buf)
#define OFF_AH 0
#define OFF_BH 34816
#define OFF_BL 52224
#define OFF_LC 69632
#define OFF_DT 70144
#define OFF_CUM 70656
#define PH_SMEM 71168

// S_partial[n][p] = sum_s exp(lc[127]-lc[s]) dt[s] B[s][n] x[s][p]
__global__ __launch_bounds__(256, 2)
void chunk_state_kernel(const float* __restrict__ A_log)
{
    const int c = blockIdx.x, h = blockIdx.y, b = blockIdx.z;
    extern __shared__ __align__(1024) char sm[];
    const uint32_t sb = s2u(sm);
    float* slc = (float*)(sm + OFF_LC);
    float* sdt = (float*)(sm + OFF_DT);
    const int tid = threadIdx.x;
    const int bl0 = b * L_ + c * TCH;
    const float A = -expf(A_log[h]);

    if (tid < 128) {
        const float d = g_dt[(size_t)(bl0 + tid) * H_ + h];
        sdt[tid] = d;
        slc[tid] = d * A;
    }
    __syncthreads();
    for (int off = 1; off < 128; off <<= 1) {
        float v = 0.f;
        if (tid < 128 && tid >= off) v = slc[tid - off];
        __syncthreads();
        if (tid < 128 && tid >= off) slc[tid] += v;
        __syncthreads();
    }
    const float lcT = slc[127];
    if (tid == 0) g_adec[(b * NCHUNK + c) * H_ + h] = fast_exp(lcT);

    for (int idx = tid; idx < 128 * 128; idx += 256) {
        const int s = idx >> 7, n = idx & 127;
        const float w = fast_exp(lcT - slc[s]) * sdt[s];
        const float v = g_conv[(size_t)(bl0 + s) * CONV_DIM + INTER + n] * w;
        *(__half*)(sm + OFF_AH + n * 272 + s * 2) = __float2half_rn(v);
    }
    for (int idx = tid; idx < 128 * 64; idx += 256) {
        const int s = idx >> 6, p = idx & 63;
        const float v = g_conv[(size_t)(bl0 + s) * CONV_DIM + h * P_ + p];
        split2h(v, (__half*)(sm + OFF_BH + p * 272 + s * 2),
                   (__half*)(sm + OFF_BL + p * 272 + s * 2));
    }
    __syncthreads();

    const int wid = tid >> 5, lane = tid & 31;
    const int wm = (wid & 3) * 32;
    const int wn = (wid >> 2) * 32;
    const uint32_t laneoff = (uint32_t)((lane >> 2) * 272 + (lane & 3) * 4);

    float acc[2][4][4];
#pragma unroll
    for (int i = 0; i < 2; ++i)
#pragma unroll
        for (int j = 0; j < 4; ++j)
#pragma unroll
            for (int q = 0; q < 4; ++q) acc[i][j][q] = 0.f;

#pragma unroll
    for (int k0 = 0; k0 < 128; k0 += 16) {
        const uint32_t ko = (uint32_t)(k0 * 2) + laneoff;
        uint32_t ah[2][4];
#pragma unroll
        for (int mf = 0; mf < 2; ++mf)
            ldfragA(ah[mf], sb + OFF_AH + (uint32_t)((wm + mf * 16) * 272) + ko);
        uint32_t bh[4][2], bl[4][2];
#pragma unroll
        for (int nf = 0; nf < 4; ++nf) {
            const uint32_t pb = (uint32_t)((wn + nf * 8) * 272) + ko;
            ldfragB(bh[nf], sb + OFF_BH + pb);
            ldfragB(bl[nf], sb + OFF_BL + pb);
        }
#pragma unroll
        for (int mf = 0; mf < 2; ++mf)
#pragma unroll
            for (int nf = 0; nf < 4; ++nf) {
                mma16816h(acc[mf][nf], ah[mf], bh[nf]);
                mma16816h(acc[mf][nf], ah[mf], bl[nf]);
            }
    }

    float* st = g_state + (size_t)((b * NCHUNK + c) * H_ + h) * (N_ * P_);
    const int g = lane >> 2;
    const int t2 = (lane & 3) * 2;
#pragma unroll
    for (int mf = 0; mf < 2; ++mf)
#pragma unroll
        for (int nf = 0; nf < 4; ++nf) {
            const int n0 = wm + mf * 16 + g;
            const int col = wn + nf * 8 + t2;
            *(float2*)(st + n0 * P_ + col) = make_float2(acc[mf][nf][0], acc[mf][nf][1]);
            *(float2*)(st + (n0 + 8) * P_ + col) = make_float2(acc[mf][nf][2], acc[mf][nf][3]);
        }
}

__global__ __launch_bounds__(256)
void scan_combine()
{
    const int idx = blockIdx.x * 256 + threadIdx.x;
    if (idx >= B_ * H_ * P_ * N_) return;
    const int h = (idx >> 13) & (H_ - 1);
    const int b = idx >> 18;
    const int pn = idx & (P_ * N_ - 1);
    float carry = 0.f;
#pragma unroll 4
    for (int c = 0; c < NCHUNK; ++c) {
        const size_t off = (size_t)((b * NCHUNK + c) * H_ + h) * (P_ * N_) + pn;
        g_init[off] = carry;
        carry = fmaf(g_adec[(b * NCHUNK + c) * H_ + h], carry, g_state[off]);
    }
}

__global__ __launch_bounds__(256, 2)
void chunk_y_kernel(const float* __restrict__ A_log)
{
    const int c = blockIdx.x, h = blockIdx.y, b = blockIdx.z;
    extern __shared__ __align__(1024) char sm[];
    const uint32_t sb = s2u(sm);
    float* slc = (float*)(sm + OFF_LC);
    float* sdt = (float*)(sm + OFF_DT);
    float* scum = (float*)(sm + OFF_CUM);
    const int tid = threadIdx.x;
    const int bl0 = b * L_ + c * TCH;
    const float A = -expf(A_log[h]);

    if (tid < 128) {
        const float d = g_dt[(size_t)(bl0 + tid) * H_ + h];
        sdt[tid] = d;
        slc[tid] = d * A;
    }
    __syncthreads();
    for (int off = 1; off < 128; off <<= 1) {
        float v = 0.f;
        if (tid < 128 && tid >= off) v = slc[tid - off];
        __syncthreads();
        if (tid < 128 && tid >= off) slc[tid] += v;
        __syncthreads();
    }
    if (tid < 128) scum[tid] = fast_exp(slc[tid]);

    // stage 1: A = C [t][n] fp16; B = S_init^T [p][n] split
    for (int idx = tid; idx < 128 * 128; idx += 256) {
        const int t = idx >> 7, n = idx & 127;
        const float v = g_conv[(size_t)(bl0 + t) * CONV_DIM + INTER + N_ + n];
        *(__half*)(sm + OFF_AH + t * 272 + n * 2) = __float2half_rn(v);
    }
    const float* Sini = g_init + (size_t)((b * NCHUNK + c) * H_ + h) * (N_ * P_);
    for (int idx = tid; idx < 128 * 64; idx += 256) {
        const int n = idx >> 6, p = idx & 63;
        split2h(Sini[n * P_ + p], (__half*)(sm + OFF_BH + p * 272 + n * 2),
                                   (__half*)(sm + OFF_BL + p * 272 + n * 2));
    }
    __syncthreads();

    const int wid = tid >> 5, lane = tid & 31;
    const int wm = (wid & 3) * 32;
    const int wn = (wid >> 2) * 32;
    const uint32_t laneoff = (uint32_t)((lane >> 2) * 272 + (lane & 3) * 4);

    float acc[2][4][4];
#pragma unroll
    for (int i = 0; i < 2; ++i)
#pragma unroll
        for (int j = 0; j < 4; ++j)
#pragma unroll
            for (int q = 0; q < 4; ++q) acc[i][j][q] = 0.f;

#pragma unroll
    for (int k0 = 0; k0 < 128; k0 += 16) {
        const uint32_t ko = (uint32_t)(k0 * 2) + laneoff;
        uint32_t ah[2][4];
#pragma unroll
        for (int mf = 0; mf < 2; ++mf)
            ldfragA(ah[mf], sb + OFF_AH + (uint32_t)((wm + mf * 16) * 272) + ko);
        uint32_t bh[4][2], bl[4][2];
#pragma unroll
        for (int nf = 0; nf < 4; ++nf) {
            const uint32_t pb = (uint32_t)((wn + nf * 8) * 272) + ko;
            ldfragB(bh[nf], sb + OFF_BH + pb);
            ldfragB(bl[nf], sb + OFF_BL + pb);
        }
#pragma unroll
        for (int mf = 0; mf < 2; ++mf)
#pragma unroll
            for (int nf = 0; nf < 4; ++nf) {
                mma16816h(acc[mf][nf], ah[mf], bh[nf]);
                mma16816h(acc[mf][nf], ah[mf], bl[nf]);
            }
    }
    __syncthreads();

    const int g = lane >> 2;
#pragma unroll
    for (int mf = 0; mf < 2; ++mf) {
        const float s0 = scum[wm + mf * 16 + g];
        const float s1 = scum[wm + mf * 16 + g + 8];
#pragma unroll
        for (int nf = 0; nf < 4; ++nf) {
            acc[mf][nf][0] *= s0; acc[mf][nf][1] *= s0;
            acc[mf][nf][2] *= s1; acc[mf][nf][3] *= s1;
        }
    }

    // stage 2: A = Gamma.*G [t][s] fp16; B = X^T [p][s] split
    const float* Gp = g_G + (size_t)(b * NCHUNK + c) * (TCH * TCH);
    for (int idx = tid; idx < 128 * 128; idx += 256) {
        const int t = idx >> 7, s = idx & 127;
        float val = 0.f;
        if (s <= t) val = fast_exp(slc[t] - slc[s]) * sdt[s] * Gp[idx];
        *(__half*)(sm + OFF_AH + t * 272 + s * 2) = __float2half_rn(val);
    }
    for (int idx = tid; idx < 128 * 64; idx += 256) {
        const int s = idx >> 6, p = idx & 63;
        const float v = g_conv[(size_t)(bl0 + s) * CONV_DIM + h * P_ + p];
        split2h(v, (__half*)(sm + OFF_BH + p * 272 + s * 2),
                   (__half*)(sm + OFF_BL + p * 272 + s * 2));
    }
    __syncthreads();

#pragma unroll
    for (int k0 = 0; k0 < 128; k0 += 16) {
        const uint32_t ko = (uint32_t)(k0 * 2) + laneoff;
        uint32_t ah[2][4];
#pragma unroll
        for (int mf = 0; mf < 2; ++mf)
            ldfragA(ah[mf], sb + OFF_AH + (uint32_t)((wm + mf * 16) * 272) + ko);
        uint32_t bh[4][2], bl[4][2];
#pragma unroll
        for (int nf = 0; nf < 4; ++nf) {
            const uint32_t pb = (uint32_t)((wn + nf * 8) * 272) + ko;
            ldfragB(bh[nf], sb + OFF_BH + pb);
            ldfragB(bl[nf], sb + OFF_BL + pb);
        }
#pragma unroll
        for (int mf = 0; mf < 2; ++mf)
#pragma unroll
            for (int nf = 0; nf < 4; ++nf) {
                mma16816h(acc[mf][nf], ah[mf], bh[nf]);
                mma16816h(acc[mf][nf], ah[mf], bl[nf]);
            }
    }

    const int t2 = (lane & 3) * 2;
#pragma unroll
    for (int mf = 0; mf < 2; ++mf)
#pragma unroll
        for (int nf = 0; nf < 4; ++nf) {
            const int row0 = wm + mf * 16 + g;
            const int col = h * P_ + wn + nf * 8 + t2;
            *(float2*)(g_y + (size_t)(bl0 + row0) * INTER + col) =
                make_float2(acc[mf][nf][0], acc[mf][nf][1]);
            *(float2*)(g_y + (size_t)(bl0 + row0 + 8) * INTER + col) =
                make_float2(acc[mf][nf][2], acc[mf][nf][3]);
        }
}

// ---------------- y + D*xs, gate*silu, RMSNorm, fp16 round ------------------
__global__ __launch_bounds__(256)
void gate_rms_kernel(const float* __restrict__ D_param, const float* __restrict__ norm_w)
{
    const int bl = blockIdx.x;
    const int tid = threadIdx.x;
    const float* yrow = g_y + (size_t)bl * INTER;
    const float* grow = g_proj + (size_t)bl * PROJ_PAD;
    const float* xrow = g_conv + (size_t)bl * CONV_DIM;

    float vals[8];
    float ss = 0.f;
#pragma unroll
    for (int r = 0; r < 2; ++r) {
        const int i = tid * 4 + r * 1024;
        const float4 yv = *(const float4*)(yrow + i);
        const float4 gv = *(const float4*)(grow + i);
        const float4 xv = *(const float4*)(xrow + i);
        const float d = D_param[i >> 6];
        float g0 = (yv.x + d * xv.x) * siluf(gv.x);
        float g1 = (yv.y + d * xv.y) * siluf(gv.y);
        float g2 = (yv.z + d * xv.z) * siluf(gv.z);
        float g3 = (yv.w + d * xv.w) * siluf(gv.w);
        vals[r * 4 + 0] = g0; vals[r * 4 + 1] = g1;
        vals[r * 4 + 2] = g2; vals[r * 4 + 3] = g3;
        ss += g0 * g0 + g1 * g1 + g2 * g2 + g3 * g3;
    }

    __shared__ float red[8];
    __shared__ float stot;
#pragma unroll
    for (int o = 16; o; o >>= 1) ss += __shfl_xor_sync(0xffffffffu, ss, o);
    if ((tid & 31) == 0) red[tid >> 5] = ss;
    __syncthreads();
    if (tid == 0) {
        float v = 0.f;
#pragma unroll
        for (int i = 0; i < 8; ++i) v += red[i];
        stot = rsqrtf(v * (1.f / (float)INTER) + EPSV);
    }
    __syncthreads();
    const float rs = stot;

    __half* gh = g_gate_h + (size_t)bl * INTER;
#pragma unroll
    for (int r = 0; r < 2; ++r) {
        const int i = tid * 4 + r * 1024;
        const float4 nw = *(const float4*)(norm_w + i);
        gh[i + 0] = __float2half_rn(vals[r * 4 + 0] * rs * nw.x);
        gh[i + 1] = __float2half_rn(vals[r * 4 + 1] * rs * nw.y);
        gh[i + 2] = __float2half_rn(vals[r * 4 + 2] * rs * nw.z);
        gh[i + 3] = __float2half_rn(vals[r * 4 + 3] * rs * nw.w);
    }
}

// ---------------- launch -----------------------------------------------------
extern "C" void kernel_launch(void* const* d_in, const int* in_sizes, int n_in,
                              void* d_out, int out_size)
{
    const float* hs      = (const float*)d_in[0];
    const float* W_in    = (const float*)d_in[1];
    const float* conv_w  = (const float*)d_in[2];
    const float* conv_b  = (const float*)d_in[3];
    const float* dt_bias = (const float*)d_in[4];
    const float* A_log   = (const float*)d_in[5];
    const float* D_param = (const float*)d_in[6];
    const float* norm_w  = (const float*)d_in[7];
    const float* W_out   = (const float*)d_in[8];
    float* out = (float*)d_out;

    cudaFuncSetAttribute(gemm_mma1, cudaFuncAttributeMaxDynamicSharedMemorySize,
                         GEMM_SMEM_BYTES);
    cudaFuncSetAttribute(chunk_G_kernel, cudaFuncAttributeMaxDynamicSharedMemorySize,
                         G_SMEM);
    cudaFuncSetAttribute(chunk_state_kernel, cudaFuncAttributeMaxDynamicSharedMemorySize,
                         PH_SMEM);
    cudaFuncSetAttribute(chunk_y_kernel, cudaFuncAttributeMaxDynamicSharedMemorySize,
                         PH_SMEM);

    void *pproj = nullptr;
    void *phh = nullptr, *pwh = nullptr, *pgh = nullptr, *poh = nullptr;
    cudaGetSymbolAddress(&pproj, g_proj);
    cudaGetSymbolAddress(&phh, g_hs_h);
    cudaGetSymbolAddress(&pwh, g_win_h);
    cudaGetSymbolAddress(&pgh, g_gate_h);
    cudaGetSymbolAddress(&poh, g_wo_h);

    // 0) conversions
    {
        const int n4 = B_ * L_ * DM / 4;
        round_h_kernel<<<(n4 + 255) / 256, 256>>>(hs, (__half*)phh, n4);
    }
    round_pad_h_kernel<<<(PROJ_PAD * DM / 4 + 255) / 256, 256>>>(W_in, (__half*)pwh);
    {
        const int n4 = DM * INTER / 4;
        round_h_kernel<<<(n4 + 255) / 256, 256>>>(W_out, (__half*)poh, n4);
    }

    // 1) proj = hs @ W_in^T
    {
        dim3 grid(PROJ_PAD / 128, (B_ * L_) / 128);
        gemm_mma1<<<grid, 256, GEMM_SMEM_BYTES>>>(
            (const __half*)phh, (const __half*)pwh, (float*)pproj, DM, PROJ_PAD);
    }
    // 2) conv + silu + dt (fused)
    {
        dim3 grid(10, B_ * L_);
        conv_dt_kernel<<<grid, 256>>>(conv_w, conv_b, dt_bias);
    }
    // 3) SSD chunked scan
    chunk_G_kernel<<<dim3(NCHUNK, B_), 256, G_SMEM>>>();
    chunk_state_kernel<<<dim3(NCHUNK, H_, B_), 256, PH_SMEM>>>(A_log);
    scan_combine<<<(B_ * H_ * P_ * N_) / 256, 256>>>();
    chunk_y_kernel<<<dim3(NCHUNK, H_, B_), 256, PH_SMEM>>>(A_log);
    // 4) gate + rmsnorm + fp16 round
    gate_rms_kernel<<<B_ * L_, 256>>>(D_param, norm_w);
    // 5) out = g @ W_out^T
    {
        dim3 grid(DM / 128, (B_ * L_) / 128);
        gemm_mma1<<<grid, 256, GEMM_SMEM_BYTES>>>(
            (const __half*)pgh, (const __half*)poh, out, INTER, DM);
    }
}

// round 14
// speedup vs baseline: 2.3990x; 1.0611x over previous
#include <cuda_runtime.h>
#include <cuda_bf16.h>
#include <cuda_fp16.h>
#include <cstdint>
#include <cstddef>

#define B_ 2
#define L_ 4096
#define DM 2048
#define H_ 32
#define P_ 64
#define N_ 128
#define INTER 2048
#define CONV_DIM 2304
#define PROJ 4384
#define PROJ_PAD 4480
#define EPSV 1e-5f
#define NCHUNK 32
#define TCH 128

// ---------------- scratch (__device__ globals; no allocations allowed) ------
__device__ float g_proj[(size_t)B_ * L_ * PROJ_PAD];
__device__ __half g_conv_h[(size_t)B_ * L_ * CONV_DIM];
__device__ float g_y[(size_t)B_ * L_ * INTER];
__device__ float g_dt[B_ * L_ * H_];
__device__ float g_G[(size_t)B_ * NCHUNK * TCH * TCH];
__device__ float g_state[(size_t)B_ * NCHUNK * H_ * N_ * P_];
__device__ float g_init[(size_t)B_ * NCHUNK * H_ * N_ * P_];
__device__ float g_adec[B_ * NCHUNK * H_];
// fp16 GEMM operands
__device__ __half g_hs_h[(size_t)B_ * L_ * DM];
__device__ __half g_win_h[(size_t)PROJ_PAD * DM];
__device__ __half g_gate_h[(size_t)B_ * L_ * INTER];
__device__ __half g_wo_h[(size_t)DM * INTER];

// ---------------- helpers ----------------------------------------------------
__device__ __forceinline__ float siluf(float x) {
    return x * (1.f / (1.f + expf(-x)));
}
__device__ __forceinline__ float softplusf(float x) {
    return (x > 20.f) ? x : log1pf(expf(x));
}
__device__ __forceinline__ uint32_t s2u(const void* p) {
    return (uint32_t)__cvta_generic_to_shared(p);
}
__device__ __forceinline__ void cp16(uint32_t saddr, const void* g) {
    asm volatile("cp.async.cg.shared.global [%0], [%1], 16;\n" :: "r"(saddr), "l"(g));
}
__device__ __forceinline__ void cp_commit() {
    asm volatile("cp.async.commit_group;\n" ::: "memory");
}
__device__ __forceinline__ void cp_wait2() {
    asm volatile("cp.async.wait_group 2;\n" ::: "memory");
}
__device__ __forceinline__ uint32_t lds32(uint32_t a) {
    uint32_t v;
    asm volatile("ld.shared.b32 %0, [%1];" : "=r"(v) : "r"(a));
    return v;
}
// e^d for d <= 0, rel err ~3e-7, no MUFU
__device__ __forceinline__ float fast_exp(float d) {
    float y = d * 1.44269504f;
    if (y < -126.f) return 0.f;
    float n = floorf(y);
    float f = y - n;
    float p = 1.33336498e-3f;
    p = fmaf(p, f, 9.61011667e-3f);
    p = fmaf(p, f, 5.55036329e-2f);
    p = fmaf(p, f, 2.40226507e-1f);
    p = fmaf(p, f, 6.93147182e-1f);
    p = fmaf(p, f, 1.0f);
    return p * __int_as_float(((int)n + 127) << 23);
}

// ---------------- warp-level HMMA plumbing ----------------------------------
__device__ __forceinline__ void ldm_x4(uint32_t* r, uint32_t addr) {
    asm volatile("ldmatrix.sync.aligned.m8n8.x4.shared.b16 {%0,%1,%2,%3}, [%4];"
                 : "=r"(r[0]), "=r"(r[1]), "=r"(r[2]), "=r"(r[3]) : "r"(addr));
}
__device__ __forceinline__ void mma16816h(float* d, const uint32_t* a, const uint32_t* b) {
    asm volatile(
        "mma.sync.aligned.m16n8k16.row.col.f32.f16.f16.f32 "
        "{%0,%1,%2,%3}, {%4,%5,%6,%7}, {%8,%9}, {%0,%1,%2,%3};"
        : "+f"(d[0]), "+f"(d[1]), "+f"(d[2]), "+f"(d[3])
        : "r"(a[0]), "r"(a[1]), "r"(a[2]), "r"(a[3]), "r"(b[0]), "r"(b[1]));
}
// LDS-based fragment loads from 272B-pitch row-major fp16 tiles
__device__ __forceinline__ void ldfragA(uint32_t r[4], uint32_t base) {
    r[0] = lds32(base);        r[1] = lds32(base + 2176);
    r[2] = lds32(base + 16);   r[3] = lds32(base + 2192);
}
__device__ __forceinline__ void ldfragB(uint32_t r[2], uint32_t base) {
    r[0] = lds32(base);        r[1] = lds32(base + 16);
}
__device__ __forceinline__ void split2h(float v, __half* hp, __half* lp) {
    __half h = __float2half_rn(v);
    *hp = h;
    *lp = __float2half_rn(v - __half2float(h));
}

// ---------------- single-product fp16 GEMM, 4-stage, 2 CTAs/SM --------------
#define STAGE_BYTES 16384
#define TEN_BYTES 8192
#define GEMM_SMEM_BYTES (4 * STAGE_BYTES)

__global__ __launch_bounds__(256, 2)
void gemm_mma1(const __half* __restrict__ Ah, const __half* __restrict__ Bh,
               float* __restrict__ C, int K, int ldc)
{
    extern __shared__ __align__(1024) char smem[];
    const uint32_t sb = s2u(smem);
    const int tid = threadIdx.x;
    const int wid = tid >> 5;
    const int lane = tid & 31;
    const int bn = blockIdx.x * 128;
    const int bm = blockIdx.y * 128;
    const int chunks = K >> 5;

    const int wm = (wid & 1) * 64;
    const int wn = (wid >> 1) * 32;

    const int rA = wm + (lane & 15);
    const uint32_t selA = (lane & 16) ? 16u : 0u;
    const uint32_t xorA = (uint32_t)(((rA >> 1) & 3) * 16);
    uint32_t rowOffA[4];
#pragma unroll
    for (int mf = 0; mf < 4; ++mf) rowOffA[mf] = (uint32_t)((rA + mf * 16) * 64);

    const int rB = wn + (lane & 7) + ((lane & 16) ? 8 : 0);
    const uint32_t selB = (lane & 8) ? 16u : 0u;
    const uint32_t xorB = (uint32_t)(((rB >> 1) & 3) * 16);
    uint32_t rowOffB[2];
#pragma unroll
    for (int nb = 0; nb < 2; ++nb) rowOffB[nb] = (uint32_t)((rB + nb * 16) * 64);

    auto issue = [&](int c) {
        const int s = c & 3;
        const uint32_t base = sb + (uint32_t)s * STAGE_BYTES;
        const int k0 = c << 5;
#pragma unroll
        for (int q = 0; q < 2; ++q) {
            const int cc = q * 256 + tid;
            const int row = cc >> 2;
            const int seg = cc & 3;
            const uint32_t dst =
                (uint32_t)(row * 64 + ((seg * 16) ^ (((row >> 1) & 3) * 16)));
            cp16(base + 0 * TEN_BYTES + dst, Ah + (size_t)(bm + row) * K + k0 + seg * 8);
            cp16(base + 1 * TEN_BYTES + dst, Bh + (size_t)(bn + row) * K + k0 + seg * 8);
        }
    };

    float acc[4][4][4];
#pragma unroll
    for (int i = 0; i < 4; ++i)
#pragma unroll
        for (int j = 0; j < 4; ++j)
#pragma unroll
            for (int q = 0; q < 4; ++q) acc[i][j][q] = 0.f;

    issue(0); cp_commit();
    issue(1); cp_commit();
    issue(2); cp_commit();

    for (int c = 0; c < chunks; ++c) {
        cp_wait2();
        __syncthreads();
        if (c + 3 < chunks) issue(c + 3);
        cp_commit();

        const uint32_t base = sb + (uint32_t)(c & 3) * STAGE_BYTES;
        const uint32_t bAh = base;
        const uint32_t bBh = base + TEN_BYTES;

#pragma unroll
        for (int ks = 0; ks < 2; ++ks) {
            const uint32_t cA = ((uint32_t)(ks * 32) + selA) ^ xorA;
            const uint32_t cB = ((uint32_t)(ks * 32) + selB) ^ xorB;
            uint32_t ah[4][4];
#pragma unroll
            for (int mf = 0; mf < 4; ++mf)
                ldm_x4(ah[mf], bAh + rowOffA[mf] + cA);
            uint32_t bh[4][2];
#pragma unroll
            for (int nb = 0; nb < 2; ++nb) {
                uint32_t t[4];
                ldm_x4(t, bBh + rowOffB[nb] + cB);
                bh[nb * 2][0] = t[0]; bh[nb * 2][1] = t[1];
                bh[nb * 2 + 1][0] = t[2]; bh[nb * 2 + 1][1] = t[3];
            }
#pragma unroll
            for (int mf = 0; mf < 4; ++mf)
#pragma unroll
                for (int nf = 0; nf < 4; ++nf)
                    mma16816h(acc[mf][nf], ah[mf], bh[nf]);
        }
    }

    const int g = lane >> 2;
    const int t2 = (lane & 3) * 2;
#pragma unroll
    for (int mf = 0; mf < 4; ++mf) {
#pragma unroll
        for (int nf = 0; nf < 4; ++nf) {
            const int col = bn + wn + nf * 8 + t2;
            const int row0 = bm + wm + mf * 16 + g;
            *(float2*)(C + (size_t)row0 * ldc + col) =
                make_float2(acc[mf][nf][0], acc[mf][nf][1]);
            *(float2*)(C + (size_t)(row0 + 8) * ldc + col) =
                make_float2(acc[mf][nf][2], acc[mf][nf][3]);
        }
    }
}

// ---------------- fp32 -> fp16 conversions ----------------------------------
__global__ __launch_bounds__(256)
void round_h_kernel(const float* __restrict__ src, __half* __restrict__ hi, int n4)
{
    const int i = blockIdx.x * 256 + threadIdx.x;
    if (i >= n4) return;
    const float4 v = ((const float4*)src)[i];
    hi[i * 4 + 0] = __float2half_rn(v.x);
    hi[i * 4 + 1] = __float2half_rn(v.y);
    hi[i * 4 + 2] = __float2half_rn(v.z);
    hi[i * 4 + 3] = __float2half_rn(v.w);
}

__global__ __launch_bounds__(256)
void round_pad_h_kernel(const float* __restrict__ src, __half* __restrict__ hi)
{
    const int i = blockIdx.x * 256 + threadIdx.x;
    if (i >= PROJ_PAD * DM / 4) return;
    const int row = i / (DM / 4);
    float4 v = make_float4(0.f, 0.f, 0.f, 0.f);
    if (row < PROJ) v = ((const float4*)src)[i];
    hi[i * 4 + 0] = __float2half_rn(v.x);
    hi[i * 4 + 1] = __float2half_rn(v.y);
    hi[i * 4 + 2] = __float2half_rn(v.z);
    hi[i * 4 + 3] = __float2half_rn(v.w);
}

// ---------------- depthwise conv (K=4) + bias + SiLU -> fp16, plus dt -------
// One block per (b,l): 9 channel iterations + dt for the row.
__global__ __launch_bounds__(256)
void conv_dt_kernel(const float* __restrict__ conv_w, const float* __restrict__ conv_b,
                    const float* __restrict__ dt_bias)
{
    const int bl = blockIdx.x;
    const int tid = threadIdx.x;
    const int l = bl & (L_ - 1);
    const float* base0 = g_proj + (size_t)bl * PROJ_PAD + INTER;
#pragma unroll
    for (int it = 0; it < 9; ++it) {
        const int c = it * 256 + tid;
        float acc = conv_b[c];
        const float* w = conv_w + c * 4;
#pragma unroll
        for (int j = 0; j < 4; ++j) {
            const int ll = l - 3 + j;
            if (ll >= 0)
                acc = fmaf(base0[(ptrdiff_t)(j - 3) * PROJ_PAD + c], w[j], acc);
        }
        g_conv_h[(size_t)bl * CONV_DIM + c] = __float2half_rn(siluf(acc));
    }
    if (tid < H_) {
        const float x = g_proj[(size_t)bl * PROJ_PAD + INTER + CONV_DIM + tid] + dt_bias[tid];
        g_dt[bl * H_ + tid] = softplusf(x);
    }
}

// ---------------- SSD chunked scan ------------------------------------------
#define G_SMEM (2 * 128 * 129 * 4)
__global__ __launch_bounds__(256, 1)
void chunk_G_kernel()
{
    const int c = blockIdx.x, b = blockIdx.y;
    extern __shared__ float sg[];
    float* sC = sg;
    float* sB = sg + 128 * 129;
    const int tid = threadIdx.x;
    const int bl0 = b * L_ + c * TCH;
    for (int idx = tid; idx < 128 * 128; idx += 256) {
        const int t = idx >> 7, n = idx & 127;
        const __half* row = g_conv_h + (size_t)(bl0 + t) * CONV_DIM + INTER;
        sB[t * 129 + n] = __half2float(row[n]);
        sC[t * 129 + n] = __half2float(row[N_ + n]);
    }
    __syncthreads();
    const int tt = (tid >> 4) * 8, ss = (tid & 15) * 8;
    float acc[8][8];
#pragma unroll
    for (int i = 0; i < 8; ++i)
#pragma unroll
        for (int j = 0; j < 8; ++j) acc[i][j] = 0.f;
    for (int k = 0; k < 128; ++k) {
        float rc[8], rb[8];
#pragma unroll
        for (int i = 0; i < 8; ++i) rc[i] = sC[(tt + i) * 129 + k];
#pragma unroll
        for (int j = 0; j < 8; ++j) rb[j] = sB[(ss + j) * 129 + k];
#pragma unroll
        for (int i = 0; i < 8; ++i)
#pragma unroll
            for (int j = 0; j < 8; ++j) acc[i][j] = fmaf(rc[i], rb[j], acc[i][j]);
    }
    float* Gp = g_G + (size_t)(b * NCHUNK + c) * (TCH * TCH);
#pragma unroll
    for (int i = 0; i < 8; ++i)
#pragma unroll
        for (int j = 0; j < 8; ++j) Gp[(tt + i) * 128 + ss + j] = acc[i][j];
}

// smem offsets (272B pitch rows)
#define OFF_AH 0
#define OFF_BH 34816
#define OFF_BL 52224
#define OFF_LC 69632
#define OFF_DT 70144
#define OFF_CUM 70656
#define PH_SMEM 71168

// S_partial[n][p]: A = wB^T rounded fp16; B = X^T exact fp16 (single product)
__global__ __launch_bounds__(256, 2)
void chunk_state_kernel(const float* __restrict__ A_log)
{
    const int c = blockIdx.x, h = blockIdx.y, b = blockIdx.z;
    extern __shared__ __align__(1024) char sm[];
    const uint32_t sb = s2u(sm);
    float* slc = (float*)(sm + OFF_LC);
    float* sdt = (float*)(sm + OFF_DT);
    const int tid = threadIdx.x;
    const int bl0 = b * L_ + c * TCH;
    const float A = -expf(A_log[h]);

    if (tid < 128) {
        const float d = g_dt[(size_t)(bl0 + tid) * H_ + h];
        sdt[tid] = d;
        slc[tid] = d * A;
    }
    __syncthreads();
    for (int off = 1; off < 128; off <<= 1) {
        float v = 0.f;
        if (tid < 128 && tid >= off) v = slc[tid - off];
        __syncthreads();
        if (tid < 128 && tid >= off) slc[tid] += v;
        __syncthreads();
    }
    const float lcT = slc[127];
    if (tid == 0) g_adec[(b * NCHUNK + c) * H_ + h] = fast_exp(lcT);

    for (int idx = tid; idx < 128 * 128; idx += 256) {
        const int s = idx >> 7, n = idx & 127;
        const float w = fast_exp(lcT - slc[s]) * sdt[s];
        const float v = __half2float(g_conv_h[(size_t)(bl0 + s) * CONV_DIM + INTER + n]) * w;
        *(__half*)(sm + OFF_AH + n * 272 + s * 2) = __float2half_rn(v);
    }
    for (int idx = tid; idx < 128 * 64; idx += 256) {
        const int s = idx >> 6, p = idx & 63;
        *(__half*)(sm + OFF_BH + p * 272 + s * 2) =
            g_conv_h[(size_t)(bl0 + s) * CONV_DIM + h * P_ + p];
    }
    __syncthreads();

    const int wid = tid >> 5, lane = tid & 31;
    const int wm = (wid & 3) * 32;
    const int wn = (wid >> 2) * 32;
    const uint32_t laneoff = (uint32_t)((lane >> 2) * 272 + (lane & 3) * 4);

    float acc[2][4][4];
#pragma unroll
    for (int i = 0; i < 2; ++i)
#pragma unroll
        for (int j = 0; j < 4; ++j)
#pragma unroll
            for (int q = 0; q < 4; ++q) acc[i][j][q] = 0.f;

#pragma unroll
    for (int k0 = 0; k0 < 128; k0 += 16) {
        const uint32_t ko = (uint32_t)(k0 * 2) + laneoff;
        uint32_t ah[2][4];
#pragma unroll
        for (int mf = 0; mf < 2; ++mf)
            ldfragA(ah[mf], sb + OFF_AH + (uint32_t)((wm + mf * 16) * 272) + ko);
        uint32_t bh[4][2];
#pragma unroll
        for (int nf = 0; nf < 4; ++nf)
            ldfragB(bh[nf], sb + OFF_BH + (uint32_t)((wn + nf * 8) * 272) + ko);
#pragma unroll
        for (int mf = 0; mf < 2; ++mf)
#pragma unroll
            for (int nf = 0; nf < 4; ++nf)
                mma16816h(acc[mf][nf], ah[mf], bh[nf]);
    }

    float* st = g_state + (size_t)((b * NCHUNK + c) * H_ + h) * (N_ * P_);
    const int g = lane >> 2;
    const int t2 = (lane & 3) * 2;
#pragma unroll
    for (int mf = 0; mf < 2; ++mf)
#pragma unroll
        for (int nf = 0; nf < 4; ++nf) {
            const int n0 = wm + mf * 16 + g;
            const int col = wn + nf * 8 + t2;
            *(float2*)(st + n0 * P_ + col) = make_float2(acc[mf][nf][0], acc[mf][nf][1]);
            *(float2*)(st + (n0 + 8) * P_ + col) = make_float2(acc[mf][nf][2], acc[mf][nf][3]);
        }
}

__global__ __launch_bounds__(256)
void scan_combine()
{
    const int idx = blockIdx.x * 256 + threadIdx.x;
    if (idx >= B_ * H_ * P_ * N_) return;
    const int h = (idx >> 13) & (H_ - 1);
    const int b = idx >> 18;
    const int pn = idx & (P_ * N_ - 1);
    float carry = 0.f;
#pragma unroll 4
    for (int c = 0; c < NCHUNK; ++c) {
        const size_t off = (size_t)((b * NCHUNK + c) * H_ + h) * (P_ * N_) + pn;
        g_init[off] = carry;
        carry = fmaf(g_adec[(b * NCHUNK + c) * H_ + h], carry, g_state[off]);
    }
}

// Y: stage1 A=C exact fp16, B=Sini split (2-product); stage2 A=Gamma.*G
// rounded, B=X exact fp16 (single product).
__global__ __launch_bounds__(256, 2)
void chunk_y_kernel(const float* __restrict__ A_log)
{
    const int c = blockIdx.x, h = blockIdx.y, b = blockIdx.z;
    extern __shared__ __align__(1024) char sm[];
    const uint32_t sb = s2u(sm);
    float* slc = (float*)(sm + OFF_LC);
    float* sdt = (float*)(sm + OFF_DT);
    float* scum = (float*)(sm + OFF_CUM);
    const int tid = threadIdx.x;
    const int bl0 = b * L_ + c * TCH;
    const float A = -expf(A_log[h]);

    if (tid < 128) {
        const float d = g_dt[(size_t)(bl0 + tid) * H_ + h];
        sdt[tid] = d;
        slc[tid] = d * A;
    }
    __syncthreads();
    for (int off = 1; off < 128; off <<= 1) {
        float v = 0.f;
        if (tid < 128 && tid >= off) v = slc[tid - off];
        __syncthreads();
        if (tid < 128 && tid >= off) slc[tid] += v;
        __syncthreads();
    }
    if (tid < 128) scum[tid] = fast_exp(slc[tid]);

    // stage 1
    for (int idx = tid; idx < 128 * 128; idx += 256) {
        const int t = idx >> 7, n = idx & 127;
        *(__half*)(sm + OFF_AH + t * 272 + n * 2) =
            g_conv_h[(size_t)(bl0 + t) * CONV_DIM + INTER + N_ + n];
    }
    const float* Sini = g_init + (size_t)((b * NCHUNK + c) * H_ + h) * (N_ * P_);
    for (int idx = tid; idx < 128 * 64; idx += 256) {
        const int n = idx >> 6, p = idx & 63;
        split2h(Sini[n * P_ + p], (__half*)(sm + OFF_BH + p * 272 + n * 2),
                                   (__half*)(sm + OFF_BL + p * 272 + n * 2));
    }
    __syncthreads();

    const int wid = tid >> 5, lane = tid & 31;
    const int wm = (wid & 3) * 32;
    const int wn = (wid >> 2) * 32;
    const uint32_t laneoff = (uint32_t)((lane >> 2) * 272 + (lane & 3) * 4);

    float acc[2][4][4];
#pragma unroll
    for (int i = 0; i < 2; ++i)
#pragma unroll
        for (int j = 0; j < 4; ++j)
#pragma unroll
            for (int q = 0; q < 4; ++q) acc[i][j][q] = 0.f;

#pragma unroll
    for (int k0 = 0; k0 < 128; k0 += 16) {
        const uint32_t ko = (uint32_t)(k0 * 2) + laneoff;
        uint32_t ah[2][4];
#pragma unroll
        for (int mf = 0; mf < 2; ++mf)
            ldfragA(ah[mf], sb + OFF_AH + (uint32_t)((wm + mf * 16) * 272) + ko);
        uint32_t bh[4][2], bl[4][2];
#pragma unroll
        for (int nf = 0; nf < 4; ++nf) {
            const uint32_t pb = (uint32_t)((wn + nf * 8) * 272) + ko;
            ldfragB(bh[nf], sb + OFF_BH + pb);
            ldfragB(bl[nf], sb + OFF_BL + pb);
        }
#pragma unroll
        for (int mf = 0; mf < 2; ++mf)
#pragma unroll
            for (int nf = 0; nf < 4; ++nf) {
                mma16816h(acc[mf][nf], ah[mf], bh[nf]);
                mma16816h(acc[mf][nf], ah[mf], bl[nf]);
            }
    }
    __syncthreads();

    const int g = lane >> 2;
#pragma unroll
    for (int mf = 0; mf < 2; ++mf) {
        const float s0 = scum[wm + mf * 16 + g];
        const float s1 = scum[wm + mf * 16 + g + 8];
#pragma unroll
        for (int nf = 0; nf < 4; ++nf) {
            acc[mf][nf][0] *= s0; acc[mf][nf][1] *= s0;
            acc[mf][nf][2] *= s1; acc[mf][nf][3] *= s1;
        }
    }

    // stage 2
    const float* Gp = g_G + (size_t)(b * NCHUNK + c) * (TCH * TCH);
    for (int idx = tid; idx < 128 * 128; idx += 256) {
        const int t = idx >> 7, s = idx & 127;
        float val = 0.f;
        if (s <= t) val = fast_exp(slc[t] - slc[s]) * sdt[s] * Gp[idx];
        *(__half*)(sm + OFF_AH + t * 272 + s * 2) = __float2half_rn(val);
    }
    for (int idx = tid; idx < 128 * 64; idx += 256) {
        const int s = idx >> 6, p = idx & 63;
        *(__half*)(sm + OFF_BH + p * 272 + s * 2) =
            g_conv_h[(size_t)(bl0 + s) * CONV_DIM + h * P_ + p];
    }
    __syncthreads();

#pragma unroll
    for (int k0 = 0; k0 < 128; k0 += 16) {
        const uint32_t ko = (uint32_t)(k0 * 2) + laneoff;
        uint32_t ah[2][4];
#pragma unroll
        for (int mf = 0; mf < 2; ++mf)
            ldfragA(ah[mf], sb + OFF_AH + (uint32_t)((wm + mf * 16) * 272) + ko);
        uint32_t bh[4][2];
#pragma unroll
        for (int nf = 0; nf < 4; ++nf)
            ldfragB(bh[nf], sb + OFF_BH + (uint32_t)((wn + nf * 8) * 272) + ko);
#pragma unroll
        for (int mf = 0; mf < 2; ++mf)
#pragma unroll
            for (int nf = 0; nf < 4; ++nf)
                mma16816h(acc[mf][nf], ah[mf], bh[nf]);
    }

    const int t2 = (lane & 3) * 2;
#pragma unroll
    for (int mf = 0; mf < 2; ++mf)
#pragma unroll
        for (int nf = 0; nf < 4; ++nf) {
            const int row0 = wm + mf * 16 + g;
            const int col = h * P_ + wn + nf * 8 + t2;
            *(float2*)(g_y + (size_t)(bl0 + row0) * INTER + col) =
                make_float2(acc[mf][nf][0], acc[mf][nf][1]);
            *(float2*)(g_y + (size_t)(bl0 + row0 + 8) * INTER + col) =
                make_float2(acc[mf][nf][2], acc[mf][nf][3]);
        }
}

// ---------------- y + D*xs, gate*silu, RMSNorm, fp16 round ------------------
__global__ __launch_bounds__(256)
void gate_rms_kernel(const float* __restrict__ D_param, const float* __restrict__ norm_w)
{
    const int bl = blockIdx.x;
    const int tid = threadIdx.x;
    const float* yrow = g_y + (size_t)bl * INTER;
    const float* grow = g_proj + (size_t)bl * PROJ_PAD;
    const __half2* xrow = (const __half2*)(g_conv_h + (size_t)bl * CONV_DIM);

    float vals[8];
    float ss = 0.f;
#pragma unroll
    for (int r = 0; r < 2; ++r) {
        const int i = tid * 4 + r * 1024;
        const float4 yv = *(const float4*)(yrow + i);
        const float4 gv = *(const float4*)(grow + i);
        const float2 xa = __half22float2(xrow[i / 2]);
        const float2 xb = __half22float2(xrow[i / 2 + 1]);
        const float d = D_param[i >> 6];
        float g0 = (yv.x + d * xa.x) * siluf(gv.x);
        float g1 = (yv.y + d * xa.y) * siluf(gv.y);
        float g2 = (yv.z + d * xb.x) * siluf(gv.z);
        float g3 = (yv.w + d * xb.y) * siluf(gv.w);
        vals[r * 4 + 0] = g0; vals[r * 4 + 1] = g1;
        vals[r * 4 + 2] = g2; vals[r * 4 + 3] = g3;
        ss += g0 * g0 + g1 * g1 + g2 * g2 + g3 * g3;
    }

    __shared__ float red[8];
    __shared__ float stot;
#pragma unroll
    for (int o = 16; o; o >>= 1) ss += __shfl_xor_sync(0xffffffffu, ss, o);
    if ((tid & 31) == 0) red[tid >> 5] = ss;
    __syncthreads();
    if (tid == 0) {
        float v = 0.f;
#pragma unroll
        for (int i = 0; i < 8; ++i) v += red[i];
        stot = rsqrtf(v * (1.f / (float)INTER) + EPSV);
    }
    __syncthreads();
    const float rs = stot;

    __half* gh = g_gate_h + (size_t)bl * INTER;
#pragma unroll
    for (int r = 0; r < 2; ++r) {
        const int i = tid * 4 + r * 1024;
        const float4 nw = *(const float4*)(norm_w + i);
        gh[i + 0] = __float2half_rn(vals[r * 4 + 0] * rs * nw.x);
        gh[i + 1] = __float2half_rn(vals[r * 4 + 1] * rs * nw.y);
        gh[i + 2] = __float2half_rn(vals[r * 4 + 2] * rs * nw.z);
        gh[i + 3] = __float2half_rn(vals[r * 4 + 3] * rs * nw.w);
    }
}

// ---------------- launch -----------------------------------------------------
extern "C" void kernel_launch(void* const* d_in, const int* in_sizes, int n_in,
                              void* d_out, int out_size)
{
    const float* hs      = (const float*)d_in[0];
    const float* W_in    = (const float*)d_in[1];
    const float* conv_w  = (const float*)d_in[2];
    const float* conv_b  = (const float*)d_in[3];
    const float* dt_bias = (const float*)d_in[4];
    const float* A_log   = (const float*)d_in[5];
    const float* D_param = (const float*)d_in[6];
    const float* norm_w  = (const float*)d_in[7];
    const float* W_out   = (const float*)d_in[8];
    float* out = (float*)d_out;

    cudaFuncSetAttribute(gemm_mma1, cudaFuncAttributeMaxDynamicSharedMemorySize,
                         GEMM_SMEM_BYTES);
    cudaFuncSetAttribute(chunk_G_kernel, cudaFuncAttributeMaxDynamicSharedMemorySize,
                         G_SMEM);
    cudaFuncSetAttribute(chunk_state_kernel, cudaFuncAttributeMaxDynamicSharedMemorySize,
                         PH_SMEM);
    cudaFuncSetAttribute(chunk_y_kernel, cudaFuncAttributeMaxDynamicSharedMemorySize,
                         PH_SMEM);

    void *pproj = nullptr;
    void *phh = nullptr, *pwh = nullptr, *pgh = nullptr, *poh = nullptr;
    cudaGetSymbolAddress(&pproj, g_proj);
    cudaGetSymbolAddress(&phh, g_hs_h);
    cudaGetSymbolAddress(&pwh, g_win_h);
    cudaGetSymbolAddress(&pgh, g_gate_h);
    cudaGetSymbolAddress(&poh, g_wo_h);

    // 0) conversions
    {
        const int n4 = B_ * L_ * DM / 4;
        round_h_kernel<<<(n4 + 255) / 256, 256>>>(hs, (__half*)phh, n4);
    }
    round_pad_h_kernel<<<(PROJ_PAD * DM / 4 + 255) / 256, 256>>>(W_in, (__half*)pwh);
    {
        const int n4 = DM * INTER / 4;
        round_h_kernel<<<(n4 + 255) / 256, 256>>>(W_out, (__half*)poh, n4);
    }

    // 1) proj = hs @ W_in^T
    {
        dim3 grid(PROJ_PAD / 128, (B_ * L_) / 128);
        gemm_mma1<<<grid, 256, GEMM_SMEM_BYTES>>>(
            (const __half*)phh, (const __half*)pwh, (float*)pproj, DM, PROJ_PAD);
    }
    // 2) conv + silu + dt
    conv_dt_kernel<<<B_ * L_, 256>>>(conv_w, conv_b, dt_bias);
    // 3) SSD chunked scan
    chunk_G_kernel<<<dim3(NCHUNK, B_), 256, G_SMEM>>>();
    chunk_state_kernel<<<dim3(NCHUNK, H_, B_), 256, PH_SMEM>>>(A_log);
    scan_combine<<<(B_ * H_ * P_ * N_) / 256, 256>>>();
    chunk_y_kernel<<<dim3(NCHUNK, H_, B_), 256, PH_SMEM>>>(A_log);
    // 4) gate + rmsnorm + fp16 round
    gate_rms_kernel<<<B_ * L_, 256>>>(D_param, norm_w);
    // 5) out = g @ W_out^T
    {
        dim3 grid(DM / 128, (B_ * L_) / 128);
        gemm_mma1<<<grid, 256, GEMM_SMEM_BYTES>>>(
            (const __half*)pgh, (const __half*)poh, out, INTER, DM);
    }
}

// round 15
// speedup vs baseline: 2.4296x; 1.0127x over previous
#include <cuda_runtime.h>
#include <cuda_bf16.h>
#include <cuda_fp16.h>
#include <cstdint>
#include <cstddef>

#define B_ 2
#define L_ 4096
#define DM 2048
#define H_ 32
#define P_ 64
#define N_ 128
#define INTER 2048
#define CONV_DIM 2304
#define PROJ 4384
#define PROJ_PAD 4480
#define EPSV 1e-5f
#define NCHUNK 32
#define TCH 128

// ---------------- scratch (__device__ globals; no allocations allowed) ------
__device__ __half g_proj_h[(size_t)B_ * L_ * PROJ_PAD];
__device__ __half g_conv_h[(size_t)B_ * L_ * CONV_DIM];
__device__ __half g_y_h[(size_t)B_ * L_ * INTER];
__device__ float g_dt[B_ * L_ * H_];
__device__ float g_G[(size_t)B_ * NCHUNK * TCH * TCH];
__device__ float g_state[(size_t)B_ * NCHUNK * H_ * N_ * P_];
__device__ float g_init[(size_t)B_ * NCHUNK * H_ * N_ * P_];
__device__ float g_adec[B_ * NCHUNK * H_];
// fp16 GEMM operands
__device__ __half g_hs_h[(size_t)B_ * L_ * DM];
__device__ __half g_win_h[(size_t)PROJ_PAD * DM];
__device__ __half g_gate_h[(size_t)B_ * L_ * INTER];
__device__ __half g_wo_h[(size_t)DM * INTER];

// ---------------- helpers ----------------------------------------------------
__device__ __forceinline__ float siluf(float x) {
    return x * (1.f / (1.f + expf(-x)));
}
__device__ __forceinline__ float softplusf(float x) {
    return (x > 20.f) ? x : log1pf(expf(x));
}
__device__ __forceinline__ uint32_t s2u(const void* p) {
    return (uint32_t)__cvta_generic_to_shared(p);
}
__device__ __forceinline__ void cp16(uint32_t saddr, const void* g) {
    asm volatile("cp.async.cg.shared.global [%0], [%1], 16;\n" :: "r"(saddr), "l"(g));
}
__device__ __forceinline__ void cp_commit() {
    asm volatile("cp.async.commit_group;\n" ::: "memory");
}
__device__ __forceinline__ void cp_wait2() {
    asm volatile("cp.async.wait_group 2;\n" ::: "memory");
}
__device__ __forceinline__ uint32_t lds32(uint32_t a) {
    uint32_t v;
    asm volatile("ld.shared.b32 %0, [%1];" : "=r"(v) : "r"(a));
    return v;
}
// e^d for d <= 0, rel err ~3e-7, no MUFU
__device__ __forceinline__ float fast_exp(float d) {
    float y = d * 1.44269504f;
    if (y < -126.f) return 0.f;
    float n = floorf(y);
    float f = y - n;
    float p = 1.33336498e-3f;
    p = fmaf(p, f, 9.61011667e-3f);
    p = fmaf(p, f, 5.55036329e-2f);
    p = fmaf(p, f, 2.40226507e-1f);
    p = fmaf(p, f, 6.93147182e-1f);
    p = fmaf(p, f, 1.0f);
    return p * __int_as_float(((int)n + 127) << 23);
}

// ---------------- warp-level HMMA plumbing ----------------------------------
__device__ __forceinline__ void ldm_x4(uint32_t* r, uint32_t addr) {
    asm volatile("ldmatrix.sync.aligned.m8n8.x4.shared.b16 {%0,%1,%2,%3}, [%4];"
                 : "=r"(r[0]), "=r"(r[1]), "=r"(r[2]), "=r"(r[3]) : "r"(addr));
}
__device__ __forceinline__ void mma16816h(float* d, const uint32_t* a, const uint32_t* b) {
    asm volatile(
        "mma.sync.aligned.m16n8k16.row.col.f32.f16.f16.f32 "
        "{%0,%1,%2,%3}, {%4,%5,%6,%7}, {%8,%9}, {%0,%1,%2,%3};"
        : "+f"(d[0]), "+f"(d[1]), "+f"(d[2]), "+f"(d[3])
        : "r"(a[0]), "r"(a[1]), "r"(a[2]), "r"(a[3]), "r"(b[0]), "r"(b[1]));
}
// LDS-based fragment loads from 272B-pitch row-major fp16 tiles
__device__ __forceinline__ void ldfragA(uint32_t r[4], uint32_t base) {
    r[0] = lds32(base);        r[1] = lds32(base + 2176);
    r[2] = lds32(base + 16);   r[3] = lds32(base + 2192);
}
__device__ __forceinline__ void ldfragB(uint32_t r[2], uint32_t base) {
    r[0] = lds32(base);        r[1] = lds32(base + 16);
}
__device__ __forceinline__ void split2h(float v, __half* hp, __half* lp) {
    __half h = __float2half_rn(v);
    *hp = h;
    *lp = __float2half_rn(v - __half2float(h));
}

// ---------------- single-product fp16 GEMM core (templated epilogue) --------
#define STAGE_BYTES 16384
#define TEN_BYTES 8192
#define GEMM_SMEM_BYTES (4 * STAGE_BYTES)

template <int HALF_OUT>
__global__ __launch_bounds__(256, 2)
void gemm_mma1(const __half* __restrict__ Ah, const __half* __restrict__ Bh,
               void* __restrict__ Cv, int K, int ldc)
{
    extern __shared__ __align__(1024) char smem[];
    const uint32_t sb = s2u(smem);
    const int tid = threadIdx.x;
    const int wid = tid >> 5;
    const int lane = tid & 31;
    const int bn = blockIdx.x * 128;
    const int bm = blockIdx.y * 128;
    const int chunks = K >> 5;

    const int wm = (wid & 1) * 64;
    const int wn = (wid >> 1) * 32;

    const int rA = wm + (lane & 15);
    const uint32_t selA = (lane & 16) ? 16u : 0u;
    const uint32_t xorA = (uint32_t)(((rA >> 1) & 3) * 16);
    uint32_t rowOffA[4];
#pragma unroll
    for (int mf = 0; mf < 4; ++mf) rowOffA[mf] = (uint32_t)((rA + mf * 16) * 64);

    const int rB = wn + (lane & 7) + ((lane & 16) ? 8 : 0);
    const uint32_t selB = (lane & 8) ? 16u : 0u;
    const uint32_t xorB = (uint32_t)(((rB >> 1) & 3) * 16);
    uint32_t rowOffB[2];
#pragma unroll
    for (int nb = 0; nb < 2; ++nb) rowOffB[nb] = (uint32_t)((rB + nb * 16) * 64);

    auto issue = [&](int c) {
        const int s = c & 3;
        const uint32_t base = sb + (uint32_t)s * STAGE_BYTES;
        const int k0 = c << 5;
#pragma unroll
        for (int q = 0; q < 2; ++q) {
            const int cc = q * 256 + tid;
            const int row = cc >> 2;
            const int seg = cc & 3;
            const uint32_t dst =
                (uint32_t)(row * 64 + ((seg * 16) ^ (((row >> 1) & 3) * 16)));
            cp16(base + 0 * TEN_BYTES + dst, Ah + (size_t)(bm + row) * K + k0 + seg * 8);
            cp16(base + 1 * TEN_BYTES + dst, Bh + (size_t)(bn + row) * K + k0 + seg * 8);
        }
    };

    float acc[4][4][4];
#pragma unroll
    for (int i = 0; i < 4; ++i)
#pragma unroll
        for (int j = 0; j < 4; ++j)
#pragma unroll
            for (int q = 0; q < 4; ++q) acc[i][j][q] = 0.f;

    issue(0); cp_commit();
    issue(1); cp_commit();
    issue(2); cp_commit();

    for (int c = 0; c < chunks; ++c) {
        cp_wait2();
        __syncthreads();
        if (c + 3 < chunks) issue(c + 3);
        cp_commit();

        const uint32_t base = sb + (uint32_t)(c & 3) * STAGE_BYTES;
        const uint32_t bAh = base;
        const uint32_t bBh = base + TEN_BYTES;

#pragma unroll
        for (int ks = 0; ks < 2; ++ks) {
            const uint32_t cA = ((uint32_t)(ks * 32) + selA) ^ xorA;
            const uint32_t cB = ((uint32_t)(ks * 32) + selB) ^ xorB;
            uint32_t ah[4][4];
#pragma unroll
            for (int mf = 0; mf < 4; ++mf)
                ldm_x4(ah[mf], bAh + rowOffA[mf] + cA);
            uint32_t bh[4][2];
#pragma unroll
            for (int nb = 0; nb < 2; ++nb) {
                uint32_t t[4];
                ldm_x4(t, bBh + rowOffB[nb] + cB);
                bh[nb * 2][0] = t[0]; bh[nb * 2][1] = t[1];
                bh[nb * 2 + 1][0] = t[2]; bh[nb * 2 + 1][1] = t[3];
            }
#pragma unroll
            for (int mf = 0; mf < 4; ++mf)
#pragma unroll
                for (int nf = 0; nf < 4; ++nf)
                    mma16816h(acc[mf][nf], ah[mf], bh[nf]);
        }
    }

    const int g = lane >> 2;
    const int t2 = (lane & 3) * 2;
#pragma unroll
    for (int mf = 0; mf < 4; ++mf) {
#pragma unroll
        for (int nf = 0; nf < 4; ++nf) {
            const int col = bn + wn + nf * 8 + t2;
            const int row0 = bm + wm + mf * 16 + g;
            if (HALF_OUT) {
                __half* C = (__half*)Cv;
                *(__half2*)(C + (size_t)row0 * ldc + col) =
                    __floats2half2_rn(acc[mf][nf][0], acc[mf][nf][1]);
                *(__half2*)(C + (size_t)(row0 + 8) * ldc + col) =
                    __floats2half2_rn(acc[mf][nf][2], acc[mf][nf][3]);
            } else {
                float* C = (float*)Cv;
                *(float2*)(C + (size_t)row0 * ldc + col) =
                    make_float2(acc[mf][nf][0], acc[mf][nf][1]);
                *(float2*)(C + (size_t)(row0 + 8) * ldc + col) =
                    make_float2(acc[mf][nf][2], acc[mf][nf][3]);
            }
        }
    }
}

// ---------------- fp32 -> fp16 conversions ----------------------------------
__global__ __launch_bounds__(256)
void round_h_kernel(const float* __restrict__ src, __half* __restrict__ hi, int n4)
{
    const int i = blockIdx.x * 256 + threadIdx.x;
    if (i >= n4) return;
    const float4 v = ((const float4*)src)[i];
    hi[i * 4 + 0] = __float2half_rn(v.x);
    hi[i * 4 + 1] = __float2half_rn(v.y);
    hi[i * 4 + 2] = __float2half_rn(v.z);
    hi[i * 4 + 3] = __float2half_rn(v.w);
}

__global__ __launch_bounds__(256)
void round_pad_h_kernel(const float* __restrict__ src, __half* __restrict__ hi)
{
    const int i = blockIdx.x * 256 + threadIdx.x;
    if (i >= PROJ_PAD * DM / 4) return;
    const int row = i / (DM / 4);
    float4 v = make_float4(0.f, 0.f, 0.f, 0.f);
    if (row < PROJ) v = ((const float4*)src)[i];
    hi[i * 4 + 0] = __float2half_rn(v.x);
    hi[i * 4 + 1] = __float2half_rn(v.y);
    hi[i * 4 + 2] = __float2half_rn(v.z);
    hi[i * 4 + 3] = __float2half_rn(v.w);
}

// ---------------- depthwise conv (K=4) + bias + SiLU -> fp16, plus dt -------
__global__ __launch_bounds__(256)
void conv_dt_kernel(const float* __restrict__ conv_w, const float* __restrict__ conv_b,
                    const float* __restrict__ dt_bias)
{
    const int bl = blockIdx.x;
    const int tid = threadIdx.x;
    const int l = bl & (L_ - 1);
    const __half* base0 = g_proj_h + (size_t)bl * PROJ_PAD + INTER;
#pragma unroll
    for (int it = 0; it < 9; ++it) {
        const int c = it * 256 + tid;
        float acc = conv_b[c];
        const float* w = conv_w + c * 4;
#pragma unroll
        for (int j = 0; j < 4; ++j) {
            const int ll = l - 3 + j;
            if (ll >= 0)
                acc = fmaf(__half2float(base0[(ptrdiff_t)(j - 3) * PROJ_PAD + c]), w[j], acc);
        }
        g_conv_h[(size_t)bl * CONV_DIM + c] = __float2half_rn(siluf(acc));
    }
    if (tid < H_) {
        const float x = __half2float(g_proj_h[(size_t)bl * PROJ_PAD + INTER + CONV_DIM + tid])
                        + dt_bias[tid];
        g_dt[bl * H_ + tid] = softplusf(x);
    }
}

// ---------------- SSD chunked scan ------------------------------------------
#define G_SMEM (2 * 128 * 129 * 4)
__global__ __launch_bounds__(256, 1)
void chunk_G_kernel()
{
    const int c = blockIdx.x, b = blockIdx.y;
    extern __shared__ float sg[];
    float* sC = sg;
    float* sB = sg + 128 * 129;
    const int tid = threadIdx.x;
    const int bl0 = b * L_ + c * TCH;
    for (int idx = tid; idx < 128 * 128; idx += 256) {
        const int t = idx >> 7, n = idx & 127;
        const __half* row = g_conv_h + (size_t)(bl0 + t) * CONV_DIM + INTER;
        sB[t * 129 + n] = __half2float(row[n]);
        sC[t * 129 + n] = __half2float(row[N_ + n]);
    }
    __syncthreads();
    const int tt = (tid >> 4) * 8, ss = (tid & 15) * 8;
    float acc[8][8];
#pragma unroll
    for (int i = 0; i < 8; ++i)
#pragma unroll
        for (int j = 0; j < 8; ++j) acc[i][j] = 0.f;
    for (int k = 0; k < 128; ++k) {
        float rc[8], rb[8];
#pragma unroll
        for (int i = 0; i < 8; ++i) rc[i] = sC[(tt + i) * 129 + k];
#pragma unroll
        for (int j = 0; j < 8; ++j) rb[j] = sB[(ss + j) * 129 + k];
#pragma unroll
        for (int i = 0; i < 8; ++i)
#pragma unroll
            for (int j = 0; j < 8; ++j) acc[i][j] = fmaf(rc[i], rb[j], acc[i][j]);
    }
    float* Gp = g_G + (size_t)(b * NCHUNK + c) * (TCH * TCH);
#pragma unroll
    for (int i = 0; i < 8; ++i)
#pragma unroll
        for (int j = 0; j < 8; ++j) Gp[(tt + i) * 128 + ss + j] = acc[i][j];
}

// smem offsets (272B pitch rows)
#define OFF_AH 0
#define OFF_BH 34816
#define OFF_BL 52224
#define OFF_LC 69632
#define OFF_DT 70144
#define OFF_CUM 70656
#define PH_SMEM 71168

__global__ __launch_bounds__(256, 2)
void chunk_state_kernel(const float* __restrict__ A_log)
{
    const int c = blockIdx.x, h = blockIdx.y, b = blockIdx.z;
    extern __shared__ __align__(1024) char sm[];
    const uint32_t sb = s2u(sm);
    float* slc = (float*)(sm + OFF_LC);
    float* sdt = (float*)(sm + OFF_DT);
    const int tid = threadIdx.x;
    const int bl0 = b * L_ + c * TCH;
    const float A = -expf(A_log[h]);

    if (tid < 128) {
        const float d = g_dt[(size_t)(bl0 + tid) * H_ + h];
        sdt[tid] = d;
        slc[tid] = d * A;
    }
    __syncthreads();
    for (int off = 1; off < 128; off <<= 1) {
        float v = 0.f;
        if (tid < 128 && tid >= off) v = slc[tid - off];
        __syncthreads();
        if (tid < 128 && tid >= off) slc[tid] += v;
        __syncthreads();
    }
    const float lcT = slc[127];
    if (tid == 0) g_adec[(b * NCHUNK + c) * H_ + h] = fast_exp(lcT);

    for (int idx = tid; idx < 128 * 128; idx += 256) {
        const int s = idx >> 7, n = idx & 127;
        const float w = fast_exp(lcT - slc[s]) * sdt[s];
        const float v = __half2float(g_conv_h[(size_t)(bl0 + s) * CONV_DIM + INTER + n]) * w;
        *(__half*)(sm + OFF_AH + n * 272 + s * 2) = __float2half_rn(v);
    }
    for (int idx = tid; idx < 128 * 64; idx += 256) {
        const int s = idx >> 6, p = idx & 63;
        *(__half*)(sm + OFF_BH + p * 272 + s * 2) =
            g_conv_h[(size_t)(bl0 + s) * CONV_DIM + h * P_ + p];
    }
    __syncthreads();

    const int wid = tid >> 5, lane = tid & 31;
    const int wm = (wid & 3) * 32;
    const int wn = (wid >> 2) * 32;
    const uint32_t laneoff = (uint32_t)((lane >> 2) * 272 + (lane & 3) * 4);

    float acc[2][4][4];
#pragma unroll
    for (int i = 0; i < 2; ++i)
#pragma unroll
        for (int j = 0; j < 4; ++j)
#pragma unroll
            for (int q = 0; q < 4; ++q) acc[i][j][q] = 0.f;

#pragma unroll
    for (int k0 = 0; k0 < 128; k0 += 16) {
        const uint32_t ko = (uint32_t)(k0 * 2) + laneoff;
        uint32_t ah[2][4];
#pragma unroll
        for (int mf = 0; mf < 2; ++mf)
            ldfragA(ah[mf], sb + OFF_AH + (uint32_t)((wm + mf * 16) * 272) + ko);
        uint32_t bh[4][2];
#pragma unroll
        for (int nf = 0; nf < 4; ++nf)
            ldfragB(bh[nf], sb + OFF_BH + (uint32_t)((wn + nf * 8) * 272) + ko);
#pragma unroll
        for (int mf = 0; mf < 2; ++mf)
#pragma unroll
            for (int nf = 0; nf < 4; ++nf)
                mma16816h(acc[mf][nf], ah[mf], bh[nf]);
    }

    float* st = g_state + (size_t)((b * NCHUNK + c) * H_ + h) * (N_ * P_);
    const int g = lane >> 2;
    const int t2 = (lane & 3) * 2;
#pragma unroll
    for (int mf = 0; mf < 2; ++mf)
#pragma unroll
        for (int nf = 0; nf < 4; ++nf) {
            const int n0 = wm + mf * 16 + g;
            const int col = wn + nf * 8 + t2;
            *(float2*)(st + n0 * P_ + col) = make_float2(acc[mf][nf][0], acc[mf][nf][1]);
            *(float2*)(st + (n0 + 8) * P_ + col) = make_float2(acc[mf][nf][2], acc[mf][nf][3]);
        }
}

__global__ __launch_bounds__(256)
void scan_combine()
{
    const int idx = blockIdx.x * 256 + threadIdx.x;
    if (idx >= B_ * H_ * P_ * N_) return;
    const int h = (idx >> 13) & (H_ - 1);
    const int b = idx >> 18;
    const int pn = idx & (P_ * N_ - 1);
    float carry = 0.f;
#pragma unroll 4
    for (int c = 0; c < NCHUNK; ++c) {
        const size_t off = (size_t)((b * NCHUNK + c) * H_ + h) * (P_ * N_) + pn;
        g_init[off] = carry;
        carry = fmaf(g_adec[(b * NCHUNK + c) * H_ + h], carry, g_state[off]);
    }
}

__global__ __launch_bounds__(256, 2)
void chunk_y_kernel(const float* __restrict__ A_log)
{
    const int c = blockIdx.x, h = blockIdx.y, b = blockIdx.z;
    extern __shared__ __align__(1024) char sm[];
    const uint32_t sb = s2u(sm);
    float* slc = (float*)(sm + OFF_LC);
    float* sdt = (float*)(sm + OFF_DT);
    float* scum = (float*)(sm + OFF_CUM);
    const int tid = threadIdx.x;
    const int bl0 = b * L_ + c * TCH;
    const float A = -expf(A_log[h]);

    if (tid < 128) {
        const float d = g_dt[(size_t)(bl0 + tid) * H_ + h];
        sdt[tid] = d;
        slc[tid] = d * A;
    }
    __syncthreads();
    for (int off = 1; off < 128; off <<= 1) {
        float v = 0.f;
        if (tid < 128 && tid >= off) v = slc[tid - off];
        __syncthreads();
        if (tid < 128 && tid >= off) slc[tid] += v;
        __syncthreads();
    }
    if (tid < 128) scum[tid] = fast_exp(slc[tid]);

    // stage 1: A = C exact fp16; B = Sini split (2-product)
    for (int idx = tid; idx < 128 * 128; idx += 256) {
        const int t = idx >> 7, n = idx & 127;
        *(__half*)(sm + OFF_AH + t * 272 + n * 2) =
            g_conv_h[(size_t)(bl0 + t) * CONV_DIM + INTER + N_ + n];
    }
    const float* Sini = g_init + (size_t)((b * NCHUNK + c) * H_ + h) * (N_ * P_);
    for (int idx = tid; idx < 128 * 64; idx += 256) {
        const int n = idx >> 6, p = idx & 63;
        split2h(Sini[n * P_ + p], (__half*)(sm + OFF_BH + p * 272 + n * 2),
                                   (__half*)(sm + OFF_BL + p * 272 + n * 2));
    }
    __syncthreads();

    const int wid = tid >> 5, lane = tid & 31;
    const int wm = (wid & 3) * 32;
    const int wn = (wid >> 2) * 32;
    const uint32_t laneoff = (uint32_t)((lane >> 2) * 272 + (lane & 3) * 4);

    float acc[2][4][4];
#pragma unroll
    for (int i = 0; i < 2; ++i)
#pragma unroll
        for (int j = 0; j < 4; ++j)
#pragma unroll
            for (int q = 0; q < 4; ++q) acc[i][j][q] = 0.f;

#pragma unroll
    for (int k0 = 0; k0 < 128; k0 += 16) {
        const uint32_t ko = (uint32_t)(k0 * 2) + laneoff;
        uint32_t ah[2][4];
#pragma unroll
        for (int mf = 0; mf < 2; ++mf)
            ldfragA(ah[mf], sb + OFF_AH + (uint32_t)((wm + mf * 16) * 272) + ko);
        uint32_t bh[4][2], bl[4][2];
#pragma unroll
        for (int nf = 0; nf < 4; ++nf) {
            const uint32_t pb = (uint32_t)((wn + nf * 8) * 272) + ko;
            ldfragB(bh[nf], sb + OFF_BH + pb);
            ldfragB(bl[nf], sb + OFF_BL + pb);
        }
#pragma unroll
        for (int mf = 0; mf < 2; ++mf)
#pragma unroll
            for (int nf = 0; nf < 4; ++nf) {
                mma16816h(acc[mf][nf], ah[mf], bh[nf]);
                mma16816h(acc[mf][nf], ah[mf], bl[nf]);
            }
    }
    __syncthreads();

    const int g = lane >> 2;
#pragma unroll
    for (int mf = 0; mf < 2; ++mf) {
        const float s0 = scum[wm + mf * 16 + g];
        const float s1 = scum[wm + mf * 16 + g + 8];
#pragma unroll
        for (int nf = 0; nf < 4; ++nf) {
            acc[mf][nf][0] *= s0; acc[mf][nf][1] *= s0;
            acc[mf][nf][2] *= s1; acc[mf][nf][3] *= s1;
        }
    }

    // stage 2: A = Gamma.*G rounded fp16; B = X exact fp16 (single product)
    const float* Gp = g_G + (size_t)(b * NCHUNK + c) * (TCH * TCH);
    for (int idx = tid; idx < 128 * 128; idx += 256) {
        const int t = idx >> 7, s = idx & 127;
        float val = 0.f;
        if (s <= t) val = fast_exp(slc[t] - slc[s]) * sdt[s] * Gp[idx];
        *(__half*)(sm + OFF_AH + t * 272 + s * 2) = __float2half_rn(val);
    }
    for (int idx = tid; idx < 128 * 64; idx += 256) {
        const int s = idx >> 6, p = idx & 63;
        *(__half*)(sm + OFF_BH + p * 272 + s * 2) =
            g_conv_h[(size_t)(bl0 + s) * CONV_DIM + h * P_ + p];
    }
    __syncthreads();

#pragma unroll
    for (int k0 = 0; k0 < 128; k0 += 16) {
        const uint32_t ko = (uint32_t)(k0 * 2) + laneoff;
        uint32_t ah[2][4];
#pragma unroll
        for (int mf = 0; mf < 2; ++mf)
            ldfragA(ah[mf], sb + OFF_AH + (uint32_t)((wm + mf * 16) * 272) + ko);
        uint32_t bh[4][2];
#pragma unroll
        for (int nf = 0; nf < 4; ++nf)
            ldfragB(bh[nf], sb + OFF_BH + (uint32_t)((wn + nf * 8) * 272) + ko);
#pragma unroll
        for (int mf = 0; mf < 2; ++mf)
#pragma unroll
            for (int nf = 0; nf < 4; ++nf)
                mma16816h(acc[mf][nf], ah[mf], bh[nf]);
    }

    const int t2 = (lane & 3) * 2;
#pragma unroll
    for (int mf = 0; mf < 2; ++mf)
#pragma unroll
        for (int nf = 0; nf < 4; ++nf) {
            const int row0 = wm + mf * 16 + g;
            const int col = h * P_ + wn + nf * 8 + t2;
            *(__half2*)(g_y_h + (size_t)(bl0 + row0) * INTER + col) =
                __floats2half2_rn(acc[mf][nf][0], acc[mf][nf][1]);
            *(__half2*)(g_y_h + (size_t)(bl0 + row0 + 8) * INTER + col) =
                __floats2half2_rn(acc[mf][nf][2], acc[mf][nf][3]);
        }
}

// ---------------- y + D*xs, gate*silu, RMSNorm, fp16 round ------------------
__global__ __launch_bounds__(256)
void gate_rms_kernel(const float* __restrict__ D_param, const float* __restrict__ norm_w)
{
    const int bl = blockIdx.x;
    const int tid = threadIdx.x;
    const __half2* yrow = (const __half2*)(g_y_h + (size_t)bl * INTER);
    const __half2* grow = (const __half2*)(g_proj_h + (size_t)bl * PROJ_PAD);
    const __half2* xrow = (const __half2*)(g_conv_h + (size_t)bl * CONV_DIM);

    float vals[8];
    float ss = 0.f;
#pragma unroll
    for (int r = 0; r < 2; ++r) {
        const int i = tid * 4 + r * 1024;
        const float2 ya = __half22float2(yrow[i / 2]);
        const float2 yb = __half22float2(yrow[i / 2 + 1]);
        const float2 ga = __half22float2(grow[i / 2]);
        const float2 gb = __half22float2(grow[i / 2 + 1]);
        const float2 xa = __half22float2(xrow[i / 2]);
        const float2 xb = __half22float2(xrow[i / 2 + 1]);
        const float d = D_param[i >> 6];
        float g0 = (ya.x + d * xa.x) * siluf(ga.x);
        float g1 = (ya.y + d * xa.y) * siluf(ga.y);
        float g2 = (yb.x + d * xb.x) * siluf(gb.x);
        float g3 = (yb.y + d * xb.y) * siluf(gb.y);
        vals[r * 4 + 0] = g0; vals[r * 4 + 1] = g1;
        vals[r * 4 + 2] = g2; vals[r * 4 + 3] = g3;
        ss += g0 * g0 + g1 * g1 + g2 * g2 + g3 * g3;
    }

    __shared__ float red[8];
    __shared__ float stot;
#pragma unroll
    for (int o = 16; o; o >>= 1) ss += __shfl_xor_sync(0xffffffffu, ss, o);
    if ((tid & 31) == 0) red[tid >> 5] = ss;
    __syncthreads();
    if (tid == 0) {
        float v = 0.f;
#pragma unroll
        for (int i = 0; i < 8; ++i) v += red[i];
        stot = rsqrtf(v * (1.f / (float)INTER) + EPSV);
    }
    __syncthreads();
    const float rs = stot;

    __half* gh = g_gate_h + (size_t)bl * INTER;
#pragma unroll
    for (int r = 0; r < 2; ++r) {
        const int i = tid * 4 + r * 1024;
        const float4 nw = *(const float4*)(norm_w + i);
        gh[i + 0] = __float2half_rn(vals[r * 4 + 0] * rs * nw.x);
        gh[i + 1] = __float2half_rn(vals[r * 4 + 1] * rs * nw.y);
        gh[i + 2] = __float2half_rn(vals[r * 4 + 2] * rs * nw.z);
        gh[i + 3] = __float2half_rn(vals[r * 4 + 3] * rs * nw.w);
    }
}

// ---------------- launch -----------------------------------------------------
extern "C" void kernel_launch(void* const* d_in, const int* in_sizes, int n_in,
                              void* d_out, int out_size)
{
    const float* hs      = (const float*)d_in[0];
    const float* W_in    = (const float*)d_in[1];
    const float* conv_w  = (const float*)d_in[2];
    const float* conv_b  = (const float*)d_in[3];
    const float* dt_bias = (const float*)d_in[4];
    const float* A_log   = (const float*)d_in[5];
    const float* D_param = (const float*)d_in[6];
    const float* norm_w  = (const float*)d_in[7];
    const float* W_out   = (const float*)d_in[8];
    float* out = (float*)d_out;

    cudaFuncSetAttribute(gemm_mma1<0>, cudaFuncAttributeMaxDynamicSharedMemorySize,
                         GEMM_SMEM_BYTES);
    cudaFuncSetAttribute(gemm_mma1<1>, cudaFuncAttributeMaxDynamicSharedMemorySize,
                         GEMM_SMEM_BYTES);
    cudaFuncSetAttribute(chunk_G_kernel, cudaFuncAttributeMaxDynamicSharedMemorySize,
                         G_SMEM);
    cudaFuncSetAttribute(chunk_state_kernel, cudaFuncAttributeMaxDynamicSharedMemorySize,
                         PH_SMEM);
    cudaFuncSetAttribute(chunk_y_kernel, cudaFuncAttributeMaxDynamicSharedMemorySize,
                         PH_SMEM);

    void *pproj = nullptr;
    void *phh = nullptr, *pwh = nullptr, *pgh = nullptr, *poh = nullptr;
    cudaGetSymbolAddress(&pproj, g_proj_h);
    cudaGetSymbolAddress(&phh, g_hs_h);
    cudaGetSymbolAddress(&pwh, g_win_h);
    cudaGetSymbolAddress(&pgh, g_gate_h);
    cudaGetSymbolAddress(&poh, g_wo_h);

    // 0) conversions
    {
        const int n4 = B_ * L_ * DM / 4;
        round_h_kernel<<<(n4 + 255) / 256, 256>>>(hs, (__half*)phh, n4);
    }
    round_pad_h_kernel<<<(PROJ_PAD * DM / 4 + 255) / 256, 256>>>(W_in, (__half*)pwh);
    {
        const int n4 = DM * INTER / 4;
        round_h_kernel<<<(n4 + 255) / 256, 256>>>(W_out, (__half*)poh, n4);
    }

    // 1) proj = hs @ W_in^T  (fp16 output)
    {
        dim3 grid(PROJ_PAD / 128, (B_ * L_) / 128);
        gemm_mma1<1><<<grid, 256, GEMM_SMEM_BYTES>>>(
            (const __half*)phh, (const __half*)pwh, pproj, DM, PROJ_PAD);
    }
    // 2) conv + silu + dt
    conv_dt_kernel<<<B_ * L_, 256>>>(conv_w, conv_b, dt_bias);
    // 3) SSD chunked scan
    chunk_G_kernel<<<dim3(NCHUNK, B_), 256, G_SMEM>>>();
    chunk_state_kernel<<<dim3(NCHUNK, H_, B_), 256, PH_SMEM>>>(A_log);
    scan_combine<<<(B_ * H_ * P_ * N_) / 256, 256>>>();
    chunk_y_kernel<<<dim3(NCHUNK, H_, B_), 256, PH_SMEM>>>(A_log);
    // 4) gate + rmsnorm + fp16 round
    gate_rms_kernel<<<B_ * L_, 256>>>(D_param, norm_w);
    // 5) out = g @ W_out^T  (fp32 output)
    {
        dim3 grid(DM / 128, (B_ * L_) / 128);
        gemm_mma1<0><<<grid, 256, GEMM_SMEM_BYTES>>>(
            (const __half*)pgh, (const __half*)poh, out, INTER, DM);
    }
}

// round 16
// speedup vs baseline: 2.4850x; 1.0228x over previous
#include <cuda_runtime.h>
#include <cuda_bf16.h>
#include <cuda_fp16.h>
#include <cstdint>
#include <cstddef>

#define B_ 2
#define L_ 4096
#define DM 2048
#define H_ 32
#define P_ 64
#define N_ 128
#define INTER 2048
#define CONV_DIM 2304
#define PROJ 4384
#define PROJ_PAD 4480
#define EPSV 1e-5f
#define NCHUNK 32
#define TCH 128

// ---------------- scratch (__device__ globals; no allocations allowed) ------
__device__ __half g_proj_h[(size_t)B_ * L_ * PROJ_PAD];
__device__ __half g_conv_h[(size_t)B_ * L_ * CONV_DIM];
__device__ __half g_y_h[(size_t)B_ * L_ * INTER];
__device__ float g_dt[B_ * L_ * H_];
__device__ __half g_G_h[(size_t)B_ * NCHUNK * TCH * TCH];
__device__ float g_state[(size_t)B_ * NCHUNK * H_ * N_ * P_];
__device__ float g_init[(size_t)B_ * NCHUNK * H_ * N_ * P_];
__device__ float g_adec[B_ * NCHUNK * H_];
// fp16 GEMM operands
__device__ __half g_hs_h[(size_t)B_ * L_ * DM];
__device__ __half g_win_h[(size_t)PROJ_PAD * DM];
__device__ __half g_gate_h[(size_t)B_ * L_ * INTER];
__device__ __half g_wo_h[(size_t)DM * INTER];

// ---------------- helpers ----------------------------------------------------
__device__ __forceinline__ float siluf(float x) {
    return x * (1.f / (1.f + expf(-x)));
}
__device__ __forceinline__ float softplusf(float x) {
    return (x > 20.f) ? x : log1pf(expf(x));
}
__device__ __forceinline__ uint32_t s2u(const void* p) {
    return (uint32_t)__cvta_generic_to_shared(p);
}
__device__ __forceinline__ void cp16(uint32_t saddr, const void* g) {
    asm volatile("cp.async.cg.shared.global [%0], [%1], 16;\n" :: "r"(saddr), "l"(g));
}
__device__ __forceinline__ void cp_commit() {
    asm volatile("cp.async.commit_group;\n" ::: "memory");
}
__device__ __forceinline__ void cp_wait1() {
    asm volatile("cp.async.wait_group 1;\n" ::: "memory");
}
__device__ __forceinline__ uint32_t lds32(uint32_t a) {
    uint32_t v;
    asm volatile("ld.shared.b32 %0, [%1];" : "=r"(v) : "r"(a));
    return v;
}
// e^d for d <= 0, rel err ~3e-7, no MUFU
__device__ __forceinline__ float fast_exp(float d) {
    float y = d * 1.44269504f;
    if (y < -126.f) return 0.f;
    float n = floorf(y);
    float f = y - n;
    float p = 1.33336498e-3f;
    p = fmaf(p, f, 9.61011667e-3f);
    p = fmaf(p, f, 5.55036329e-2f);
    p = fmaf(p, f, 2.40226507e-1f);
    p = fmaf(p, f, 6.93147182e-1f);
    p = fmaf(p, f, 1.0f);
    return p * __int_as_float(((int)n + 127) << 23);
}

// ---------------- warp-level HMMA plumbing ----------------------------------
__device__ __forceinline__ void ldm_x4(uint32_t* r, uint32_t addr) {
    asm volatile("ldmatrix.sync.aligned.m8n8.x4.shared.b16 {%0,%1,%2,%3}, [%4];"
                 : "=r"(r[0]), "=r"(r[1]), "=r"(r[2]), "=r"(r[3]) : "r"(addr));
}
__device__ __forceinline__ void mma16816h(float* d, const uint32_t* a, const uint32_t* b) {
    asm volatile(
        "mma.sync.aligned.m16n8k16.row.col.f32.f16.f16.f32 "
        "{%0,%1,%2,%3}, {%4,%5,%6,%7}, {%8,%9}, {%0,%1,%2,%3};"
        : "+f"(d[0]), "+f"(d[1]), "+f"(d[2]), "+f"(d[3])
        : "r"(a[0]), "r"(a[1]), "r"(a[2]), "r"(a[3]), "r"(b[0]), "r"(b[1]));
}
// LDS-based fragment loads from 272B-pitch row-major fp16 tiles
__device__ __forceinline__ void ldfragA(uint32_t r[4], uint32_t base) {
    r[0] = lds32(base);        r[1] = lds32(base + 2176);
    r[2] = lds32(base + 16);   r[3] = lds32(base + 2192);
}
__device__ __forceinline__ void ldfragB(uint32_t r[2], uint32_t base) {
    r[0] = lds32(base);        r[1] = lds32(base + 16);
}
__device__ __forceinline__ void split2h(float v, __half* hp, __half* lp) {
    __half h = __float2half_rn(v);
    *hp = h;
    *lp = __float2half_rn(v - __half2float(h));
}

// ---------------- single-product fp16 GEMM, BK=64, 3-stage, 2 CTAs/SM -------
// CTA tile 128x128, 128B SW128 rows, 8 warps (warp tile 64x32), 1 barrier/chunk.
#define STAGE_BYTES 32768
#define TEN_BYTES 16384
#define GEMM_SMEM_BYTES (3 * STAGE_BYTES)

template <int HALF_OUT>
__global__ __launch_bounds__(256, 2)
void gemm_mma1(const __half* __restrict__ Ah, const __half* __restrict__ Bh,
               void* __restrict__ Cv, int K, int ldc)
{
    extern __shared__ __align__(1024) char smem[];
    const uint32_t sb = s2u(smem);
    const int tid = threadIdx.x;
    const int wid = tid >> 5;
    const int lane = tid & 31;
    const int bn = blockIdx.x * 128;
    const int bm = blockIdx.y * 128;
    const int chunks = K >> 6;

    const int wm = (wid & 1) * 64;
    const int wn = (wid >> 1) * 32;

    const int rA = wm + (lane & 15);
    const uint32_t selA = (lane & 16) ? 16u : 0u;
    const uint32_t xorA = (uint32_t)((rA & 7) * 16);
    uint32_t rowOffA[4];
#pragma unroll
    for (int mf = 0; mf < 4; ++mf) rowOffA[mf] = (uint32_t)((rA + mf * 16) * 128);

    const int rB = wn + (lane & 7) + ((lane & 16) ? 8 : 0);
    const uint32_t selB = (lane & 8) ? 16u : 0u;
    const uint32_t xorB = (uint32_t)((rB & 7) * 16);
    uint32_t rowOffB[2];
#pragma unroll
    for (int nb = 0; nb < 2; ++nb) rowOffB[nb] = (uint32_t)((rB + nb * 16) * 128);

    // per stage: 2 tensors x 1024 x 16B chunks; 8 cp16 per thread
    auto issue = [&](int c) {
        const int s = c % 3;
        const uint32_t base = sb + (uint32_t)s * STAGE_BYTES;
        const int k0 = c << 6;
#pragma unroll
        for (int q = 0; q < 4; ++q) {
            const int cc = q * 256 + tid;       // 0..1023
            const int row = cc >> 3;
            const int seg = cc & 7;
            const uint32_t dst =
                (uint32_t)(row * 128 + ((seg * 16) ^ ((row & 7) * 16)));
            cp16(base + dst, Ah + (size_t)(bm + row) * K + k0 + seg * 8);
            cp16(base + TEN_BYTES + dst, Bh + (size_t)(bn + row) * K + k0 + seg * 8);
        }
    };

    float acc[4][4][4];
#pragma unroll
    for (int i = 0; i < 4; ++i)
#pragma unroll
        for (int j = 0; j < 4; ++j)
#pragma unroll
            for (int q = 0; q < 4; ++q) acc[i][j][q] = 0.f;

    issue(0); cp_commit();
    issue(1); cp_commit();

    for (int c = 0; c < chunks; ++c) {
        cp_wait1();           // <=1 group pending -> stage c complete
        __syncthreads();      // visible to all; prior readers of target stage done
        if (c + 2 < chunks) issue(c + 2);
        cp_commit();

        const uint32_t base = sb + (uint32_t)(c % 3) * STAGE_BYTES;
        const uint32_t bAh = base;
        const uint32_t bBh = base + TEN_BYTES;

#pragma unroll
        for (int ks = 0; ks < 4; ++ks) {
            const uint32_t cA = ((uint32_t)(ks * 32) + selA) ^ xorA;
            const uint32_t cB = ((uint32_t)(ks * 32) + selB) ^ xorB;
            uint32_t ah[4][4];
#pragma unroll
            for (int mf = 0; mf < 4; ++mf)
                ldm_x4(ah[mf], bAh + rowOffA[mf] + cA);
            uint32_t bh[4][2];
#pragma unroll
            for (int nb = 0; nb < 2; ++nb) {
                uint32_t t[4];
                ldm_x4(t, bBh + rowOffB[nb] + cB);
                bh[nb * 2][0] = t[0]; bh[nb * 2][1] = t[1];
                bh[nb * 2 + 1][0] = t[2]; bh[nb * 2 + 1][1] = t[3];
            }
#pragma unroll
            for (int mf = 0; mf < 4; ++mf)
#pragma unroll
                for (int nf = 0; nf < 4; ++nf)
                    mma16816h(acc[mf][nf], ah[mf], bh[nf]);
        }
    }

    const int g = lane >> 2;
    const int t2 = (lane & 3) * 2;
#pragma unroll
    for (int mf = 0; mf < 4; ++mf) {
#pragma unroll
        for (int nf = 0; nf < 4; ++nf) {
            const int col = bn + wn + nf * 8 + t2;
            const int row0 = bm + wm + mf * 16 + g;
            if (HALF_OUT) {
                __half* C = (__half*)Cv;
                *(__half2*)(C + (size_t)row0 * ldc + col) =
                    __floats2half2_rn(acc[mf][nf][0], acc[mf][nf][1]);
                *(__half2*)(C + (size_t)(row0 + 8) * ldc + col) =
                    __floats2half2_rn(acc[mf][nf][2], acc[mf][nf][3]);
            } else {
                float* C = (float*)Cv;
                *(float2*)(C + (size_t)row0 * ldc + col) =
                    make_float2(acc[mf][nf][0], acc[mf][nf][1]);
                *(float2*)(C + (size_t)(row0 + 8) * ldc + col) =
                    make_float2(acc[mf][nf][2], acc[mf][nf][3]);
            }
        }
    }
}

// ---------------- all fp32 -> fp16 conversions in one kernel -----------------
#define HS4 (B_ * L_ * DM / 4)
#define WI4 (PROJ_PAD * DM / 4)
#define WO4 (DM * INTER / 4)
__global__ __launch_bounds__(256)
void convert_all_kernel(const float* __restrict__ hs, const float* __restrict__ W_in,
                        const float* __restrict__ W_out)
{
    const int i = blockIdx.x * 256 + threadIdx.x;
    const float4 z4 = make_float4(0.f, 0.f, 0.f, 0.f);
    float4 v;
    __half* dst;
    int o;
    if (i < HS4) {
        v = ((const float4*)hs)[i];
        dst = g_hs_h; o = i;
    } else if (i < HS4 + WI4) {
        o = i - HS4;
        const int row = o / (DM / 4);
        v = (row < PROJ) ? ((const float4*)W_in)[o] : z4;
        dst = g_win_h;
    } else if (i < HS4 + WI4 + WO4) {
        o = i - HS4 - WI4;
        v = ((const float4*)W_out)[o];
        dst = g_wo_h;
    } else {
        return;
    }
    *(__half2*)(dst + o * 4) = __floats2half2_rn(v.x, v.y);
    *(__half2*)(dst + o * 4 + 2) = __floats2half2_rn(v.z, v.w);
}

// ---------------- depthwise conv (K=4) + bias + SiLU -> fp16, plus dt -------
__global__ __launch_bounds__(256)
void conv_dt_kernel(const float* __restrict__ conv_w, const float* __restrict__ conv_b,
                    const float* __restrict__ dt_bias)
{
    const int bl = blockIdx.x;
    const int tid = threadIdx.x;
    const int l = bl & (L_ - 1);
    const __half* base0 = g_proj_h + (size_t)bl * PROJ_PAD + INTER;
#pragma unroll
    for (int it = 0; it < 9; ++it) {
        const int c = it * 256 + tid;
        float acc = conv_b[c];
        const float* w = conv_w + c * 4;
#pragma unroll
        for (int j = 0; j < 4; ++j) {
            const int ll = l - 3 + j;
            if (ll >= 0)
                acc = fmaf(__half2float(base0[(ptrdiff_t)(j - 3) * PROJ_PAD + c]), w[j], acc);
        }
        g_conv_h[(size_t)bl * CONV_DIM + c] = __float2half_rn(siluf(acc));
    }
    if (tid < H_) {
        const float x = __half2float(g_proj_h[(size_t)bl * PROJ_PAD + INTER + CONV_DIM + tid])
                        + dt_bias[tid];
        g_dt[bl * H_ + tid] = softplusf(x);
    }
}

// ---------------- SSD chunked scan ------------------------------------------
#define G_SMEM (2 * 128 * 129 * 4)
__global__ __launch_bounds__(256, 1)
void chunk_G_kernel()
{
    const int c = blockIdx.x, b = blockIdx.y;
    extern __shared__ float sg[];
    float* sC = sg;
    float* sB = sg + 128 * 129;
    const int tid = threadIdx.x;
    const int bl0 = b * L_ + c * TCH;
    for (int idx = tid; idx < 128 * 128; idx += 256) {
        const int t = idx >> 7, n = idx & 127;
        const __half* row = g_conv_h + (size_t)(bl0 + t) * CONV_DIM + INTER;
        sB[t * 129 + n] = __half2float(row[n]);
        sC[t * 129 + n] = __half2float(row[N_ + n]);
    }
    __syncthreads();
    const int tt = (tid >> 4) * 8, ss = (tid & 15) * 8;
    float acc[8][8];
#pragma unroll
    for (int i = 0; i < 8; ++i)
#pragma unroll
        for (int j = 0; j < 8; ++j) acc[i][j] = 0.f;
    for (int k = 0; k < 128; ++k) {
        float rc[8], rb[8];
#pragma unroll
        for (int i = 0; i < 8; ++i) rc[i] = sC[(tt + i) * 129 + k];
#pragma unroll
        for (int j = 0; j < 8; ++j) rb[j] = sB[(ss + j) * 129 + k];
#pragma unroll
        for (int i = 0; i < 8; ++i)
#pragma unroll
            for (int j = 0; j < 8; ++j) acc[i][j] = fmaf(rc[i], rb[j], acc[i][j]);
    }
    __half* Gp = g_G_h + (size_t)(b * NCHUNK + c) * (TCH * TCH);
#pragma unroll
    for (int i = 0; i < 8; ++i)
#pragma unroll
        for (int j = 0; j < 8; ++j)
            Gp[(tt + i) * 128 + ss + j] = __float2half_rn(acc[i][j]);
}

// smem offsets (272B pitch rows)
#define OFF_AH 0
#define OFF_BH 34816
#define OFF_BL 52224
#define OFF_LC 69632
#define OFF_DT 70144
#define OFF_CUM 70656
#define PH_SMEM 71168

__global__ __launch_bounds__(256, 2)
void chunk_state_kernel(const float* __restrict__ A_log)
{
    const int c = blockIdx.x, h = blockIdx.y, b = blockIdx.z;
    extern __shared__ __align__(1024) char sm[];
    const uint32_t sb = s2u(sm);
    float* slc = (float*)(sm + OFF_LC);
    float* sdt = (float*)(sm + OFF_DT);
    const int tid = threadIdx.x;
    const int bl0 = b * L_ + c * TCH;
    const float A = -expf(A_log[h]);

    if (tid < 128) {
        const float d = g_dt[(size_t)(bl0 + tid) * H_ + h];
        sdt[tid] = d;
        slc[tid] = d * A;
    }
    __syncthreads();
    for (int off = 1; off < 128; off <<= 1) {
        float v = 0.f;
        if (tid < 128 && tid >= off) v = slc[tid - off];
        __syncthreads();
        if (tid < 128 && tid >= off) slc[tid] += v;
        __syncthreads();
    }
    const float lcT = slc[127];
    if (tid == 0) g_adec[(b * NCHUNK + c) * H_ + h] = fast_exp(lcT);

    for (int idx = tid; idx < 128 * 128; idx += 256) {
        const int s = idx >> 7, n = idx & 127;
        const float w = fast_exp(lcT - slc[s]) * sdt[s];
        const float v = __half2float(g_conv_h[(size_t)(bl0 + s) * CONV_DIM + INTER + n]) * w;
        *(__half*)(sm + OFF_AH + n * 272 + s * 2) = __float2half_rn(v);
    }
    for (int idx = tid; idx < 128 * 64; idx += 256) {
        const int s = idx >> 6, p = idx & 63;
        *(__half*)(sm + OFF_BH + p * 272 + s * 2) =
            g_conv_h[(size_t)(bl0 + s) * CONV_DIM + h * P_ + p];
    }
    __syncthreads();

    const int wid = tid >> 5, lane = tid & 31;
    const int wm = (wid & 3) * 32;
    const int wn = (wid >> 2) * 32;
    const uint32_t laneoff = (uint32_t)((lane >> 2) * 272 + (lane & 3) * 4);

    float acc[2][4][4];
#pragma unroll
    for (int i = 0; i < 2; ++i)
#pragma unroll
        for (int j = 0; j < 4; ++j)
#pragma unroll
            for (int q = 0; q < 4; ++q) acc[i][j][q] = 0.f;

#pragma unroll
    for (int k0 = 0; k0 < 128; k0 += 16) {
        const uint32_t ko = (uint32_t)(k0 * 2) + laneoff;
        uint32_t ah[2][4];
#pragma unroll
        for (int mf = 0; mf < 2; ++mf)
            ldfragA(ah[mf], sb + OFF_AH + (uint32_t)((wm + mf * 16) * 272) + ko);
        uint32_t bh[4][2];
#pragma unroll
        for (int nf = 0; nf < 4; ++nf)
            ldfragB(bh[nf], sb + OFF_BH + (uint32_t)((wn + nf * 8) * 272) + ko);
#pragma unroll
        for (int mf = 0; mf < 2; ++mf)
#pragma unroll
            for (int nf = 0; nf < 4; ++nf)
                mma16816h(acc[mf][nf], ah[mf], bh[nf]);
    }

    float* st = g_state + (size_t)((b * NCHUNK + c) * H_ + h) * (N_ * P_);
    const int g = lane >> 2;
    const int t2 = (lane & 3) * 2;
#pragma unroll
    for (int mf = 0; mf < 2; ++mf)
#pragma unroll
        for (int nf = 0; nf < 4; ++nf) {
            const int n0 = wm + mf * 16 + g;
            const int col = wn + nf * 8 + t2;
            *(float2*)(st + n0 * P_ + col) = make_float2(acc[mf][nf][0], acc[mf][nf][1]);
            *(float2*)(st + (n0 + 8) * P_ + col) = make_float2(acc[mf][nf][2], acc[mf][nf][3]);
        }
}

__global__ __launch_bounds__(256)
void scan_combine()
{
    const int idx = blockIdx.x * 256 + threadIdx.x;
    if (idx >= B_ * H_ * P_ * N_) return;
    const int h = (idx >> 13) & (H_ - 1);
    const int b = idx >> 18;
    const int pn = idx & (P_ * N_ - 1);
    float carry = 0.f;
#pragma unroll 4
    for (int c = 0; c < NCHUNK; ++c) {
        const size_t off = (size_t)((b * NCHUNK + c) * H_ + h) * (P_ * N_) + pn;
        g_init[off] = carry;
        carry = fmaf(g_adec[(b * NCHUNK + c) * H_ + h], carry, g_state[off]);
    }
}

__global__ __launch_bounds__(256, 2)
void chunk_y_kernel(const float* __restrict__ A_log)
{
    const int c = blockIdx.x, h = blockIdx.y, b = blockIdx.z;
    extern __shared__ __align__(1024) char sm[];
    const uint32_t sb = s2u(sm);
    float* slc = (float*)(sm + OFF_LC);
    float* sdt = (float*)(sm + OFF_DT);
    float* scum = (float*)(sm + OFF_CUM);
    const int tid = threadIdx.x;
    const int bl0 = b * L_ + c * TCH;
    const float A = -expf(A_log[h]);

    if (tid < 128) {
        const float d = g_dt[(size_t)(bl0 + tid) * H_ + h];
        sdt[tid] = d;
        slc[tid] = d * A;
    }
    __syncthreads();
    for (int off = 1; off < 128; off <<= 1) {
        float v = 0.f;
        if (tid < 128 && tid >= off) v = slc[tid - off];
        __syncthreads();
        if (tid < 128 && tid >= off) slc[tid] += v;
        __syncthreads();
    }
    if (tid < 128) scum[tid] = fast_exp(slc[tid]);

    // stage 1: A = C exact fp16; B = Sini split (2-product)
    for (int idx = tid; idx < 128 * 128; idx += 256) {
        const int t = idx >> 7, n = idx & 127;
        *(__half*)(sm + OFF_AH + t * 272 + n * 2) =
            g_conv_h[(size_t)(bl0 + t) * CONV_DIM + INTER + N_ + n];
    }
    const float* Sini = g_init + (size_t)((b * NCHUNK + c) * H_ + h) * (N_ * P_);
    for (int idx = tid; idx < 128 * 64; idx += 256) {
        const int n = idx >> 6, p = idx & 63;
        split2h(Sini[n * P_ + p], (__half*)(sm + OFF_BH + p * 272 + n * 2),
                                   (__half*)(sm + OFF_BL + p * 272 + n * 2));
    }
    __syncthreads();

    const int wid = tid >> 5, lane = tid & 31;
    const int wm = (wid & 3) * 32;
    const int wn = (wid >> 2) * 32;
    const uint32_t laneoff = (uint32_t)((lane >> 2) * 272 + (lane & 3) * 4);

    float acc[2][4][4];
#pragma unroll
    for (int i = 0; i < 2; ++i)
#pragma unroll
        for (int j = 0; j < 4; ++j)
#pragma unroll
            for (int q = 0; q < 4; ++q) acc[i][j][q] = 0.f;

#pragma unroll
    for (int k0 = 0; k0 < 128; k0 += 16) {
        const uint32_t ko = (uint32_t)(k0 * 2) + laneoff;
        uint32_t ah[2][4];
#pragma unroll
        for (int mf = 0; mf < 2; ++mf)
            ldfragA(ah[mf], sb + OFF_AH + (uint32_t)((wm + mf * 16) * 272) + ko);
        uint32_t bh[4][2], bl[4][2];
#pragma unroll
        for (int nf = 0; nf < 4; ++nf) {
            const uint32_t pb = (uint32_t)((wn + nf * 8) * 272) + ko;
            ldfragB(bh[nf], sb + OFF_BH + pb);
            ldfragB(bl[nf], sb + OFF_BL + pb);
        }
#pragma unroll
        for (int mf = 0; mf < 2; ++mf)
#pragma unroll
            for (int nf = 0; nf < 4; ++nf) {
                mma16816h(acc[mf][nf], ah[mf], bh[nf]);
                mma16816h(acc[mf][nf], ah[mf], bl[nf]);
            }
    }
    __syncthreads();

    const int g = lane >> 2;
#pragma unroll
    for (int mf = 0; mf < 2; ++mf) {
        const float s0 = scum[wm + mf * 16 + g];
        const float s1 = scum[wm + mf * 16 + g + 8];
#pragma unroll
        for (int nf = 0; nf < 4; ++nf) {
            acc[mf][nf][0] *= s0; acc[mf][nf][1] *= s0;
            acc[mf][nf][2] *= s1; acc[mf][nf][3] *= s1;
        }
    }

    // stage 2: A = Gamma.*G rounded fp16; B = X exact fp16 (single product)
    const __half* Gp = g_G_h + (size_t)(b * NCHUNK + c) * (TCH * TCH);
    for (int idx = tid; idx < 128 * 128; idx += 256) {
        const int t = idx >> 7, s = idx & 127;
        float val = 0.f;
        if (s <= t)
            val = fast_exp(slc[t] - slc[s]) * sdt[s] * __half2float(Gp[idx]);
        *(__half*)(sm + OFF_AH + t * 272 + s * 2) = __float2half_rn(val);
    }
    for (int idx = tid; idx < 128 * 64; idx += 256) {
        const int s = idx >> 6, p = idx & 63;
        *(__half*)(sm + OFF_BH + p * 272 + s * 2) =
            g_conv_h[(size_t)(bl0 + s) * CONV_DIM + h * P_ + p];
    }
    __syncthreads();

#pragma unroll
    for (int k0 = 0; k0 < 128; k0 += 16) {
        const uint32_t ko = (uint32_t)(k0 * 2) + laneoff;
        uint32_t ah[2][4];
#pragma unroll
        for (int mf = 0; mf < 2; ++mf)
            ldfragA(ah[mf], sb + OFF_AH + (uint32_t)((wm + mf * 16) * 272) + ko);
        uint32_t bh[4][2];
#pragma unroll
        for (int nf = 0; nf < 4; ++nf)
            ldfragB(bh[nf], sb + OFF_BH + (uint32_t)((wn + nf * 8) * 272) + ko);
#pragma unroll
        for (int mf = 0; mf < 2; ++mf)
#pragma unroll
            for (int nf = 0; nf < 4; ++nf)
                mma16816h(acc[mf][nf], ah[mf], bh[nf]);
    }

    const int t2 = (lane & 3) * 2;
#pragma unroll
    for (int mf = 0; mf < 2; ++mf)
#pragma unroll
        for (int nf = 0; nf < 4; ++nf) {
            const int row0 = wm + mf * 16 + g;
            const int col = h * P_ + wn + nf * 8 + t2;
            *(__half2*)(g_y_h + (size_t)(bl0 + row0) * INTER + col) =
                __floats2half2_rn(acc[mf][nf][0], acc[mf][nf][1]);
            *(__half2*)(g_y_h + (size_t)(bl0 + row0 + 8) * INTER + col) =
                __floats2half2_rn(acc[mf][nf][2], acc[mf][nf][3]);
        }
}

// ---------------- y + D*xs, gate*silu, RMSNorm, fp16 round ------------------
__global__ __launch_bounds__(256)
void gate_rms_kernel(const float* __restrict__ D_param, const float* __restrict__ norm_w)
{
    const int bl = blockIdx.x;
    const int tid = threadIdx.x;
    const __half2* yrow = (const __half2*)(g_y_h + (size_t)bl * INTER);
    const __half2* grow = (const __half2*)(g_proj_h + (size_t)bl * PROJ_PAD);
    const __half2* xrow = (const __half2*)(g_conv_h + (size_t)bl * CONV_DIM);

    float vals[8];
    float ss = 0.f;
#pragma unroll
    for (int r = 0; r < 2; ++r) {
        const int i = tid * 4 + r * 1024;
        const float2 ya = __half22float2(yrow[i / 2]);
        const float2 yb = __half22float2(yrow[i / 2 + 1]);
        const float2 ga = __half22float2(grow[i / 2]);
        const float2 gb = __half22float2(grow[i / 2 + 1]);
        const float2 xa = __half22float2(xrow[i / 2]);
        const float2 xb = __half22float2(xrow[i / 2 + 1]);
        const float d = D_param[i >> 6];
        float g0 = (ya.x + d * xa.x) * siluf(ga.x);
        float g1 = (ya.y + d * xa.y) * siluf(ga.y);
        float g2 = (yb.x + d * xb.x) * siluf(gb.x);
        float g3 = (yb.y + d * xb.y) * siluf(gb.y);
        vals[r * 4 + 0] = g0; vals[r * 4 + 1] = g1;
        vals[r * 4 + 2] = g2; vals[r * 4 + 3] = g3;
        ss += g0 * g0 + g1 * g1 + g2 * g2 + g3 * g3;
    }

    __shared__ float red[8];
    __shared__ float stot;
#pragma unroll
    for (int o = 16; o; o >>= 1) ss += __shfl_xor_sync(0xffffffffu, ss, o);
    if ((tid & 31) == 0) red[tid >> 5] = ss;
    __syncthreads();
    if (tid == 0) {
        float v = 0.f;
#pragma unroll
        for (int i = 0; i < 8; ++i) v += red[i];
        stot = rsqrtf(v * (1.f / (float)INTER) + EPSV);
    }
    __syncthreads();
    const float rs = stot;

    __half* gh = g_gate_h + (size_t)bl * INTER;
#pragma unroll
    for (int r = 0; r < 2; ++r) {
        const int i = tid * 4 + r * 1024;
        const float4 nw = *(const float4*)(norm_w + i);
        gh[i + 0] = __float2half_rn(vals[r * 4 + 0] * rs * nw.x);
        gh[i + 1] = __float2half_rn(vals[r * 4 + 1] * rs * nw.y);
        gh[i + 2] = __float2half_rn(vals[r * 4 + 2] * rs * nw.z);
        gh[i + 3] = __float2half_rn(vals[r * 4 + 3] * rs * nw.w);
    }
}

// ---------------- launch -----------------------------------------------------
extern "C" void kernel_launch(void* const* d_in, const int* in_sizes, int n_in,
                              void* d_out, int out_size)
{
    const float* hs      = (const float*)d_in[0];
    const float* W_in    = (const float*)d_in[1];
    const float* conv_w  = (const float*)d_in[2];
    const float* conv_b  = (const float*)d_in[3];
    const float* dt_bias = (const float*)d_in[4];
    const float* A_log   = (const float*)d_in[5];
    const float* D_param = (const float*)d_in[6];
    const float* norm_w  = (const float*)d_in[7];
    const float* W_out   = (const float*)d_in[8];
    float* out = (float*)d_out;

    cudaFuncSetAttribute(gemm_mma1<0>, cudaFuncAttributeMaxDynamicSharedMemorySize,
                         GEMM_SMEM_BYTES);
    cudaFuncSetAttribute(gemm_mma1<1>, cudaFuncAttributeMaxDynamicSharedMemorySize,
                         GEMM_SMEM_BYTES);
    cudaFuncSetAttribute(chunk_G_kernel, cudaFuncAttributeMaxDynamicSharedMemorySize,
                         G_SMEM);
    cudaFuncSetAttribute(chunk_state_kernel, cudaFuncAttributeMaxDynamicSharedMemorySize,
                         PH_SMEM);
    cudaFuncSetAttribute(chunk_y_kernel, cudaFuncAttributeMaxDynamicSharedMemorySize,
                         PH_SMEM);

    void *pproj = nullptr;
    void *phh = nullptr, *pwh = nullptr, *pgh = nullptr, *poh = nullptr;
    cudaGetSymbolAddress(&pproj, g_proj_h);
    cudaGetSymbolAddress(&phh, g_hs_h);
    cudaGetSymbolAddress(&pwh, g_win_h);
    cudaGetSymbolAddress(&pgh, g_gate_h);
    cudaGetSymbolAddress(&poh, g_wo_h);

    // 0) all conversions in one launch
    {
        const int tot = HS4 + WI4 + WO4;
        convert_all_kernel<<<(tot + 255) / 256, 256>>>(hs, W_in, W_out);
    }
    // 1) proj = hs @ W_in^T (fp16 output)
    {
        dim3 grid(PROJ_PAD / 128, (B_ * L_) / 128);
        gemm_mma1<1><<<grid, 256, GEMM_SMEM_BYTES>>>(
            (const __half*)phh, (const __half*)pwh, pproj, DM, PROJ_PAD);
    }
    // 2) conv + silu + dt
    conv_dt_kernel<<<B_ * L_, 256>>>(conv_w, conv_b, dt_bias);
    // 3) SSD chunked scan
    chunk_G_kernel<<<dim3(NCHUNK, B_), 256, G_SMEM>>>();
    chunk_state_kernel<<<dim3(NCHUNK, H_, B_), 256, PH_SMEM>>>(A_log);
    scan_combine<<<(B_ * H_ * P_ * N_) / 256, 256>>>();
    chunk_y_kernel<<<dim3(NCHUNK, H_, B_), 256, PH_SMEM>>>(A_log);
    // 4) gate + rmsnorm + fp16 round
    gate_rms_kernel<<<B_ * L_, 256>>>(D_param, norm_w);
    // 5) out = g @ W_out^T (fp32 output)
    {
        dim3 grid(DM / 128, (B_ * L_) / 128);
        gemm_mma1<0><<<grid, 256, GEMM_SMEM_BYTES>>>(
            (const __half*)pgh, (const __half*)poh, out, INTER, DM);
    }
}

// round 17
// speedup vs baseline: 2.6959x; 1.0849x over previous
#include <cuda_runtime.h>
#include <cuda_bf16.h>
#include <cuda_fp16.h>
#include <cstdint>
#include <cstddef>

#define B_ 2
#define L_ 4096
#define DM 2048
#define H_ 32
#define P_ 64
#define N_ 128
#define INTER 2048
#define CONV_DIM 2304
#define PROJ 4384
#define PROJ_PAD 4480
#define EPSV 1e-5f
#define NCHUNK 32
#define TCH 128

// ---------------- scratch (__device__ globals; no allocations allowed) ------
__device__ __half g_proj_h[(size_t)B_ * L_ * PROJ_PAD];
__device__ __half g_conv_h[(size_t)B_ * L_ * CONV_DIM];
__device__ __half g_y_h[(size_t)B_ * L_ * INTER];
__device__ float g_dt[B_ * L_ * H_];
__device__ __half g_G_h[(size_t)B_ * NCHUNK * TCH * TCH];
__device__ __half g_state_h[(size_t)B_ * NCHUNK * H_ * N_ * P_];
__device__ __half g_init_h[(size_t)B_ * NCHUNK * H_ * N_ * P_];
__device__ float g_adec[B_ * NCHUNK * H_];
// fp16 GEMM operands
__device__ __half g_hs_h[(size_t)B_ * L_ * DM];
__device__ __half g_win_h[(size_t)PROJ_PAD * DM];
__device__ __half g_gate_h[(size_t)B_ * L_ * INTER];
__device__ __half g_wo_h[(size_t)DM * INTER];

// ---------------- helpers ----------------------------------------------------
__device__ __forceinline__ float siluf(float x) {
    return x * (1.f / (1.f + expf(-x)));
}
__device__ __forceinline__ float softplusf(float x) {
    return (x > 20.f) ? x : log1pf(expf(x));
}
__device__ __forceinline__ uint32_t s2u(const void* p) {
    return (uint32_t)__cvta_generic_to_shared(p);
}
__device__ __forceinline__ void cp16(uint32_t saddr, const void* g) {
    asm volatile("cp.async.cg.shared.global [%0], [%1], 16;\n" :: "r"(saddr), "l"(g));
}
__device__ __forceinline__ void cp_commit() {
    asm volatile("cp.async.commit_group;\n" ::: "memory");
}
__device__ __forceinline__ void cp_wait1() {
    asm volatile("cp.async.wait_group 1;\n" ::: "memory");
}
__device__ __forceinline__ uint32_t lds32(uint32_t a) {
    uint32_t v;
    asm volatile("ld.shared.b32 %0, [%1];" : "=r"(v) : "r"(a));
    return v;
}
// e^d for d <= 0, rel err ~3e-7, no MUFU
__device__ __forceinline__ float fast_exp(float d) {
    float y = d * 1.44269504f;
    if (y < -126.f) return 0.f;
    float n = floorf(y);
    float f = y - n;
    float p = 1.33336498e-3f;
    p = fmaf(p, f, 9.61011667e-3f);
    p = fmaf(p, f, 5.55036329e-2f);
    p = fmaf(p, f, 2.40226507e-1f);
    p = fmaf(p, f, 6.93147182e-1f);
    p = fmaf(p, f, 1.0f);
    return p * __int_as_float(((int)n + 127) << 23);
}

// ---------------- warp-level HMMA plumbing ----------------------------------
__device__ __forceinline__ void ldm_x4(uint32_t* r, uint32_t addr) {
    asm volatile("ldmatrix.sync.aligned.m8n8.x4.shared.b16 {%0,%1,%2,%3}, [%4];"
                 : "=r"(r[0]), "=r"(r[1]), "=r"(r[2]), "=r"(r[3]) : "r"(addr));
}
__device__ __forceinline__ void mma16816h(float* d, const uint32_t* a, const uint32_t* b) {
    asm volatile(
        "mma.sync.aligned.m16n8k16.row.col.f32.f16.f16.f32 "
        "{%0,%1,%2,%3}, {%4,%5,%6,%7}, {%8,%9}, {%0,%1,%2,%3};"
        : "+f"(d[0]), "+f"(d[1]), "+f"(d[2]), "+f"(d[3])
        : "r"(a[0]), "r"(a[1]), "r"(a[2]), "r"(a[3]), "r"(b[0]), "r"(b[1]));
}
// LDS-based fragment loads from 272B-pitch row-major fp16 tiles
__device__ __forceinline__ void ldfragA(uint32_t r[4], uint32_t base) {
    r[0] = lds32(base);        r[1] = lds32(base + 2176);
    r[2] = lds32(base + 16);   r[3] = lds32(base + 2192);
}
__device__ __forceinline__ void ldfragB(uint32_t r[2], uint32_t base) {
    r[0] = lds32(base);        r[1] = lds32(base + 16);
}

// ---------------- single-product fp16 GEMM, BK=64, 3-stage, 2 CTAs/SM -------
#define STAGE_BYTES 32768
#define TEN_BYTES 16384
#define GEMM_SMEM_BYTES (3 * STAGE_BYTES)

template <int HALF_OUT>
__global__ __launch_bounds__(256, 2)
void gemm_mma1(const __half* __restrict__ Ah, const __half* __restrict__ Bh,
               void* __restrict__ Cv, int K, int ldc)
{
    extern __shared__ __align__(1024) char smem[];
    const uint32_t sb = s2u(smem);
    const int tid = threadIdx.x;
    const int wid = tid >> 5;
    const int lane = tid & 31;
    const int bn = blockIdx.x * 128;
    const int bm = blockIdx.y * 128;
    const int chunks = K >> 6;

    const int wm = (wid & 1) * 64;
    const int wn = (wid >> 1) * 32;

    const int rA = wm + (lane & 15);
    const uint32_t selA = (lane & 16) ? 16u : 0u;
    const uint32_t xorA = (uint32_t)((rA & 7) * 16);
    uint32_t rowOffA[4];
#pragma unroll
    for (int mf = 0; mf < 4; ++mf) rowOffA[mf] = (uint32_t)((rA + mf * 16) * 128);

    const int rB = wn + (lane & 7) + ((lane & 16) ? 8 : 0);
    const uint32_t selB = (lane & 8) ? 16u : 0u;
    const uint32_t xorB = (uint32_t)((rB & 7) * 16);
    uint32_t rowOffB[2];
#pragma unroll
    for (int nb = 0; nb < 2; ++nb) rowOffB[nb] = (uint32_t)((rB + nb * 16) * 128);

    auto issue = [&](int c) {
        const int s = c % 3;
        const uint32_t base = sb + (uint32_t)s * STAGE_BYTES;
        const int k0 = c << 6;
#pragma unroll
        for (int q = 0; q < 4; ++q) {
            const int cc = q * 256 + tid;
            const int row = cc >> 3;
            const int seg = cc & 7;
            const uint32_t dst =
                (uint32_t)(row * 128 + ((seg * 16) ^ ((row & 7) * 16)));
            cp16(base + dst, Ah + (size_t)(bm + row) * K + k0 + seg * 8);
            cp16(base + TEN_BYTES + dst, Bh + (size_t)(bn + row) * K + k0 + seg * 8);
        }
    };

    float acc[4][4][4];
#pragma unroll
    for (int i = 0; i < 4; ++i)
#pragma unroll
        for (int j = 0; j < 4; ++j)
#pragma unroll
            for (int q = 0; q < 4; ++q) acc[i][j][q] = 0.f;

    issue(0); cp_commit();
    issue(1); cp_commit();

    for (int c = 0; c < chunks; ++c) {
        cp_wait1();
        __syncthreads();
        if (c + 2 < chunks) issue(c + 2);
        cp_commit();

        const uint32_t base = sb + (uint32_t)(c % 3) * STAGE_BYTES;
        const uint32_t bAh = base;
        const uint32_t bBh = base + TEN_BYTES;

#pragma unroll
        for (int ks = 0; ks < 4; ++ks) {
            const uint32_t cA = ((uint32_t)(ks * 32) + selA) ^ xorA;
            const uint32_t cB = ((uint32_t)(ks * 32) + selB) ^ xorB;
            uint32_t ah[4][4];
#pragma unroll
            for (int mf = 0; mf < 4; ++mf)
                ldm_x4(ah[mf], bAh + rowOffA[mf] + cA);
            uint32_t bh[4][2];
#pragma unroll
            for (int nb = 0; nb < 2; ++nb) {
                uint32_t t[4];
                ldm_x4(t, bBh + rowOffB[nb] + cB);
                bh[nb * 2][0] = t[0]; bh[nb * 2][1] = t[1];
                bh[nb * 2 + 1][0] = t[2]; bh[nb * 2 + 1][1] = t[3];
            }
#pragma unroll
            for (int mf = 0; mf < 4; ++mf)
#pragma unroll
                for (int nf = 0; nf < 4; ++nf)
                    mma16816h(acc[mf][nf], ah[mf], bh[nf]);
        }
    }

    const int g = lane >> 2;
    const int t2 = (lane & 3) * 2;
#pragma unroll
    for (int mf = 0; mf < 4; ++mf) {
#pragma unroll
        for (int nf = 0; nf < 4; ++nf) {
            const int col = bn + wn + nf * 8 + t2;
            const int row0 = bm + wm + mf * 16 + g;
            if (HALF_OUT) {
                __half* C = (__half*)Cv;
                *(__half2*)(C + (size_t)row0 * ldc + col) =
                    __floats2half2_rn(acc[mf][nf][0], acc[mf][nf][1]);
                *(__half2*)(C + (size_t)(row0 + 8) * ldc + col) =
                    __floats2half2_rn(acc[mf][nf][2], acc[mf][nf][3]);
            } else {
                float* C = (float*)Cv;
                *(float2*)(C + (size_t)row0 * ldc + col) =
                    make_float2(acc[mf][nf][0], acc[mf][nf][1]);
                *(float2*)(C + (size_t)(row0 + 8) * ldc + col) =
                    make_float2(acc[mf][nf][2], acc[mf][nf][3]);
            }
        }
    }
}

// ---------------- all fp32 -> fp16 conversions in one kernel -----------------
#define HS4 (B_ * L_ * DM / 4)
#define WI4 (PROJ_PAD * DM / 4)
#define WO4 (DM * INTER / 4)
__global__ __launch_bounds__(256)
void convert_all_kernel(const float* __restrict__ hs, const float* __restrict__ W_in,
                        const float* __restrict__ W_out)
{
    const int i = blockIdx.x * 256 + threadIdx.x;
    const float4 z4 = make_float4(0.f, 0.f, 0.f, 0.f);
    float4 v;
    __half* dst;
    int o;
    if (i < HS4) {
        v = ((const float4*)hs)[i];
        dst = g_hs_h; o = i;
    } else if (i < HS4 + WI4) {
        o = i - HS4;
        const int row = o / (DM / 4);
        v = (row < PROJ) ? ((const float4*)W_in)[o] : z4;
        dst = g_win_h;
    } else if (i < HS4 + WI4 + WO4) {
        o = i - HS4 - WI4;
        v = ((const float4*)W_out)[o];
        dst = g_wo_h;
    } else {
        return;
    }
    *(__half2*)(dst + o * 4) = __floats2half2_rn(v.x, v.y);
    *(__half2*)(dst + o * 4 + 2) = __floats2half2_rn(v.z, v.w);
}

// ---------------- depthwise conv (K=4) + bias + SiLU -> fp16, plus dt -------
__global__ __launch_bounds__(256)
void conv_dt_kernel(const float* __restrict__ conv_w, const float* __restrict__ conv_b,
                    const float* __restrict__ dt_bias)
{
    const int bl = blockIdx.x;
    const int tid = threadIdx.x;
    const int l = bl & (L_ - 1);
    const __half* base0 = g_proj_h + (size_t)bl * PROJ_PAD + INTER;
#pragma unroll
    for (int it = 0; it < 9; ++it) {
        const int c = it * 256 + tid;
        float acc = conv_b[c];
        const float* w = conv_w + c * 4;
#pragma unroll
        for (int j = 0; j < 4; ++j) {
            const int ll = l - 3 + j;
            if (ll >= 0)
                acc = fmaf(__half2float(base0[(ptrdiff_t)(j - 3) * PROJ_PAD + c]), w[j], acc);
        }
        g_conv_h[(size_t)bl * CONV_DIM + c] = __float2half_rn(siluf(acc));
    }
    if (tid < H_) {
        const float x = __half2float(g_proj_h[(size_t)bl * PROJ_PAD + INTER + CONV_DIM + tid])
                        + dt_bias[tid];
        g_dt[bl * H_ + tid] = softplusf(x);
    }
}

// ---------------- chunk_G on HMMA: G = C @ B^T (exact fp16 inputs) ----------
// Block = (t-half, c, b): 64 t-rows x 128 s. 8 warps, warp tile 32x32.
#define GOFF_A 0
#define GOFF_B 17408
#define G2_SMEM (17408 + 34816)
__global__ __launch_bounds__(256, 2)
void chunk_G_kernel()
{
    const int th = blockIdx.x, c = blockIdx.y, b = blockIdx.z;
    extern __shared__ __align__(1024) char sm[];
    const uint32_t sb = s2u(sm);
    const int tid = threadIdx.x;
    const int bl0 = b * L_ + c * TCH;
    const int t0 = th * 64;

    for (int idx = tid; idx < 64 * 128; idx += 256) {
        const int t = idx >> 7, n = idx & 127;
        *(__half*)(sm + GOFF_A + t * 272 + n * 2) =
            g_conv_h[(size_t)(bl0 + t0 + t) * CONV_DIM + INTER + N_ + n];
    }
    for (int idx = tid; idx < 128 * 128; idx += 256) {
        const int s = idx >> 7, n = idx & 127;
        *(__half*)(sm + GOFF_B + s * 272 + n * 2) =
            g_conv_h[(size_t)(bl0 + s) * CONV_DIM + INTER + n];
    }
    __syncthreads();

    const int wid = tid >> 5, lane = tid & 31;
    const int wm = (wid & 1) * 32;        // t within 64
    const int wn = (wid >> 1) * 32;       // s
    const uint32_t laneoff = (uint32_t)((lane >> 2) * 272 + (lane & 3) * 4);

    float acc[2][4][4];
#pragma unroll
    for (int i = 0; i < 2; ++i)
#pragma unroll
        for (int j = 0; j < 4; ++j)
#pragma unroll
            for (int q = 0; q < 4; ++q) acc[i][j][q] = 0.f;

#pragma unroll
    for (int k0 = 0; k0 < 128; k0 += 16) {
        const uint32_t ko = (uint32_t)(k0 * 2) + laneoff;
        uint32_t ah[2][4];
#pragma unroll
        for (int mf = 0; mf < 2; ++mf)
            ldfragA(ah[mf], sb + GOFF_A + (uint32_t)((wm + mf * 16) * 272) + ko);
        uint32_t bh[4][2];
#pragma unroll
        for (int nf = 0; nf < 4; ++nf)
            ldfragB(bh[nf], sb + GOFF_B + (uint32_t)((wn + nf * 8) * 272) + ko);
#pragma unroll
        for (int mf = 0; mf < 2; ++mf)
#pragma unroll
            for (int nf = 0; nf < 4; ++nf)
                mma16816h(acc[mf][nf], ah[mf], bh[nf]);
    }

    __half* Gp = g_G_h + (size_t)(b * NCHUNK + c) * (TCH * TCH);
    const int g = lane >> 2;
    const int t2 = (lane & 3) * 2;
#pragma unroll
    for (int mf = 0; mf < 2; ++mf)
#pragma unroll
        for (int nf = 0; nf < 4; ++nf) {
            const int row0 = t0 + wm + mf * 16 + g;
            const int col = wn + nf * 8 + t2;
            *(__half2*)(Gp + row0 * 128 + col) =
                __floats2half2_rn(acc[mf][nf][0], acc[mf][nf][1]);
            *(__half2*)(Gp + (row0 + 8) * 128 + col) =
                __floats2half2_rn(acc[mf][nf][2], acc[mf][nf][3]);
        }
}

// smem offsets (272B pitch rows; single-product everywhere)
#define OFF_AH 0
#define OFF_BH 34816
#define OFF_LC 52224
#define OFF_DT 52736
#define OFF_CUM 53248
#define PH_SMEM 53760

__global__ __launch_bounds__(256, 2)
void chunk_state_kernel(const float* __restrict__ A_log)
{
    const int c = blockIdx.x, h = blockIdx.y, b = blockIdx.z;
    extern __shared__ __align__(1024) char sm[];
    const uint32_t sb = s2u(sm);
    float* slc = (float*)(sm + OFF_LC);
    float* sdt = (float*)(sm + OFF_DT);
    const int tid = threadIdx.x;
    const int bl0 = b * L_ + c * TCH;
    const float A = -expf(A_log[h]);

    if (tid < 128) {
        const float d = g_dt[(size_t)(bl0 + tid) * H_ + h];
        sdt[tid] = d;
        slc[tid] = d * A;
    }
    __syncthreads();
    for (int off = 1; off < 128; off <<= 1) {
        float v = 0.f;
        if (tid < 128 && tid >= off) v = slc[tid - off];
        __syncthreads();
        if (tid < 128 && tid >= off) slc[tid] += v;
        __syncthreads();
    }
    const float lcT = slc[127];
    if (tid == 0) g_adec[(b * NCHUNK + c) * H_ + h] = fast_exp(lcT);

    for (int idx = tid; idx < 128 * 128; idx += 256) {
        const int s = idx >> 7, n = idx & 127;
        const float w = fast_exp(lcT - slc[s]) * sdt[s];
        const float v = __half2float(g_conv_h[(size_t)(bl0 + s) * CONV_DIM + INTER + n]) * w;
        *(__half*)(sm + OFF_AH + n * 272 + s * 2) = __float2half_rn(v);
    }
    for (int idx = tid; idx < 128 * 64; idx += 256) {
        const int s = idx >> 6, p = idx & 63;
        *(__half*)(sm + OFF_BH + p * 272 + s * 2) =
            g_conv_h[(size_t)(bl0 + s) * CONV_DIM + h * P_ + p];
    }
    __syncthreads();

    const int wid = tid >> 5, lane = tid & 31;
    const int wm = (wid & 3) * 32;
    const int wn = (wid >> 2) * 32;
    const uint32_t laneoff = (uint32_t)((lane >> 2) * 272 + (lane & 3) * 4);

    float acc[2][4][4];
#pragma unroll
    for (int i = 0; i < 2; ++i)
#pragma unroll
        for (int j = 0; j < 4; ++j)
#pragma unroll
            for (int q = 0; q < 4; ++q) acc[i][j][q] = 0.f;

#pragma unroll
    for (int k0 = 0; k0 < 128; k0 += 16) {
        const uint32_t ko = (uint32_t)(k0 * 2) + laneoff;
        uint32_t ah[2][4];
#pragma unroll
        for (int mf = 0; mf < 2; ++mf)
            ldfragA(ah[mf], sb + OFF_AH + (uint32_t)((wm + mf * 16) * 272) + ko);
        uint32_t bh[4][2];
#pragma unroll
        for (int nf = 0; nf < 4; ++nf)
            ldfragB(bh[nf], sb + OFF_BH + (uint32_t)((wn + nf * 8) * 272) + ko);
#pragma unroll
        for (int mf = 0; mf < 2; ++mf)
#pragma unroll
            for (int nf = 0; nf < 4; ++nf)
                mma16816h(acc[mf][nf], ah[mf], bh[nf]);
    }

    __half* st = g_state_h + (size_t)((b * NCHUNK + c) * H_ + h) * (N_ * P_);
    const int g = lane >> 2;
    const int t2 = (lane & 3) * 2;
#pragma unroll
    for (int mf = 0; mf < 2; ++mf)
#pragma unroll
        for (int nf = 0; nf < 4; ++nf) {
            const int n0 = wm + mf * 16 + g;
            const int col = wn + nf * 8 + t2;
            *(__half2*)(st + n0 * P_ + col) =
                __floats2half2_rn(acc[mf][nf][0], acc[mf][nf][1]);
            *(__half2*)(st + (n0 + 8) * P_ + col) =
                __floats2half2_rn(acc[mf][nf][2], acc[mf][nf][3]);
        }
}

// combine chunk states (fp32 carry in registers; fp16 storage), half2-wide
__global__ __launch_bounds__(256)
void scan_combine()
{
    const int idx = blockIdx.x * 256 + threadIdx.x;   // over B*H*P*N/2
    if (idx >= B_ * H_ * P_ * N_ / 2) return;
    const int h = (idx >> 12) & (H_ - 1);
    const int b = idx >> 17;
    const int pn2 = idx & (P_ * N_ / 2 - 1);
    float2 carry = make_float2(0.f, 0.f);
#pragma unroll 4
    for (int c = 0; c < NCHUNK; ++c) {
        const size_t off = (size_t)((b * NCHUNK + c) * H_ + h) * (P_ * N_ / 2) + pn2;
        ((__half2*)g_init_h)[off] = __floats2half2_rn(carry.x, carry.y);
        const float2 s = __half22float2(((const __half2*)g_state_h)[off]);
        const float a = g_adec[(b * NCHUNK + c) * H_ + h];
        carry.x = fmaf(a, carry.x, s.x);
        carry.y = fmaf(a, carry.y, s.y);
    }
}

// Y: stage1 A=C, B=Sini (both exact fp16, single product); stage2 as before.
__global__ __launch_bounds__(256, 2)
void chunk_y_kernel(const float* __restrict__ A_log)
{
    const int c = blockIdx.x, h = blockIdx.y, b = blockIdx.z;
    extern __shared__ __align__(1024) char sm[];
    const uint32_t sb = s2u(sm);
    float* slc = (float*)(sm + OFF_LC);
    float* sdt = (float*)(sm + OFF_DT);
    float* scum = (float*)(sm + OFF_CUM);
    const int tid = threadIdx.x;
    const int bl0 = b * L_ + c * TCH;
    const float A = -expf(A_log[h]);

    if (tid < 128) {
        const float d = g_dt[(size_t)(bl0 + tid) * H_ + h];
        sdt[tid] = d;
        slc[tid] = d * A;
    }
    __syncthreads();
    for (int off = 1; off < 128; off <<= 1) {
        float v = 0.f;
        if (tid < 128 && tid >= off) v = slc[tid - off];
        __syncthreads();
        if (tid < 128 && tid >= off) slc[tid] += v;
        __syncthreads();
    }
    if (tid < 128) scum[tid] = fast_exp(slc[tid]);

    // stage 1: A = C [t][n]; B = Sini^T [p][n], both exact fp16
    for (int idx = tid; idx < 128 * 128; idx += 256) {
        const int t = idx >> 7, n = idx & 127;
        *(__half*)(sm + OFF_AH + t * 272 + n * 2) =
            g_conv_h[(size_t)(bl0 + t) * CONV_DIM + INTER + N_ + n];
    }
    const __half* Sini = g_init_h + (size_t)((b * NCHUNK + c) * H_ + h) * (N_ * P_);
    for (int idx = tid; idx < 128 * 64; idx += 256) {
        const int n = idx >> 6, p = idx & 63;
        *(__half*)(sm + OFF_BH + p * 272 + n * 2) = Sini[n * P_ + p];
    }
    __syncthreads();

    const int wid = tid >> 5, lane = tid & 31;
    const int wm = (wid & 3) * 32;
    const int wn = (wid >> 2) * 32;
    const uint32_t laneoff = (uint32_t)((lane >> 2) * 272 + (lane & 3) * 4);

    float acc[2][4][4];
#pragma unroll
    for (int i = 0; i < 2; ++i)
#pragma unroll
        for (int j = 0; j < 4; ++j)
#pragma unroll
            for (int q = 0; q < 4; ++q) acc[i][j][q] = 0.f;

#pragma unroll
    for (int k0 = 0; k0 < 128; k0 += 16) {
        const uint32_t ko = (uint32_t)(k0 * 2) + laneoff;
        uint32_t ah[2][4];
#pragma unroll
        for (int mf = 0; mf < 2; ++mf)
            ldfragA(ah[mf], sb + OFF_AH + (uint32_t)((wm + mf * 16) * 272) + ko);
        uint32_t bh[4][2];
#pragma unroll
        for (int nf = 0; nf < 4; ++nf)
            ldfragB(bh[nf], sb + OFF_BH + (uint32_t)((wn + nf * 8) * 272) + ko);
#pragma unroll
        for (int mf = 0; mf < 2; ++mf)
#pragma unroll
            for (int nf = 0; nf < 4; ++nf)
                mma16816h(acc[mf][nf], ah[mf], bh[nf]);
    }
    __syncthreads();

    const int g = lane >> 2;
#pragma unroll
    for (int mf = 0; mf < 2; ++mf) {
        const float s0 = scum[wm + mf * 16 + g];
        const float s1 = scum[wm + mf * 16 + g + 8];
#pragma unroll
        for (int nf = 0; nf < 4; ++nf) {
            acc[mf][nf][0] *= s0; acc[mf][nf][1] *= s0;
            acc[mf][nf][2] *= s1; acc[mf][nf][3] *= s1;
        }
    }

    // stage 2: A = Gamma.*G rounded fp16; B = X exact fp16
    const __half* Gp = g_G_h + (size_t)(b * NCHUNK + c) * (TCH * TCH);
    for (int idx = tid; idx < 128 * 128; idx += 256) {
        const int t = idx >> 7, s = idx & 127;
        float val = 0.f;
        if (s <= t)
            val = fast_exp(slc[t] - slc[s]) * sdt[s] * __half2float(Gp[idx]);
        *(__half*)(sm + OFF_AH + t * 272 + s * 2) = __float2half_rn(val);
    }
    for (int idx = tid; idx < 128 * 64; idx += 256) {
        const int s = idx >> 6, p = idx & 63;
        *(__half*)(sm + OFF_BH + p * 272 + s * 2) =
            g_conv_h[(size_t)(bl0 + s) * CONV_DIM + h * P_ + p];
    }
    __syncthreads();

#pragma unroll
    for (int k0 = 0; k0 < 128; k0 += 16) {
        const uint32_t ko = (uint32_t)(k0 * 2) + laneoff;
        uint32_t ah[2][4];
#pragma unroll
        for (int mf = 0; mf < 2; ++mf)
            ldfragA(ah[mf], sb + OFF_AH + (uint32_t)((wm + mf * 16) * 272) + ko);
        uint32_t bh[4][2];
#pragma unroll
        for (int nf = 0; nf < 4; ++nf)
            ldfragB(bh[nf], sb + OFF_BH + (uint32_t)((wn + nf * 8) * 272) + ko);
#pragma unroll
        for (int mf = 0; mf < 2; ++mf)
#pragma unroll
            for (int nf = 0; nf < 4; ++nf)
                mma16816h(acc[mf][nf], ah[mf], bh[nf]);
    }

    const int t2 = (lane & 3) * 2;
#pragma unroll
    for (int mf = 0; mf < 2; ++mf)
#pragma unroll
        for (int nf = 0; nf < 4; ++nf) {
            const int row0 = wm + mf * 16 + g;
            const int col = h * P_ + wn + nf * 8 + t2;
            *(__half2*)(g_y_h + (size_t)(bl0 + row0) * INTER + col) =
                __floats2half2_rn(acc[mf][nf][0], acc[mf][nf][1]);
            *(__half2*)(g_y_h + (size_t)(bl0 + row0 + 8) * INTER + col) =
                __floats2half2_rn(acc[mf][nf][2], acc[mf][nf][3]);
        }
}

// ---------------- y + D*xs, gate*silu, RMSNorm, fp16 round ------------------
__global__ __launch_bounds__(256)
void gate_rms_kernel(const float* __restrict__ D_param, const float* __restrict__ norm_w)
{
    const int bl = blockIdx.x;
    const int tid = threadIdx.x;
    const __half2* yrow = (const __half2*)(g_y_h + (size_t)bl * INTER);
    const __half2* grow = (const __half2*)(g_proj_h + (size_t)bl * PROJ_PAD);
    const __half2* xrow = (const __half2*)(g_conv_h + (size_t)bl * CONV_DIM);

    float vals[8];
    float ss = 0.f;
#pragma unroll
    for (int r = 0; r < 2; ++r) {
        const int i = tid * 4 + r * 1024;
        const float2 ya = __half22float2(yrow[i / 2]);
        const float2 yb = __half22float2(yrow[i / 2 + 1]);
        const float2 ga = __half22float2(grow[i / 2]);
        const float2 gb = __half22float2(grow[i / 2 + 1]);
        const float2 xa = __half22float2(xrow[i / 2]);
        const float2 xb = __half22float2(xrow[i / 2 + 1]);
        const float d = D_param[i >> 6];
        float g0 = (ya.x + d * xa.x) * siluf(ga.x);
        float g1 = (ya.y + d * xa.y) * siluf(ga.y);
        float g2 = (yb.x + d * xb.x) * siluf(gb.x);
        float g3 = (yb.y + d * xb.y) * siluf(gb.y);
        vals[r * 4 + 0] = g0; vals[r * 4 + 1] = g1;
        vals[r * 4 + 2] = g2; vals[r * 4 + 3] = g3;
        ss += g0 * g0 + g1 * g1 + g2 * g2 + g3 * g3;
    }

    __shared__ float red[8];
    __shared__ float stot;
#pragma unroll
    for (int o = 16; o; o >>= 1) ss += __shfl_xor_sync(0xffffffffu, ss, o);
    if ((tid & 31) == 0) red[tid >> 5] = ss;
    __syncthreads();
    if (tid == 0) {
        float v = 0.f;
#pragma unroll
        for (int i = 0; i < 8; ++i) v += red[i];
        stot = rsqrtf(v * (1.f / (float)INTER) + EPSV);
    }
    __syncthreads();
    const float rs = stot;

    __half* gh = g_gate_h + (size_t)bl * INTER;
#pragma unroll
    for (int r = 0; r < 2; ++r) {
        const int i = tid * 4 + r * 1024;
        const float4 nw = *(const float4*)(norm_w + i);
        gh[i + 0] = __float2half_rn(vals[r * 4 + 0] * rs * nw.x);
        gh[i + 1] = __float2half_rn(vals[r * 4 + 1] * rs * nw.y);
        gh[i + 2] = __float2half_rn(vals[r * 4 + 2] * rs * nw.z);
        gh[i + 3] = __float2half_rn(vals[r * 4 + 3] * rs * nw.w);
    }
}

// ---------------- launch -----------------------------------------------------
extern "C" void kernel_launch(void* const* d_in, const int* in_sizes, int n_in,
                              void* d_out, int out_size)
{
    const float* hs      = (const float*)d_in[0];
    const float* W_in    = (const float*)d_in[1];
    const float* conv_w  = (const float*)d_in[2];
    const float* conv_b  = (const float*)d_in[3];
    const float* dt_bias = (const float*)d_in[4];
    const float* A_log   = (const float*)d_in[5];
    const float* D_param = (const float*)d_in[6];
    const float* norm_w  = (const float*)d_in[7];
    const float* W_out   = (const float*)d_in[8];
    float* out = (float*)d_out;

    cudaFuncSetAttribute(gemm_mma1<0>, cudaFuncAttributeMaxDynamicSharedMemorySize,
                         GEMM_SMEM_BYTES);
    cudaFuncSetAttribute(gemm_mma1<1>, cudaFuncAttributeMaxDynamicSharedMemorySize,
                         GEMM_SMEM_BYTES);
    cudaFuncSetAttribute(chunk_G_kernel, cudaFuncAttributeMaxDynamicSharedMemorySize,
                         G2_SMEM);
    cudaFuncSetAttribute(chunk_state_kernel, cudaFuncAttributeMaxDynamicSharedMemorySize,
                         PH_SMEM);
    cudaFuncSetAttribute(chunk_y_kernel, cudaFuncAttributeMaxDynamicSharedMemorySize,
                         PH_SMEM);

    void *pproj = nullptr;
    void *phh = nullptr, *pwh = nullptr, *pgh = nullptr, *poh = nullptr;
    cudaGetSymbolAddress(&pproj, g_proj_h);
    cudaGetSymbolAddress(&phh, g_hs_h);
    cudaGetSymbolAddress(&pwh, g_win_h);
    cudaGetSymbolAddress(&pgh, g_gate_h);
    cudaGetSymbolAddress(&poh, g_wo_h);

    // 0) all conversions in one launch
    {
        const int tot = HS4 + WI4 + WO4;
        convert_all_kernel<<<(tot + 255) / 256, 256>>>(hs, W_in, W_out);
    }
    // 1) proj = hs @ W_in^T (fp16 output)
    {
        dim3 grid(PROJ_PAD / 128, (B_ * L_) / 128);
        gemm_mma1<1><<<grid, 256, GEMM_SMEM_BYTES>>>(
            (const __half*)phh, (const __half*)pwh, pproj, DM, PROJ_PAD);
    }
    // 2) conv + silu + dt
    conv_dt_kernel<<<B_ * L_, 256>>>(conv_w, conv_b, dt_bias);
    // 3) SSD chunked scan
    chunk_G_kernel<<<dim3(2, NCHUNK, B_), 256, G2_SMEM>>>();
    chunk_state_kernel<<<dim3(NCHUNK, H_, B_), 256, PH_SMEM>>>(A_log);
    scan_combine<<<(B_ * H_ * P_ * N_ / 2 + 255) / 256, 256>>>();
    chunk_y_kernel<<<dim3(NCHUNK, H_, B_), 256, PH_SMEM>>>(A_log);
    // 4) gate + rmsnorm + fp16 round
    gate_rms_kernel<<<B_ * L_, 256>>>(D_param, norm_w);
    // 5) out = g @ W_out^T (fp32 output)
    {
        dim3 grid(DM / 128, (B_ * L_) / 128);
        gemm_mma1<0><<<grid, 256, GEMM_SMEM_BYTES>>>(
            (const __half*)pgh, (const __half*)poh, out, INTER, DM);
    }
}